// round 2
// baseline (speedup 1.0000x reference)
#include <cuda_runtime.h>
#include <math.h>

#define B_ 4
#define T_ 2048
#define C_ 768
#define H_ 12
#define D_ 64
#define BT_ (B_ * T_)
#define C3_ (3 * C_)

// Scratch (no runtime allocation allowed)
__device__ float g_qkv[(size_t)BT_ * C3_];   // [BT, 3C]  ~75.5 MB
__device__ float g_ctx[(size_t)BT_ * C_];    // [BT, C]   ~25 MB
__device__ int   g_keep[BT_];                // normalized mask: 1 = attended

// ---------------------------------------------------------------------------
// Mask normalizer. The reference mask is int64 but the harness dtype set is
// {float32,int32,bf16}, so it is most likely delivered as int32. Detect the
// actual width at runtime: if ALL odd 32-bit words among the first BT_ words
// are zero, the buffer is little-endian int64 (high words of values 0/1);
// a genuine random 0/1 int32 mask fails that test w.p. 1 - 2^-4096.
// Single block of 1024 threads; writes g_keep[i] = (mask[i] == 0).
// ---------------------------------------------------------------------------
__global__ __launch_bounds__(1024) void mask_norm(const int* __restrict__ amw)
{
    const int tid = threadIdx.x;
    int allzero = 1;
    for (int i = tid; i < BT_; i += 1024)
        if (i & 1) allzero &= (amw[i] == 0);
    int is64 = __syncthreads_and(allzero);
    for (int i = tid; i < BT_; i += 1024) {
        int v = is64 ? amw[2 * i] : amw[i];
        g_keep[i] = (v == 0) ? 1 : 0;
    }
}

// ---------------------------------------------------------------------------
// Tiled SGEMM with bias epilogue:  Out[M,N] = A[M,K] @ W[K,N] + bias[N]
// BM=BN=64, BK=16, 256 threads, 4x4 thread tile.
// ---------------------------------------------------------------------------
__global__ __launch_bounds__(256) void sgemm_bias(
    const float* __restrict__ A, const float* __restrict__ W,
    const float* __restrict__ bias, float* __restrict__ Out,
    int M, int N, int K)
{
    __shared__ float As[16][64];  // [k][m]  (transposed A tile)
    __shared__ float Ws[16][64];  // [k][n]

    const int tid = threadIdx.x;
    const int tx = tid & 15;        // n-tile coord
    const int ty = tid >> 4;        // m-tile coord
    const int m0 = blockIdx.y * 64;
    const int n0 = blockIdx.x * 64;

    const int arow = tid >> 2;
    const int akq  = (tid & 3) * 4;
    const int wrow = tid >> 4;
    const int wng  = (tid & 15) * 4;

    float acc[4][4] = {};

    for (int k0 = 0; k0 < K; k0 += 16) {
        float4 av = *(const float4*)&A[(size_t)(m0 + arow) * K + k0 + akq];
        As[akq + 0][arow] = av.x;
        As[akq + 1][arow] = av.y;
        As[akq + 2][arow] = av.z;
        As[akq + 3][arow] = av.w;
        *(float4*)&Ws[wrow][wng] =
            *(const float4*)&W[(size_t)(k0 + wrow) * N + n0 + wng];
        __syncthreads();

        #pragma unroll
        for (int kk = 0; kk < 16; kk++) {
            float4 a4 = *(const float4*)&As[kk][ty * 4];
            float4 w4 = *(const float4*)&Ws[kk][tx * 4];
            float a[4] = {a4.x, a4.y, a4.z, a4.w};
            float w[4] = {w4.x, w4.y, w4.z, w4.w};
            #pragma unroll
            for (int i = 0; i < 4; i++)
                #pragma unroll
                for (int j = 0; j < 4; j++)
                    acc[i][j] = fmaf(a[i], w[j], acc[i][j]);
        }
        __syncthreads();
    }

    #pragma unroll
    for (int i = 0; i < 4; i++) {
        int m = m0 + ty * 4 + i;
        float4 o;
        o.x = acc[i][0] + bias[n0 + tx * 4 + 0];
        o.y = acc[i][1] + bias[n0 + tx * 4 + 1];
        o.z = acc[i][2] + bias[n0 + tx * 4 + 2];
        o.w = acc[i][3] + bias[n0 + tx * 4 + 3];
        *(float4*)&Out[(size_t)m * N + n0 + tx * 4] = o;
    }
}

// ---------------------------------------------------------------------------
// Flash attention (fp32, online softmax).
// grid: (T/64, H, B), 256 threads. Q tile 64x64 resident; loop 32 K/V tiles.
// Mask quirk (from reference): attended where attention_mask == 0 (g_keep==1).
// ---------------------------------------------------------------------------
__global__ __launch_bounds__(256) void attn_kernel(
    const float* __restrict__ qkv, float* __restrict__ ctx)
{
    __shared__ float Qs[64][64];   // [q][d]
    __shared__ float KPs[64][64];  // first K^T [d][kpos], then P [q][kpos]
    __shared__ float Vs[64][64];   // [kpos][d]

    const int tid = threadIdx.x;
    const int tx = tid & 15;
    const int ty = tid >> 4;
    const int q0 = blockIdx.x * 64;
    const int h  = blockIdx.y;
    const int b  = blockIdx.z;

    const float* qbase = qkv + (size_t)b * T_ * C3_ + (size_t)h * D_;
    const int* keepb = g_keep + b * T_;

    // Load Q tile (64x64), float4 coalesced
    {
        const int r  = tid >> 2;
        const int gb = tid & 3;
        const float* qrow = qbase + (size_t)(q0 + r) * C3_;
        #pragma unroll
        for (int p = 0; p < 4; p++) {
            int c = (gb + 4 * p) * 4;
            *(float4*)&Qs[r][c] = *(const float4*)&qrow[c];
        }
    }

    float m[4], l[4], o[4][4];
    #pragma unroll
    for (int i = 0; i < 4; i++) {
        m[i] = -INFINITY; l[i] = 0.f;
        #pragma unroll
        for (int j = 0; j < 4; j++) o[i][j] = 0.f;
    }

    const float scale = 0.125f;  // 1/sqrt(64)

    for (int kb = 0; kb < 32; kb++) {
        const int k0 = kb * 64;
        __syncthreads();  // prior PV reads of KPs/Vs complete

        // Load K (transposed into KPs) and V tiles
        {
            const int r  = tid >> 2;   // kpos in tile
            const int gb = tid & 3;
            const float* krow = qbase + C_      + (size_t)(k0 + r) * C3_;
            const float* vrow = qbase + 2 * C_  + (size_t)(k0 + r) * C3_;
            #pragma unroll
            for (int p = 0; p < 4; p++) {
                int c = (gb + 4 * p) * 4;
                float4 kv = *(const float4*)&krow[c];
                KPs[c + 0][r] = kv.x;
                KPs[c + 1][r] = kv.y;
                KPs[c + 2][r] = kv.z;
                KPs[c + 3][r] = kv.w;
                *(float4*)&Vs[r][c] = *(const float4*)&vrow[c];
            }
        }
        __syncthreads();

        // S[i][j] = sum_d Q[row_i][d] * K[col_j][d]
        float s[4][4] = {};
        #pragma unroll
        for (int d4 = 0; d4 < 16; d4++) {
            float4 q4[4], k4[4];
            #pragma unroll
            for (int i = 0; i < 4; i++)
                q4[i] = *(const float4*)&Qs[ty * 4 + i][d4 * 4];
            #pragma unroll
            for (int sub = 0; sub < 4; sub++)
                k4[sub] = *(const float4*)&KPs[d4 * 4 + sub][tx * 4];
            #pragma unroll
            for (int i = 0; i < 4; i++) {
                s[i][0] = fmaf(q4[i].x, k4[0].x, fmaf(q4[i].y, k4[1].x, fmaf(q4[i].z, k4[2].x, fmaf(q4[i].w, k4[3].x, s[i][0]))));
                s[i][1] = fmaf(q4[i].x, k4[0].y, fmaf(q4[i].y, k4[1].y, fmaf(q4[i].z, k4[2].y, fmaf(q4[i].w, k4[3].y, s[i][1]))));
                s[i][2] = fmaf(q4[i].x, k4[0].z, fmaf(q4[i].y, k4[1].z, fmaf(q4[i].z, k4[2].z, fmaf(q4[i].w, k4[3].z, s[i][2]))));
                s[i][3] = fmaf(q4[i].x, k4[0].w, fmaf(q4[i].y, k4[1].w, fmaf(q4[i].z, k4[2].w, fmaf(q4[i].w, k4[3].w, s[i][3]))));
            }
        }

        // Scale + mask (keep where normalized mask says attended)
        #pragma unroll
        for (int j = 0; j < 4; j++) {
            bool keep = (keepb[k0 + tx * 4 + j] != 0);
            #pragma unroll
            for (int i = 0; i < 4; i++)
                s[i][j] = keep ? s[i][j] * scale : -1e30f;
        }

        // Online softmax update (row reduce across tx via 16-wide shuffles)
        #pragma unroll
        for (int i = 0; i < 4; i++) {
            float rmax = fmaxf(fmaxf(s[i][0], s[i][1]), fmaxf(s[i][2], s[i][3]));
            #pragma unroll
            for (int off = 8; off >= 1; off >>= 1)
                rmax = fmaxf(rmax, __shfl_xor_sync(0xffffffffu, rmax, off, 16));
            float mnew = fmaxf(m[i], rmax);
            float corr = __expf(m[i] - mnew);
            m[i] = mnew;
            float rsum = 0.f;
            #pragma unroll
            for (int j = 0; j < 4; j++) {
                s[i][j] = __expf(s[i][j] - mnew);
                rsum += s[i][j];
            }
            #pragma unroll
            for (int off = 8; off >= 1; off >>= 1)
                rsum += __shfl_xor_sync(0xffffffffu, rsum, off, 16);
            l[i] = l[i] * corr + rsum;
            #pragma unroll
            for (int j = 0; j < 4; j++) o[i][j] *= corr;
        }

        __syncthreads();  // all S reads of KPs (K^T) done before P overwrite
        #pragma unroll
        for (int i = 0; i < 4; i++) {
            float4 pv = make_float4(s[i][0], s[i][1], s[i][2], s[i][3]);
            *(float4*)&KPs[ty * 4 + i][tx * 4] = pv;  // P[q][kpos]
        }
        __syncthreads();

        // O += P @ V
        #pragma unroll
        for (int c4 = 0; c4 < 16; c4++) {
            float4 p4[4], v4[4];
            #pragma unroll
            for (int i = 0; i < 4; i++)
                p4[i] = *(const float4*)&KPs[ty * 4 + i][c4 * 4];
            #pragma unroll
            for (int sub = 0; sub < 4; sub++)
                v4[sub] = *(const float4*)&Vs[c4 * 4 + sub][tx * 4];
            #pragma unroll
            for (int i = 0; i < 4; i++) {
                o[i][0] = fmaf(p4[i].x, v4[0].x, fmaf(p4[i].y, v4[1].x, fmaf(p4[i].z, v4[2].x, fmaf(p4[i].w, v4[3].x, o[i][0]))));
                o[i][1] = fmaf(p4[i].x, v4[0].y, fmaf(p4[i].y, v4[1].y, fmaf(p4[i].z, v4[2].y, fmaf(p4[i].w, v4[3].y, o[i][1]))));
                o[i][2] = fmaf(p4[i].x, v4[0].z, fmaf(p4[i].y, v4[1].z, fmaf(p4[i].z, v4[2].z, fmaf(p4[i].w, v4[3].z, o[i][2]))));
                o[i][3] = fmaf(p4[i].x, v4[0].w, fmaf(p4[i].y, v4[1].w, fmaf(p4[i].z, v4[2].w, fmaf(p4[i].w, v4[3].w, o[i][3]))));
            }
        }
    }

    // Epilogue: normalize and write context [BT, C] (head-interleaved)
    #pragma unroll
    for (int i = 0; i < 4; i++) {
        float invl = 1.0f / l[i];
        float4 ov = make_float4(o[i][0] * invl, o[i][1] * invl,
                                o[i][2] * invl, o[i][3] * invl);
        size_t row = (size_t)b * T_ + q0 + ty * 4 + i;
        *(float4*)&g_ctx[row * C_ + h * D_ + tx * 4] = ov;
    }
}

// ---------------------------------------------------------------------------
extern "C" void kernel_launch(void* const* d_in, const int* in_sizes, int n_in,
                              void* d_out, int out_size)
{
    const float* x    = (const float*)d_in[0];
    const int*   am   = (const int*)d_in[1];     // mask words (int32 or int64)
    const float* Wqkv = (const float*)d_in[2];
    const float* bqkv = (const float*)d_in[3];
    const float* Wo   = (const float*)d_in[4];
    const float* bo   = (const float*)d_in[5];
    float* out = (float*)d_out;

    float *qkv_ptr = nullptr, *ctx_ptr = nullptr;
    cudaGetSymbolAddress((void**)&qkv_ptr, g_qkv);
    cudaGetSymbolAddress((void**)&ctx_ptr, g_ctx);

    dim3 blk(256);
    // 0) Normalize mask (handles int32 or int64 harness delivery)
    mask_norm<<<1, 1024>>>(am);
    // 1) QKV projection: [8192,768] @ [768,2304] + bqkv
    sgemm_bias<<<dim3(C3_ / 64, BT_ / 64), blk>>>(x, Wqkv, bqkv, qkv_ptr,
                                                  BT_, C3_, C_);
    // 2) Masked flash attention per (b, h, q-tile)
    attn_kernel<<<dim3(T_ / 64, H_, B_), blk>>>(qkv_ptr, ctx_ptr);
    // 3) Output projection: [8192,768] @ [768,768] + bo
    sgemm_bias<<<dim3(C_ / 64, BT_ / 64), blk>>>(ctx_ptr, Wo, bo, out,
                                                 BT_, C_, C_);
}

// round 4
// speedup vs baseline: 1.2390x; 1.2390x over previous
#include <cuda_runtime.h>
#include <cuda_bf16.h>
#include <math.h>
#include <stdint.h>

#define B_ 4
#define T_ 2048
#define C_ 768
#define H_ 12
#define D_ 64
#define BT_ (B_ * T_)
#define C3_ (3 * C_)

// ---------------------------------------------------------------------------
// Device scratch (no runtime allocation allowed)
// ---------------------------------------------------------------------------
__device__ float g_qkv[(size_t)BT_ * C3_];   // [BT, 3C] fp32
__device__ float g_ctx[(size_t)BT_ * C_];    // [BT, C]  fp32
__device__ int   g_keep[BT_];                // normalized mask: 1 = attended

__device__ __nv_bfloat16 g_xh[(size_t)BT_ * C_],  g_xl[(size_t)BT_ * C_];
__device__ __nv_bfloat16 g_ch[(size_t)BT_ * C_],  g_cl[(size_t)BT_ * C_];
__device__ __nv_bfloat16 g_wqh[(size_t)C3_ * C_], g_wql[(size_t)C3_ * C_]; // Wqkv^T [3C][C]
__device__ __nv_bfloat16 g_woh[(size_t)C_ * C_],  g_wol[(size_t)C_ * C_];  // Wo^T   [C][C]

// ---------------------------------------------------------------------------
// PTX helpers — portable tensor path only (mma.sync / ldmatrix, sm_80+).
// ---------------------------------------------------------------------------
__device__ __forceinline__ uint32_t smem_u32(const void* p) {
    uint32_t a;
    asm("{ .reg .u64 t; cvta.to.shared.u64 t, %1; cvt.u32.u64 %0, t; }"
        : "=r"(a) : "l"(p));
    return a;
}
__device__ __forceinline__ void ldm_x4(uint32_t (&r)[4], uint32_t addr) {
    asm volatile("ldmatrix.sync.aligned.m8n8.x4.shared.b16 {%0,%1,%2,%3}, [%4];"
        : "=r"(r[0]), "=r"(r[1]), "=r"(r[2]), "=r"(r[3]) : "r"(addr));
}
__device__ __forceinline__ void ldm_x2(uint32_t (&r)[2], uint32_t addr) {
    asm volatile("ldmatrix.sync.aligned.m8n8.x2.shared.b16 {%0,%1}, [%2];"
        : "=r"(r[0]), "=r"(r[1]) : "r"(addr));
}
__device__ __forceinline__ void mma_bf16(float (&d)[4], const uint32_t (&a)[4],
                                         const uint32_t (&b)[2]) {
    asm volatile(
        "mma.sync.aligned.m16n8k16.row.col.f32.bf16.bf16.f32 "
        "{%0,%1,%2,%3}, {%4,%5,%6,%7}, {%8,%9}, {%0,%1,%2,%3};"
        : "+f"(d[0]), "+f"(d[1]), "+f"(d[2]), "+f"(d[3])
        : "r"(a[0]), "r"(a[1]), "r"(a[2]), "r"(a[3]), "r"(b[0]), "r"(b[1]));
}
#define SW128(o) ((o) ^ (((o) >> 3) & 0x70))

// ---------------------------------------------------------------------------
// Mask normalizer (mask arrives as int32 or int64 words; detect at runtime)
// ---------------------------------------------------------------------------
__global__ __launch_bounds__(1024) void mask_norm(const int* __restrict__ amw)
{
    const int tid = threadIdx.x;
    int allzero = 1;
    for (int i = tid; i < BT_; i += 1024)
        if (i & 1) allzero &= (amw[i] == 0);
    int is64 = __syncthreads_and(allzero);
    for (int i = tid; i < BT_; i += 1024) {
        int v = is64 ? amw[2 * i] : amw[i];
        g_keep[i] = (v == 0) ? 1 : 0;
    }
}

// ---------------------------------------------------------------------------
// fp32 -> bf16 hi/lo split kernels
// ---------------------------------------------------------------------------
__global__ __launch_bounds__(256) void split_rm(
    const float* __restrict__ in, __nv_bfloat16* __restrict__ hi,
    __nv_bfloat16* __restrict__ lo, int n)
{
    int i = blockIdx.x * 256 + threadIdx.x;
    if (i >= n) return;
    float x = in[i];
    __nv_bfloat16 h = __float2bfloat16(x);
    hi[i] = h;
    lo[i] = __float2bfloat16(x - __bfloat162float(h));
}

// fp32 W[K][N] -> bf16 hi/lo transposed [N][K]
__global__ __launch_bounds__(256) void split_tr(
    const float* __restrict__ in, __nv_bfloat16* __restrict__ hi,
    __nv_bfloat16* __restrict__ lo, int K, int N)
{
    int i = blockIdx.x * 256 + threadIdx.x;
    if (i >= K * N) return;
    int k = i / N, n = i - k * N;
    float x = in[i];
    __nv_bfloat16 h = __float2bfloat16(x);
    hi[(size_t)n * K + k] = h;
    lo[(size_t)n * K + k] = __float2bfloat16(x - __bfloat162float(h));
}

// ---------------------------------------------------------------------------
// bf16x3 HMMA GEMM: Out[M,N] = (Ah+Al)[M][K] @ ((Bh+Bl)[N][K])^T + bias
// CTA 128x128, 8 warps (2x4), warp tile 64x32, K staged 64/iter, SW128 smem.
// ---------------------------------------------------------------------------
#define GS_AH 0
#define GS_AL 16384
#define GS_BH 32768
#define GS_BL 49152
#define GS_TOTAL 65536

__global__ __launch_bounds__(256) void gemm_bf16x3(
    const __nv_bfloat16* __restrict__ Ah, const __nv_bfloat16* __restrict__ Al,
    const __nv_bfloat16* __restrict__ Bh, const __nv_bfloat16* __restrict__ Bl,
    const float* __restrict__ bias, float* __restrict__ Out,
    int M, int N, int K)
{
    extern __shared__ __align__(1024) char smem[];
    const uint32_t sb = smem_u32(smem);
    const int tid  = threadIdx.x;
    const int wid  = tid >> 5;
    const int lane = tid & 31;
    const int m0 = blockIdx.y * 128;
    const int n0 = blockIdx.x * 128;
    const int wm = wid >> 2;        // 0..1  -> rows wm*64
    const int wn = wid & 3;         // 0..3  -> cols wn*32

    float acc[4][4][4];             // [mt][nt][reg]
    #pragma unroll
    for (int i = 0; i < 4; i++)
        #pragma unroll
        for (int j = 0; j < 4; j++)
            #pragma unroll
            for (int r = 0; r < 4; r++) acc[i][j][r] = 0.f;

    const int nstages = K / 64;
    for (int s = 0; s < nstages; s++) {
        const int k0 = s * 64;
        // Stage Ah/Al/Bh/Bl tiles: [128 rows][64 bf16] each, SW128 swizzled.
        #pragma unroll
        for (int i = 0; i < 4; i++) {
            int u = tid + 256 * i;          // 0..1023 16B units per tile
            int r = u >> 3, uk = u & 7;
            uint32_t so = SW128((uint32_t)(r * 128 + uk * 16));
            size_t ga = (size_t)(m0 + r) * K + k0 + uk * 8;
            size_t gb = (size_t)(n0 + r) * K + k0 + uk * 8;
            *(uint4*)(smem + GS_AH + so) = *(const uint4*)(Ah + ga);
            *(uint4*)(smem + GS_AL + so) = *(const uint4*)(Al + ga);
            *(uint4*)(smem + GS_BH + so) = *(const uint4*)(Bh + gb);
            *(uint4*)(smem + GS_BL + so) = *(const uint4*)(Bl + gb);
        }
        __syncthreads();

        #pragma unroll
        for (int kk = 0; kk < 4; kk++) {    // 4 x k16 per stage
            // B fragments for 4 n-subtiles (hi & lo)
            uint32_t bh[4][2], bl[4][2];
            #pragma unroll
            for (int nt = 0; nt < 4; nt++) {
                uint32_t rn = (uint32_t)(wn * 32 + nt * 8 + (lane & 7));
                uint32_t byteb = rn * 128 + kk * 32 + (((lane >> 3) & 1) << 4);
                uint32_t so = SW128(byteb);
                ldm_x2(bh[nt], sb + GS_BH + so);
                ldm_x2(bl[nt], sb + GS_BL + so);
            }
            // A fragments per m-subtile, then MMAs
            #pragma unroll
            for (int mt = 0; mt < 4; mt++) {
                uint32_t rm = (uint32_t)(wm * 64 + mt * 16 + (lane & 15));
                uint32_t bytea = rm * 128 + kk * 32 + ((lane >> 4) << 4);
                uint32_t so = SW128(bytea);
                uint32_t ah[4], al[4];
                ldm_x4(ah, sb + GS_AH + so);
                ldm_x4(al, sb + GS_AL + so);
                #pragma unroll
                for (int nt = 0; nt < 4; nt++) {
                    mma_bf16(acc[mt][nt], ah, bh[nt]);
                    mma_bf16(acc[mt][nt], ah, bl[nt]);
                    mma_bf16(acc[mt][nt], al, bh[nt]);
                }
            }
        }
        __syncthreads();
    }

    // Epilogue: registers -> global with bias.
    // d0,d1: row = lane/4, cols (lane%4)*2 + {0,1}; d2,d3: row + 8.
    #pragma unroll
    for (int mt = 0; mt < 4; mt++) {
        #pragma unroll
        for (int nt = 0; nt < 4; nt++) {
            int grow = m0 + wm * 64 + mt * 16 + (lane >> 2);
            int gcol = n0 + wn * 32 + nt * 8 + (lane & 3) * 2;
            float2 bb = *(const float2*)&bias[gcol];
            float2 v0 = make_float2(acc[mt][nt][0] + bb.x, acc[mt][nt][1] + bb.y);
            float2 v1 = make_float2(acc[mt][nt][2] + bb.x, acc[mt][nt][3] + bb.y);
            *(float2*)&Out[(size_t)grow * N + gcol] = v0;
            *(float2*)&Out[(size_t)(grow + 8) * N + gcol] = v1;
        }
    }
}

// ---------------------------------------------------------------------------
// Flash attention (fp32, online softmax) — unchanged
// ---------------------------------------------------------------------------
__global__ __launch_bounds__(256) void attn_kernel(
    const float* __restrict__ qkv, float* __restrict__ ctx)
{
    __shared__ float Qs[64][64];
    __shared__ float KPs[64][64];
    __shared__ float Vs[64][64];

    const int tid = threadIdx.x;
    const int tx = tid & 15;
    const int ty = tid >> 4;
    const int q0 = blockIdx.x * 64;
    const int h  = blockIdx.y;
    const int b  = blockIdx.z;

    const float* qbase = qkv + (size_t)b * T_ * C3_ + (size_t)h * D_;
    const int* keepb = g_keep + b * T_;

    {
        const int r  = tid >> 2;
        const int gb = tid & 3;
        const float* qrow = qbase + (size_t)(q0 + r) * C3_;
        #pragma unroll
        for (int p = 0; p < 4; p++) {
            int c = (gb + 4 * p) * 4;
            *(float4*)&Qs[r][c] = *(const float4*)&qrow[c];
        }
    }

    float m[4], l[4], o[4][4];
    #pragma unroll
    for (int i = 0; i < 4; i++) {
        m[i] = -INFINITY; l[i] = 0.f;
        #pragma unroll
        for (int j = 0; j < 4; j++) o[i][j] = 0.f;
    }

    const float scale = 0.125f;

    for (int kb = 0; kb < 32; kb++) {
        const int k0 = kb * 64;
        __syncthreads();
        {
            const int r  = tid >> 2;
            const int gb = tid & 3;
            const float* krow = qbase + C_     + (size_t)(k0 + r) * C3_;
            const float* vrow = qbase + 2 * C_ + (size_t)(k0 + r) * C3_;
            #pragma unroll
            for (int p = 0; p < 4; p++) {
                int c = (gb + 4 * p) * 4;
                float4 kv = *(const float4*)&krow[c];
                KPs[c + 0][r] = kv.x;
                KPs[c + 1][r] = kv.y;
                KPs[c + 2][r] = kv.z;
                KPs[c + 3][r] = kv.w;
                *(float4*)&Vs[r][c] = *(const float4*)&vrow[c];
            }
        }
        __syncthreads();

        float s[4][4] = {};
        #pragma unroll
        for (int d4 = 0; d4 < 16; d4++) {
            float4 q4[4], k4[4];
            #pragma unroll
            for (int i = 0; i < 4; i++)
                q4[i] = *(const float4*)&Qs[ty * 4 + i][d4 * 4];
            #pragma unroll
            for (int sub = 0; sub < 4; sub++)
                k4[sub] = *(const float4*)&KPs[d4 * 4 + sub][tx * 4];
            #pragma unroll
            for (int i = 0; i < 4; i++) {
                s[i][0] = fmaf(q4[i].x, k4[0].x, fmaf(q4[i].y, k4[1].x, fmaf(q4[i].z, k4[2].x, fmaf(q4[i].w, k4[3].x, s[i][0]))));
                s[i][1] = fmaf(q4[i].x, k4[0].y, fmaf(q4[i].y, k4[1].y, fmaf(q4[i].z, k4[2].y, fmaf(q4[i].w, k4[3].y, s[i][1]))));
                s[i][2] = fmaf(q4[i].x, k4[0].z, fmaf(q4[i].y, k4[1].z, fmaf(q4[i].z, k4[2].z, fmaf(q4[i].w, k4[3].z, s[i][2]))));
                s[i][3] = fmaf(q4[i].x, k4[0].w, fmaf(q4[i].y, k4[1].w, fmaf(q4[i].z, k4[2].w, fmaf(q4[i].w, k4[3].w, s[i][3]))));
            }
        }

        #pragma unroll
        for (int j = 0; j < 4; j++) {
            bool keep = (keepb[k0 + tx * 4 + j] != 0);
            #pragma unroll
            for (int i = 0; i < 4; i++)
                s[i][j] = keep ? s[i][j] * scale : -1e30f;
        }

        #pragma unroll
        for (int i = 0; i < 4; i++) {
            float rmax = fmaxf(fmaxf(s[i][0], s[i][1]), fmaxf(s[i][2], s[i][3]));
            #pragma unroll
            for (int off = 8; off >= 1; off >>= 1)
                rmax = fmaxf(rmax, __shfl_xor_sync(0xffffffffu, rmax, off, 16));
            float mnew = fmaxf(m[i], rmax);
            float corr = __expf(m[i] - mnew);
            m[i] = mnew;
            float rsum = 0.f;
            #pragma unroll
            for (int j = 0; j < 4; j++) {
                s[i][j] = __expf(s[i][j] - mnew);
                rsum += s[i][j];
            }
            #pragma unroll
            for (int off = 8; off >= 1; off >>= 1)
                rsum += __shfl_xor_sync(0xffffffffu, rsum, off, 16);
            l[i] = l[i] * corr + rsum;
            #pragma unroll
            for (int j = 0; j < 4; j++) o[i][j] *= corr;
        }

        __syncthreads();
        #pragma unroll
        for (int i = 0; i < 4; i++) {
            float4 pv = make_float4(s[i][0], s[i][1], s[i][2], s[i][3]);
            *(float4*)&KPs[ty * 4 + i][tx * 4] = pv;
        }
        __syncthreads();

        #pragma unroll
        for (int c4 = 0; c4 < 16; c4++) {
            float4 p4[4], v4[4];
            #pragma unroll
            for (int i = 0; i < 4; i++)
                p4[i] = *(const float4*)&KPs[ty * 4 + i][c4 * 4];
            #pragma unroll
            for (int sub = 0; sub < 4; sub++)
                v4[sub] = *(const float4*)&Vs[c4 * 4 + sub][tx * 4];
            #pragma unroll
            for (int i = 0; i < 4; i++) {
                o[i][0] = fmaf(p4[i].x, v4[0].x, fmaf(p4[i].y, v4[1].x, fmaf(p4[i].z, v4[2].x, fmaf(p4[i].w, v4[3].x, o[i][0]))));
                o[i][1] = fmaf(p4[i].x, v4[0].y, fmaf(p4[i].y, v4[1].y, fmaf(p4[i].z, v4[2].y, fmaf(p4[i].w, v4[3].y, o[i][1]))));
                o[i][2] = fmaf(p4[i].x, v4[0].z, fmaf(p4[i].y, v4[1].z, fmaf(p4[i].z, v4[2].z, fmaf(p4[i].w, v4[3].z, o[i][2]))));
                o[i][3] = fmaf(p4[i].x, v4[0].w, fmaf(p4[i].y, v4[1].w, fmaf(p4[i].z, v4[2].w, fmaf(p4[i].w, v4[3].w, o[i][3]))));
            }
        }
    }

    #pragma unroll
    for (int i = 0; i < 4; i++) {
        float invl = 1.0f / l[i];
        float4 ov = make_float4(o[i][0] * invl, o[i][1] * invl,
                                o[i][2] * invl, o[i][3] * invl);
        size_t row = (size_t)b * T_ + q0 + ty * 4 + i;
        *(float4*)&g_ctx[row * C_ + h * D_ + tx * 4] = ov;
    }
}

// ---------------------------------------------------------------------------
extern "C" void kernel_launch(void* const* d_in, const int* in_sizes, int n_in,
                              void* d_out, int out_size)
{
    const float* x    = (const float*)d_in[0];
    const int*   am   = (const int*)d_in[1];
    const float* Wqkv = (const float*)d_in[2];
    const float* bqkv = (const float*)d_in[3];
    const float* Wo   = (const float*)d_in[4];
    const float* bo   = (const float*)d_in[5];
    float* out = (float*)d_out;

    float *qkv_p, *ctx_p;
    __nv_bfloat16 *xh, *xl, *ch, *cl, *wqh, *wql, *woh, *wol;
    cudaGetSymbolAddress((void**)&qkv_p, g_qkv);
    cudaGetSymbolAddress((void**)&ctx_p, g_ctx);
    cudaGetSymbolAddress((void**)&xh, g_xh);   cudaGetSymbolAddress((void**)&xl, g_xl);
    cudaGetSymbolAddress((void**)&ch, g_ch);   cudaGetSymbolAddress((void**)&cl, g_cl);
    cudaGetSymbolAddress((void**)&wqh, g_wqh); cudaGetSymbolAddress((void**)&wql, g_wql);
    cudaGetSymbolAddress((void**)&woh, g_woh); cudaGetSymbolAddress((void**)&wol, g_wol);

    static bool attr_done = false;
    if (!attr_done) {
        cudaFuncSetAttribute(gemm_bf16x3,
                             cudaFuncAttributeMaxDynamicSharedMemorySize, GS_TOTAL);
        attr_done = true;
    }

    mask_norm<<<1, 1024>>>(am);

    split_rm<<<(BT_ * C_ + 255) / 256, 256>>>(x, xh, xl, BT_ * C_);
    split_tr<<<(C_ * C3_ + 255) / 256, 256>>>(Wqkv, wqh, wql, C_, C3_);

    gemm_bf16x3<<<dim3(C3_ / 128, BT_ / 128), 256, GS_TOTAL>>>(
        xh, xl, wqh, wql, bqkv, qkv_p, BT_, C3_, C_);

    attn_kernel<<<dim3(T_ / 64, H_, B_), 256>>>(qkv_p, ctx_p);

    split_rm<<<(BT_ * C_ + 255) / 256, 256>>>(ctx_p, ch, cl, BT_ * C_);
    split_tr<<<(C_ * C_ + 255) / 256, 256>>>(Wo, woh, wol, C_, C_);
    gemm_bf16x3<<<dim3(C_ / 128, BT_ / 128), 256, GS_TOTAL>>>(
        ch, cl, woh, wol, bo, out, BT_, C_, C_);
}

// round 5
// speedup vs baseline: 2.2576x; 1.8222x over previous
#include <cuda_runtime.h>
#include <cuda_bf16.h>
#include <math.h>
#include <stdint.h>

#define B_ 4
#define T_ 2048
#define C_ 768
#define H_ 12
#define D_ 64
#define BT_ (B_ * T_)
#define C3_ (3 * C_)

// ---------------------------------------------------------------------------
// Device scratch (no runtime allocation allowed)
// ---------------------------------------------------------------------------
__device__ int g_keep[BT_];  // normalized mask: 1 = attended

__device__ __nv_bfloat16 g_xh[(size_t)BT_ * C_],   g_xl[(size_t)BT_ * C_];
__device__ __nv_bfloat16 g_qkvh[(size_t)BT_ * C3_], g_qkvl[(size_t)BT_ * C3_];
__device__ __nv_bfloat16 g_ch[(size_t)BT_ * C_],   g_cl[(size_t)BT_ * C_];
__device__ __nv_bfloat16 g_wqh[(size_t)C3_ * C_],  g_wql[(size_t)C3_ * C_];
__device__ __nv_bfloat16 g_woh[(size_t)C_ * C_],   g_wol[(size_t)C_ * C_];

// ---------------------------------------------------------------------------
// PTX helpers — portable tensor path (mma.sync / ldmatrix)
// ---------------------------------------------------------------------------
__device__ __forceinline__ uint32_t smem_u32(const void* p) {
    uint32_t a;
    asm("{ .reg .u64 t; cvta.to.shared.u64 t, %1; cvt.u32.u64 %0, t; }"
        : "=r"(a) : "l"(p));
    return a;
}
__device__ __forceinline__ void ldm_x4(uint32_t (&r)[4], uint32_t addr) {
    asm volatile("ldmatrix.sync.aligned.m8n8.x4.shared.b16 {%0,%1,%2,%3}, [%4];"
        : "=r"(r[0]), "=r"(r[1]), "=r"(r[2]), "=r"(r[3]) : "r"(addr));
}
__device__ __forceinline__ void ldm_x2(uint32_t (&r)[2], uint32_t addr) {
    asm volatile("ldmatrix.sync.aligned.m8n8.x2.shared.b16 {%0,%1}, [%2];"
        : "=r"(r[0]), "=r"(r[1]) : "r"(addr));
}
__device__ __forceinline__ void ldm_x2t(uint32_t (&r)[2], uint32_t addr) {
    asm volatile("ldmatrix.sync.aligned.m8n8.x2.trans.shared.b16 {%0,%1}, [%2];"
        : "=r"(r[0]), "=r"(r[1]) : "r"(addr));
}
__device__ __forceinline__ void mma_bf16(float (&d)[4], const uint32_t (&a)[4],
                                         const uint32_t (&b)[2]) {
    asm volatile(
        "mma.sync.aligned.m16n8k16.row.col.f32.bf16.bf16.f32 "
        "{%0,%1,%2,%3}, {%4,%5,%6,%7}, {%8,%9}, {%0,%1,%2,%3};"
        : "+f"(d[0]), "+f"(d[1]), "+f"(d[2]), "+f"(d[3])
        : "r"(a[0]), "r"(a[1]), "r"(a[2]), "r"(a[3]), "r"(b[0]), "r"(b[1]));
}
#define SW128(o) ((o) ^ (((o) >> 3) & 0x70))

// ---------------------------------------------------------------------------
// Mask normalizer (int32 or int64 words; detect at runtime)
// ---------------------------------------------------------------------------
__global__ __launch_bounds__(1024) void mask_norm(const int* __restrict__ amw)
{
    const int tid = threadIdx.x;
    int allzero = 1;
    for (int i = tid; i < BT_; i += 1024)
        if (i & 1) allzero &= (amw[i] == 0);
    int is64 = __syncthreads_and(allzero);
    for (int i = tid; i < BT_; i += 1024) {
        int v = is64 ? amw[2 * i] : amw[i];
        g_keep[i] = (v == 0) ? 1 : 0;
    }
}

// ---------------------------------------------------------------------------
// fp32 -> bf16 hi/lo split kernels
// ---------------------------------------------------------------------------
__global__ __launch_bounds__(256) void split_rm(
    const float* __restrict__ in, __nv_bfloat16* __restrict__ hi,
    __nv_bfloat16* __restrict__ lo, int n)
{
    int i = blockIdx.x * 256 + threadIdx.x;
    if (i >= n) return;
    float x = in[i];
    __nv_bfloat16 h = __float2bfloat16(x);
    hi[i] = h;
    lo[i] = __float2bfloat16(x - __bfloat162float(h));
}

__global__ __launch_bounds__(256) void split_tr(
    const float* __restrict__ in, __nv_bfloat16* __restrict__ hi,
    __nv_bfloat16* __restrict__ lo, int K, int N)
{
    int i = blockIdx.x * 256 + threadIdx.x;
    if (i >= K * N) return;
    int k = i / N, n = i - k * N;
    float x = in[i];
    __nv_bfloat16 h = __float2bfloat16(x);
    hi[(size_t)n * K + k] = h;
    lo[(size_t)n * K + k] = __float2bfloat16(x - __bfloat162float(h));
}

// ---------------------------------------------------------------------------
// bf16x3 HMMA GEMM: CTA 128x128, 8 warps, warp tile 64x32, K staged 64/iter.
// Output: fp32 (Out) or bf16 hi/lo (Oh/Ol) when Oh != nullptr. Bias added.
// ---------------------------------------------------------------------------
#define GS_AH 0
#define GS_AL 16384
#define GS_BH 32768
#define GS_BL 49152
#define GS_TOTAL 65536

__global__ __launch_bounds__(256) void gemm_bf16x3(
    const __nv_bfloat16* __restrict__ Ah, const __nv_bfloat16* __restrict__ Al,
    const __nv_bfloat16* __restrict__ Bh, const __nv_bfloat16* __restrict__ Bl,
    const float* __restrict__ bias, float* __restrict__ Out,
    __nv_bfloat16* __restrict__ Oh, __nv_bfloat16* __restrict__ Ol,
    int M, int N, int K)
{
    extern __shared__ __align__(1024) char smem[];
    const uint32_t sb = smem_u32(smem);
    const int tid  = threadIdx.x;
    const int wid  = tid >> 5;
    const int lane = tid & 31;
    const int m0 = blockIdx.y * 128;
    const int n0 = blockIdx.x * 128;
    const int wm = wid >> 2;
    const int wn = wid & 3;

    float acc[4][4][4];
    #pragma unroll
    for (int i = 0; i < 4; i++)
        #pragma unroll
        for (int j = 0; j < 4; j++)
            #pragma unroll
            for (int r = 0; r < 4; r++) acc[i][j][r] = 0.f;

    const int nstages = K / 64;
    for (int s = 0; s < nstages; s++) {
        const int k0 = s * 64;
        #pragma unroll
        for (int i = 0; i < 4; i++) {
            int u = tid + 256 * i;
            int r = u >> 3, uk = u & 7;
            uint32_t so = SW128((uint32_t)(r * 128 + uk * 16));
            size_t ga = (size_t)(m0 + r) * K + k0 + uk * 8;
            size_t gb = (size_t)(n0 + r) * K + k0 + uk * 8;
            *(uint4*)(smem + GS_AH + so) = *(const uint4*)(Ah + ga);
            *(uint4*)(smem + GS_AL + so) = *(const uint4*)(Al + ga);
            *(uint4*)(smem + GS_BH + so) = *(const uint4*)(Bh + gb);
            *(uint4*)(smem + GS_BL + so) = *(const uint4*)(Bl + gb);
        }
        __syncthreads();

        #pragma unroll
        for (int kk = 0; kk < 4; kk++) {
            uint32_t bh[4][2], bl[4][2];
            #pragma unroll
            for (int nt = 0; nt < 4; nt++) {
                uint32_t rn = (uint32_t)(wn * 32 + nt * 8 + (lane & 7));
                uint32_t so = SW128(rn * 128 + kk * 32 + (((lane >> 3) & 1) << 4));
                ldm_x2(bh[nt], sb + GS_BH + so);
                ldm_x2(bl[nt], sb + GS_BL + so);
            }
            #pragma unroll
            for (int mt = 0; mt < 4; mt++) {
                uint32_t rm = (uint32_t)(wm * 64 + mt * 16 + (lane & 15));
                uint32_t so = SW128(rm * 128 + kk * 32 + ((lane >> 4) << 4));
                uint32_t ah[4], al[4];
                ldm_x4(ah, sb + GS_AH + so);
                ldm_x4(al, sb + GS_AL + so);
                #pragma unroll
                for (int nt = 0; nt < 4; nt++) {
                    mma_bf16(acc[mt][nt], ah, bh[nt]);
                    mma_bf16(acc[mt][nt], ah, bl[nt]);
                    mma_bf16(acc[mt][nt], al, bh[nt]);
                }
            }
        }
        __syncthreads();
    }

    #pragma unroll
    for (int mt = 0; mt < 4; mt++) {
        #pragma unroll
        for (int nt = 0; nt < 4; nt++) {
            int grow = m0 + wm * 64 + mt * 16 + (lane >> 2);
            int gcol = n0 + wn * 32 + nt * 8 + (lane & 3) * 2;
            float2 bb = *(const float2*)&bias[gcol];
            float v0 = acc[mt][nt][0] + bb.x, v1 = acc[mt][nt][1] + bb.y;
            float v2 = acc[mt][nt][2] + bb.x, v3 = acc[mt][nt][3] + bb.y;
            if (Oh) {
                __nv_bfloat162 h2, l2;
                h2.x = __float2bfloat16(v0);
                h2.y = __float2bfloat16(v1);
                l2.x = __float2bfloat16(v0 - __bfloat162float(h2.x));
                l2.y = __float2bfloat16(v1 - __bfloat162float(h2.y));
                *(__nv_bfloat162*)&Oh[(size_t)grow * N + gcol] = h2;
                *(__nv_bfloat162*)&Ol[(size_t)grow * N + gcol] = l2;
                h2.x = __float2bfloat16(v2);
                h2.y = __float2bfloat16(v3);
                l2.x = __float2bfloat16(v2 - __bfloat162float(h2.x));
                l2.y = __float2bfloat16(v3 - __bfloat162float(h2.y));
                *(__nv_bfloat162*)&Oh[(size_t)(grow + 8) * N + gcol] = h2;
                *(__nv_bfloat162*)&Ol[(size_t)(grow + 8) * N + gcol] = l2;
            } else {
                *(float2*)&Out[(size_t)grow * N + gcol] = make_float2(v0, v1);
                *(float2*)&Out[(size_t)(grow + 8) * N + gcol] = make_float2(v2, v3);
            }
        }
    }
}

// ---------------------------------------------------------------------------
// Flash attention on mma.sync. 64x64 tiles, 8 warps (4 row-bands x 2 halves).
// QK^T = QhKh+QhKl+QlKh;  PV = PhVh+PhVl+PlVh with P split in-kernel.
// Writes context as bf16 hi/lo for the output-projection GEMM.
// ---------------------------------------------------------------------------
#define AQ_H   0
#define AQ_L   8192
#define AKP_H  16384   // K^ tiles, overwritten by P
#define AKP_L  24576
#define AV_H   32768
#define AV_L   40960
#define A_BIAS 49152   // 64 fp32 mask bias
#define A_REDM 49408   // float[64][2]
#define A_REDS 49920   // float[64][2]
#define A_TOTAL 50432

__global__ __launch_bounds__(256) void attn_mma(
    const __nv_bfloat16* __restrict__ qkvh,
    const __nv_bfloat16* __restrict__ qkvl,
    __nv_bfloat16* __restrict__ ch, __nv_bfloat16* __restrict__ cl)
{
    extern __shared__ __align__(1024) char smem[];
    const uint32_t sb = smem_u32(smem);
    float* sbias = (float*)(smem + A_BIAS);
    float (*redm)[2] = (float(*)[2])(smem + A_REDM);
    float (*reds)[2] = (float(*)[2])(smem + A_REDS);

    const int tid  = threadIdx.x;
    const int wid  = tid >> 5;
    const int lane = tid & 31;
    const int wm = wid >> 1;       // 0..3 -> q rows wm*16
    const int wn = wid & 1;        // 0..1 -> cols wn*32
    const int q0 = blockIdx.x * 64;
    const int h  = blockIdx.y;
    const int b  = blockIdx.z;

    const size_t rowbase = (size_t)b * T_;
    const int* keepb = g_keep + b * T_;

    // Load Q tile once (hi/lo): 64 rows x 64 bf16 (128B rows), SW128.
    #pragma unroll
    for (int i = 0; i < 2; i++) {
        int u = tid + 256 * i;
        int r = u >> 3, uk = u & 7;
        uint32_t so = SW128((uint32_t)(r * 128 + uk * 16));
        size_t g = (rowbase + q0 + r) * C3_ + h * D_ + uk * 8;
        *(uint4*)(smem + AQ_H + so) = *(const uint4*)(qkvh + g);
        *(uint4*)(smem + AQ_L + so) = *(const uint4*)(qkvl + g);
    }

    const int r0 = wm * 16 + (lane >> 2);
    const int r1 = r0 + 8;

    float mrow[2] = {-INFINITY, -INFINITY};
    float lrow[2] = {0.f, 0.f};
    float o[4][4];
    #pragma unroll
    for (int nt = 0; nt < 4; nt++)
        #pragma unroll
        for (int r = 0; r < 4; r++) o[nt][r] = 0.f;

    for (int kb = 0; kb < 32; kb++) {
        const int k0 = kb * 64;
        __syncthreads();   // prior iter's MMA reads of K/P/V smem complete

        // Load K, V tiles (hi/lo) + mask bias
        #pragma unroll
        for (int i = 0; i < 2; i++) {
            int u = tid + 256 * i;
            int r = u >> 3, uk = u & 7;
            uint32_t so = SW128((uint32_t)(r * 128 + uk * 16));
            size_t gk = (rowbase + k0 + r) * C3_ + C_ + h * D_ + uk * 8;
            size_t gv = (rowbase + k0 + r) * C3_ + 2 * C_ + h * D_ + uk * 8;
            *(uint4*)(smem + AKP_H + so) = *(const uint4*)(qkvh + gk);
            *(uint4*)(smem + AKP_L + so) = *(const uint4*)(qkvl + gk);
            *(uint4*)(smem + AV_H + so)  = *(const uint4*)(qkvh + gv);
            *(uint4*)(smem + AV_L + so)  = *(const uint4*)(qkvl + gv);
        }
        if (tid < 64) sbias[tid] = keepb[k0 + tid] ? 0.f : -1e30f;
        __syncthreads();

        // S = Q @ K^T (bf16x3)
        float s[4][4];
        #pragma unroll
        for (int nt = 0; nt < 4; nt++)
            #pragma unroll
            for (int r = 0; r < 4; r++) s[nt][r] = 0.f;

        #pragma unroll
        for (int kk = 0; kk < 4; kk++) {
            uint32_t rm = (uint32_t)(wm * 16 + (lane & 15));
            uint32_t soa = SW128(rm * 128 + kk * 32 + ((lane >> 4) << 4));
            uint32_t qh[4], ql[4];
            ldm_x4(qh, sb + AQ_H + soa);
            ldm_x4(ql, sb + AQ_L + soa);
            #pragma unroll
            for (int nt = 0; nt < 4; nt++) {
                uint32_t rn = (uint32_t)(wn * 32 + nt * 8 + (lane & 7));
                uint32_t sob = SW128(rn * 128 + kk * 32 + (((lane >> 3) & 1) << 4));
                uint32_t kh[2], kl[2];
                ldm_x2(kh, sb + AKP_H + sob);
                ldm_x2(kl, sb + AKP_L + sob);
                mma_bf16(s[nt], qh, kh);
                mma_bf16(s[nt], qh, kl);
                mma_bf16(s[nt], ql, kh);
            }
        }

        // Scale + mask bias
        #pragma unroll
        for (int nt = 0; nt < 4; nt++) {
            int c = wn * 32 + nt * 8 + (lane & 3) * 2;
            float b0 = sbias[c], b1 = sbias[c + 1];
            s[nt][0] = s[nt][0] * 0.125f + b0;
            s[nt][1] = s[nt][1] * 0.125f + b1;
            s[nt][2] = s[nt][2] * 0.125f + b0;
            s[nt][3] = s[nt][3] * 0.125f + b1;
        }

        // Row max: local -> quad shuffle -> cross-warp-half via smem
        float mx0 = -INFINITY, mx1 = -INFINITY;
        #pragma unroll
        for (int nt = 0; nt < 4; nt++) {
            mx0 = fmaxf(mx0, fmaxf(s[nt][0], s[nt][1]));
            mx1 = fmaxf(mx1, fmaxf(s[nt][2], s[nt][3]));
        }
        mx0 = fmaxf(mx0, __shfl_xor_sync(0xffffffffu, mx0, 1));
        mx0 = fmaxf(mx0, __shfl_xor_sync(0xffffffffu, mx0, 2));
        mx1 = fmaxf(mx1, __shfl_xor_sync(0xffffffffu, mx1, 1));
        mx1 = fmaxf(mx1, __shfl_xor_sync(0xffffffffu, mx1, 2));
        if ((lane & 3) == 0) { redm[r0][wn] = mx0; redm[r1][wn] = mx1; }
        __syncthreads();
        float mnew0 = fmaxf(mrow[0], fmaxf(redm[r0][0], redm[r0][1]));
        float mnew1 = fmaxf(mrow[1], fmaxf(redm[r1][0], redm[r1][1]));
        float corr0 = __expf(mrow[0] - mnew0);
        float corr1 = __expf(mrow[1] - mnew1);
        mrow[0] = mnew0; mrow[1] = mnew1;

        // exp + row sum
        float sm0 = 0.f, sm1 = 0.f;
        #pragma unroll
        for (int nt = 0; nt < 4; nt++) {
            s[nt][0] = __expf(s[nt][0] - mnew0);
            s[nt][1] = __expf(s[nt][1] - mnew0);
            s[nt][2] = __expf(s[nt][2] - mnew1);
            s[nt][3] = __expf(s[nt][3] - mnew1);
            sm0 += s[nt][0] + s[nt][1];
            sm1 += s[nt][2] + s[nt][3];
        }
        sm0 += __shfl_xor_sync(0xffffffffu, sm0, 1);
        sm0 += __shfl_xor_sync(0xffffffffu, sm0, 2);
        sm1 += __shfl_xor_sync(0xffffffffu, sm1, 1);
        sm1 += __shfl_xor_sync(0xffffffffu, sm1, 2);
        if ((lane & 3) == 0) { reds[r0][wn] = sm0; reds[r1][wn] = sm1; }
        __syncthreads();
        lrow[0] = lrow[0] * corr0 + reds[r0][0] + reds[r0][1];
        lrow[1] = lrow[1] * corr1 + reds[r1][0] + reds[r1][1];
        #pragma unroll
        for (int nt = 0; nt < 4; nt++) {
            o[nt][0] *= corr0; o[nt][1] *= corr0;
            o[nt][2] *= corr1; o[nt][3] *= corr1;
        }

        // P (hi/lo bf16) overwrites K smem tiles
        #pragma unroll
        for (int nt = 0; nt < 4; nt++) {
            int c = wn * 32 + nt * 8 + (lane & 3) * 2;
            uint32_t so0 = SW128((uint32_t)(r0 * 128 + c * 2));
            uint32_t so1 = SW128((uint32_t)(r1 * 128 + c * 2));
            __nv_bfloat162 h2, l2;
            h2.x = __float2bfloat16(s[nt][0]);
            h2.y = __float2bfloat16(s[nt][1]);
            l2.x = __float2bfloat16(s[nt][0] - __bfloat162float(h2.x));
            l2.y = __float2bfloat16(s[nt][1] - __bfloat162float(h2.y));
            *(__nv_bfloat162*)(smem + AKP_H + so0) = h2;
            *(__nv_bfloat162*)(smem + AKP_L + so0) = l2;
            h2.x = __float2bfloat16(s[nt][2]);
            h2.y = __float2bfloat16(s[nt][3]);
            l2.x = __float2bfloat16(s[nt][2] - __bfloat162float(h2.x));
            l2.y = __float2bfloat16(s[nt][3] - __bfloat162float(h2.y));
            *(__nv_bfloat162*)(smem + AKP_H + so1) = h2;
            *(__nv_bfloat162*)(smem + AKP_L + so1) = l2;
        }
        __syncthreads();

        // O += P @ V (bf16x3); V^T fragments via ldmatrix.trans
        #pragma unroll
        for (int kk = 0; kk < 4; kk++) {
            uint32_t rm = (uint32_t)(wm * 16 + (lane & 15));
            uint32_t soa = SW128(rm * 128 + kk * 32 + ((lane >> 4) << 4));
            uint32_t ph[4], pl[4];
            ldm_x4(ph, sb + AKP_H + soa);
            ldm_x4(pl, sb + AKP_L + soa);
            #pragma unroll
            for (int nt = 0; nt < 4; nt++) {
                uint32_t rv = (uint32_t)(kk * 16 + (lane & 15));
                uint32_t sov = SW128(rv * 128 + (wn * 32 + nt * 8) * 2);
                uint32_t vh[2], vl[2];
                ldm_x2t(vh, sb + AV_H + sov);
                ldm_x2t(vl, sb + AV_L + sov);
                mma_bf16(o[nt], ph, vh);
                mma_bf16(o[nt], ph, vl);
                mma_bf16(o[nt], pl, vh);
            }
        }
    }

    // Epilogue: normalize, split to bf16 hi/lo context
    float inv0 = 1.0f / lrow[0];
    float inv1 = 1.0f / lrow[1];
    #pragma unroll
    for (int nt = 0; nt < 4; nt++) {
        int c = h * D_ + wn * 32 + nt * 8 + (lane & 3) * 2;
        size_t g0 = (rowbase + q0 + r0) * C_ + c;
        size_t g1 = (rowbase + q0 + r1) * C_ + c;
        float v0 = o[nt][0] * inv0, v1 = o[nt][1] * inv0;
        float v2 = o[nt][2] * inv1, v3 = o[nt][3] * inv1;
        __nv_bfloat162 h2, l2;
        h2.x = __float2bfloat16(v0);
        h2.y = __float2bfloat16(v1);
        l2.x = __float2bfloat16(v0 - __bfloat162float(h2.x));
        l2.y = __float2bfloat16(v1 - __bfloat162float(h2.y));
        *(__nv_bfloat162*)&ch[g0] = h2;
        *(__nv_bfloat162*)&cl[g0] = l2;
        h2.x = __float2bfloat16(v2);
        h2.y = __float2bfloat16(v3);
        l2.x = __float2bfloat16(v2 - __bfloat162float(h2.x));
        l2.y = __float2bfloat16(v3 - __bfloat162float(h2.y));
        *(__nv_bfloat162*)&ch[g1] = h2;
        *(__nv_bfloat162*)&cl[g1] = l2;
    }
}

// ---------------------------------------------------------------------------
extern "C" void kernel_launch(void* const* d_in, const int* in_sizes, int n_in,
                              void* d_out, int out_size)
{
    const float* x    = (const float*)d_in[0];
    const int*   am   = (const int*)d_in[1];
    const float* Wqkv = (const float*)d_in[2];
    const float* bqkv = (const float*)d_in[3];
    const float* Wo   = (const float*)d_in[4];
    const float* bo   = (const float*)d_in[5];
    float* out = (float*)d_out;

    __nv_bfloat16 *xh, *xl, *qh, *ql, *ch, *cl, *wqh, *wql, *woh, *wol;
    cudaGetSymbolAddress((void**)&xh, g_xh);     cudaGetSymbolAddress((void**)&xl, g_xl);
    cudaGetSymbolAddress((void**)&qh, g_qkvh);   cudaGetSymbolAddress((void**)&ql, g_qkvl);
    cudaGetSymbolAddress((void**)&ch, g_ch);     cudaGetSymbolAddress((void**)&cl, g_cl);
    cudaGetSymbolAddress((void**)&wqh, g_wqh);   cudaGetSymbolAddress((void**)&wql, g_wql);
    cudaGetSymbolAddress((void**)&woh, g_woh);   cudaGetSymbolAddress((void**)&wol, g_wol);

    static bool attr_done = false;
    if (!attr_done) {
        cudaFuncSetAttribute(gemm_bf16x3,
                             cudaFuncAttributeMaxDynamicSharedMemorySize, GS_TOTAL);
        cudaFuncSetAttribute(attn_mma,
                             cudaFuncAttributeMaxDynamicSharedMemorySize, A_TOTAL);
        attr_done = true;
    }

    mask_norm<<<1, 1024>>>(am);
    split_rm<<<(BT_ * C_ + 255) / 256, 256>>>(x, xh, xl, BT_ * C_);
    split_tr<<<(C_ * C3_ + 255) / 256, 256>>>(Wqkv, wqh, wql, C_, C3_);

    // 1) QKV projection -> bf16 hi/lo directly
    gemm_bf16x3<<<dim3(C3_ / 128, BT_ / 128), 256, GS_TOTAL>>>(
        xh, xl, wqh, wql, bqkv, nullptr, qh, ql, BT_, C3_, C_);

    // 2) Attention (tensor cores) -> ctx bf16 hi/lo
    attn_mma<<<dim3(T_ / 64, H_, B_), 256, A_TOTAL>>>(qh, ql, ch, cl);

    // 3) Output projection -> fp32 out
    split_tr<<<(C_ * C_ + 255) / 256, 256>>>(Wo, woh, wol, C_, C_);
    gemm_bf16x3<<<dim3(C_ / 128, BT_ / 128), 256, GS_TOTAL>>>(
        ch, cl, woh, wol, bo, out, nullptr, nullptr, BT_, C_, C_);
}

// round 6
// speedup vs baseline: 2.9740x; 1.3173x over previous
#include <cuda_runtime.h>
#include <cuda_bf16.h>
#include <math.h>
#include <stdint.h>

#define B_ 4
#define T_ 2048
#define C_ 768
#define H_ 12
#define D_ 64
#define BT_ (B_ * T_)
#define C3_ (3 * C_)

// ---------------------------------------------------------------------------
// Device scratch (no runtime allocation allowed)
// ---------------------------------------------------------------------------
__device__ int g_keep[BT_];

__device__ __nv_bfloat16 g_xh[(size_t)BT_ * C_],    g_xl[(size_t)BT_ * C_];
__device__ __nv_bfloat16 g_qkvh[(size_t)BT_ * C3_], g_qkvl[(size_t)BT_ * C3_];
__device__ __nv_bfloat16 g_ch[(size_t)BT_ * C_],    g_cl[(size_t)BT_ * C_];
__device__ __nv_bfloat16 g_wqh[(size_t)C3_ * C_],   g_wql[(size_t)C3_ * C_];
__device__ __nv_bfloat16 g_woh[(size_t)C_ * C_],    g_wol[(size_t)C_ * C_];

// ---------------------------------------------------------------------------
// PTX helpers — portable tensor path (mma.sync / ldmatrix / cp.async)
// ---------------------------------------------------------------------------
__device__ __forceinline__ uint32_t smem_u32(const void* p) {
    uint32_t a;
    asm("{ .reg .u64 t; cvta.to.shared.u64 t, %1; cvt.u32.u64 %0, t; }"
        : "=r"(a) : "l"(p));
    return a;
}
__device__ __forceinline__ void ldm_x4(uint32_t (&r)[4], uint32_t addr) {
    asm volatile("ldmatrix.sync.aligned.m8n8.x4.shared.b16 {%0,%1,%2,%3}, [%4];"
        : "=r"(r[0]), "=r"(r[1]), "=r"(r[2]), "=r"(r[3]) : "r"(addr));
}
__device__ __forceinline__ void ldm_x2(uint32_t (&r)[2], uint32_t addr) {
    asm volatile("ldmatrix.sync.aligned.m8n8.x2.shared.b16 {%0,%1}, [%2];"
        : "=r"(r[0]), "=r"(r[1]) : "r"(addr));
}
__device__ __forceinline__ void ldm_x2t(uint32_t (&r)[2], uint32_t addr) {
    asm volatile("ldmatrix.sync.aligned.m8n8.x2.trans.shared.b16 {%0,%1}, [%2];"
        : "=r"(r[0]), "=r"(r[1]) : "r"(addr));
}
__device__ __forceinline__ void mma_bf16(float (&d)[4], const uint32_t (&a)[4],
                                         const uint32_t (&b)[2]) {
    asm volatile(
        "mma.sync.aligned.m16n8k16.row.col.f32.bf16.bf16.f32 "
        "{%0,%1,%2,%3}, {%4,%5,%6,%7}, {%8,%9}, {%0,%1,%2,%3};"
        : "+f"(d[0]), "+f"(d[1]), "+f"(d[2]), "+f"(d[3])
        : "r"(a[0]), "r"(a[1]), "r"(a[2]), "r"(a[3]), "r"(b[0]), "r"(b[1]));
}
__device__ __forceinline__ void cp16(uint32_t saddr, const void* g) {
    asm volatile("cp.async.cg.shared.global [%0], [%1], 16;"
        :: "r"(saddr), "l"(g));
}
#define CP_COMMIT() asm volatile("cp.async.commit_group;" ::: "memory")
#define CP_WAIT(n)  asm volatile("cp.async.wait_group %0;" :: "n"(n) : "memory")
#define SW128(o) ((o) ^ (((o) >> 3) & 0x70))

// ---------------------------------------------------------------------------
__global__ __launch_bounds__(1024) void mask_norm(const int* __restrict__ amw)
{
    const int tid = threadIdx.x;
    int allzero = 1;
    for (int i = tid; i < BT_; i += 1024)
        if (i & 1) allzero &= (amw[i] == 0);
    int is64 = __syncthreads_and(allzero);
    for (int i = tid; i < BT_; i += 1024) {
        int v = is64 ? amw[2 * i] : amw[i];
        g_keep[i] = (v == 0) ? 1 : 0;
    }
}

__global__ __launch_bounds__(256) void split_rm(
    const float* __restrict__ in, __nv_bfloat16* __restrict__ hi,
    __nv_bfloat16* __restrict__ lo, int n)
{
    int i = blockIdx.x * 256 + threadIdx.x;
    if (i >= n) return;
    float x = in[i];
    __nv_bfloat16 h = __float2bfloat16(x);
    hi[i] = h;
    lo[i] = __float2bfloat16(x - __bfloat162float(h));
}

__global__ __launch_bounds__(256) void split_tr(
    const float* __restrict__ in, __nv_bfloat16* __restrict__ hi,
    __nv_bfloat16* __restrict__ lo, int K, int N)
{
    int i = blockIdx.x * 256 + threadIdx.x;
    if (i >= K * N) return;
    int k = i / N, n = i - k * N;
    float x = in[i];
    __nv_bfloat16 h = __float2bfloat16(x);
    hi[(size_t)n * K + k] = h;
    lo[(size_t)n * K + k] = __float2bfloat16(x - __bfloat162float(h));
}

// ---------------------------------------------------------------------------
// bf16x3 HMMA GEMM, cp.async double-buffered.
// CTA 128x128, 8 warps, warp tile 64x32, K staged 64/iter.
// ---------------------------------------------------------------------------
#define GS_AH 0
#define GS_AL 16384
#define GS_BH 32768
#define GS_BL 49152
#define GSTG  65536           // bytes per stage
#define GS_TOTAL (2 * GSTG)

__global__ __launch_bounds__(256) void gemm_bf16x3(
    const __nv_bfloat16* __restrict__ Ah, const __nv_bfloat16* __restrict__ Al,
    const __nv_bfloat16* __restrict__ Bh, const __nv_bfloat16* __restrict__ Bl,
    const float* __restrict__ bias, float* __restrict__ Out,
    __nv_bfloat16* __restrict__ Oh, __nv_bfloat16* __restrict__ Ol,
    int M, int N, int K)
{
    extern __shared__ __align__(1024) char smem[];
    const uint32_t sb = smem_u32(smem);
    const int tid  = threadIdx.x;
    const int wid  = tid >> 5;
    const int lane = tid & 31;
    const int m0 = blockIdx.y * 128;
    const int n0 = blockIdx.x * 128;
    const int wm = wid >> 2;
    const int wn = wid & 3;

    // Per-thread staging coords (4 16B units per tile)
    int lr[4], luk[4];
    uint32_t lso[4];
    #pragma unroll
    for (int i = 0; i < 4; i++) {
        int u = tid + 256 * i;
        lr[i] = u >> 3; luk[i] = u & 7;
        lso[i] = SW128((uint32_t)(lr[i] * 128 + luk[i] * 16));
    }

    const int nstages = K / 64;
    auto stage_load = [&](int s, uint32_t dst) {
        const int k0 = s * 64;
        #pragma unroll
        for (int i = 0; i < 4; i++) {
            size_t ga = (size_t)(m0 + lr[i]) * K + k0 + luk[i] * 8;
            size_t gb = (size_t)(n0 + lr[i]) * K + k0 + luk[i] * 8;
            cp16(dst + GS_AH + lso[i], Ah + ga);
            cp16(dst + GS_AL + lso[i], Al + ga);
            cp16(dst + GS_BH + lso[i], Bh + gb);
            cp16(dst + GS_BL + lso[i], Bl + gb);
        }
    };

    float acc[4][4][4];
    #pragma unroll
    for (int i = 0; i < 4; i++)
        #pragma unroll
        for (int j = 0; j < 4; j++)
            #pragma unroll
            for (int r = 0; r < 4; r++) acc[i][j][r] = 0.f;

    stage_load(0, sb);
    CP_COMMIT();

    for (int s = 0; s < nstages; s++) {
        const uint32_t cur = sb + (uint32_t)(s & 1) * GSTG;
        if (s + 1 < nstages) {
            stage_load(s + 1, sb + (uint32_t)((s + 1) & 1) * GSTG);
            CP_COMMIT();
            CP_WAIT(1);
        } else {
            CP_WAIT(0);
        }
        __syncthreads();

        #pragma unroll
        for (int kk = 0; kk < 4; kk++) {
            uint32_t bh[4][2], bl[4][2];
            #pragma unroll
            for (int nt = 0; nt < 4; nt++) {
                uint32_t rn = (uint32_t)(wn * 32 + nt * 8 + (lane & 7));
                uint32_t so = SW128(rn * 128 + kk * 32 + (((lane >> 3) & 1) << 4));
                ldm_x2(bh[nt], cur + GS_BH + so);
                ldm_x2(bl[nt], cur + GS_BL + so);
            }
            #pragma unroll
            for (int mt = 0; mt < 4; mt++) {
                uint32_t rm = (uint32_t)(wm * 64 + mt * 16 + (lane & 15));
                uint32_t so = SW128(rm * 128 + kk * 32 + ((lane >> 4) << 4));
                uint32_t ah[4], al[4];
                ldm_x4(ah, cur + GS_AH + so);
                ldm_x4(al, cur + GS_AL + so);
                #pragma unroll
                for (int nt = 0; nt < 4; nt++) {
                    mma_bf16(acc[mt][nt], ah, bh[nt]);
                    mma_bf16(acc[mt][nt], ah, bl[nt]);
                    mma_bf16(acc[mt][nt], al, bh[nt]);
                }
            }
        }
        __syncthreads();   // all reads of cur done before it is re-filled at s+2
    }

    #pragma unroll
    for (int mt = 0; mt < 4; mt++) {
        #pragma unroll
        for (int nt = 0; nt < 4; nt++) {
            int grow = m0 + wm * 64 + mt * 16 + (lane >> 2);
            int gcol = n0 + wn * 32 + nt * 8 + (lane & 3) * 2;
            float2 bb = *(const float2*)&bias[gcol];
            float v0 = acc[mt][nt][0] + bb.x, v1 = acc[mt][nt][1] + bb.y;
            float v2 = acc[mt][nt][2] + bb.x, v3 = acc[mt][nt][3] + bb.y;
            if (Oh) {
                __nv_bfloat162 h2, l2;
                h2.x = __float2bfloat16(v0);
                h2.y = __float2bfloat16(v1);
                l2.x = __float2bfloat16(v0 - __bfloat162float(h2.x));
                l2.y = __float2bfloat16(v1 - __bfloat162float(h2.y));
                *(__nv_bfloat162*)&Oh[(size_t)grow * N + gcol] = h2;
                *(__nv_bfloat162*)&Ol[(size_t)grow * N + gcol] = l2;
                h2.x = __float2bfloat16(v2);
                h2.y = __float2bfloat16(v3);
                l2.x = __float2bfloat16(v2 - __bfloat162float(h2.x));
                l2.y = __float2bfloat16(v3 - __bfloat162float(h2.y));
                *(__nv_bfloat162*)&Oh[(size_t)(grow + 8) * N + gcol] = h2;
                *(__nv_bfloat162*)&Ol[(size_t)(grow + 8) * N + gcol] = l2;
            } else {
                *(float2*)&Out[(size_t)grow * N + gcol] = make_float2(v0, v1);
                *(float2*)&Out[(size_t)(grow + 8) * N + gcol] = make_float2(v2, v3);
            }
        }
    }
}

// ---------------------------------------------------------------------------
// Flash attention on mma.sync, cp.async double-buffered K/V.
// 64x64 tiles, 8 warps (4 row-bands x 2 col-halves).
// ---------------------------------------------------------------------------
#define AQ_H   0
#define AQ_L   8192
#define ASTG_BASE 16384
#define ASTG   32768          // per-stage: K_H(0) K_L(8192) V_H(16384) V_L(24576)
#define AP_H   81920
#define AP_L   90112
#define A_BIAS 98304
#define A_REDM 98560
#define A_REDS 99072
#define A_TOTAL 99584

__global__ __launch_bounds__(256) void attn_mma(
    const __nv_bfloat16* __restrict__ qkvh,
    const __nv_bfloat16* __restrict__ qkvl,
    __nv_bfloat16* __restrict__ ch, __nv_bfloat16* __restrict__ cl)
{
    extern __shared__ __align__(1024) char smem[];
    const uint32_t sb = smem_u32(smem);
    float* sbias = (float*)(smem + A_BIAS);
    float (*redm)[2] = (float(*)[2])(smem + A_REDM);
    float (*reds)[2] = (float(*)[2])(smem + A_REDS);

    const int tid  = threadIdx.x;
    const int wid  = tid >> 5;
    const int lane = tid & 31;
    const int wm = wid >> 1;
    const int wn = wid & 1;
    const int q0 = blockIdx.x * 64;
    const int h  = blockIdx.y;
    const int b  = blockIdx.z;

    const size_t rowbase = (size_t)b * T_;
    const int* keepb = g_keep + b * T_;

    // Per-thread staging coords (2 16B units per 8KB tile)
    int lr[2], luk[2];
    uint32_t lso[2];
    #pragma unroll
    for (int i = 0; i < 2; i++) {
        int u = tid + 256 * i;
        lr[i] = u >> 3; luk[i] = u & 7;
        lso[i] = SW128((uint32_t)(lr[i] * 128 + luk[i] * 16));
    }

    auto kv_load = [&](int kb, uint32_t dst) {
        const int k0 = kb * 64;
        #pragma unroll
        for (int i = 0; i < 2; i++) {
            size_t gk = (rowbase + k0 + lr[i]) * C3_ + C_ + h * D_ + luk[i] * 8;
            size_t gv = (rowbase + k0 + lr[i]) * C3_ + 2 * C_ + h * D_ + luk[i] * 8;
            cp16(dst + 0     + lso[i], qkvh + gk);
            cp16(dst + 8192  + lso[i], qkvl + gk);
            cp16(dst + 16384 + lso[i], qkvh + gv);
            cp16(dst + 24576 + lso[i], qkvl + gv);
        }
    };

    // Q tile (hi/lo) via cp.async too
    #pragma unroll
    for (int i = 0; i < 2; i++) {
        size_t g = (rowbase + q0 + lr[i]) * C3_ + h * D_ + luk[i] * 8;
        cp16(sb + AQ_H + lso[i], qkvh + g);
        cp16(sb + AQ_L + lso[i], qkvl + g);
    }
    kv_load(0, sb + ASTG_BASE);
    CP_COMMIT();

    const int r0 = wm * 16 + (lane >> 2);
    const int r1 = r0 + 8;

    float mrow[2] = {-INFINITY, -INFINITY};
    float lrow[2] = {0.f, 0.f};
    float o[4][4];
    #pragma unroll
    for (int nt = 0; nt < 4; nt++)
        #pragma unroll
        for (int r = 0; r < 4; r++) o[nt][r] = 0.f;

    for (int kb = 0; kb < 32; kb++) {
        const int k0 = kb * 64;
        const uint32_t cur = sb + ASTG_BASE + (uint32_t)(kb & 1) * ASTG;

        // Issue mask LDG early to overlap with the wait
        int keepv = 0;
        if (tid < 64) keepv = keepb[k0 + tid];

        if (kb + 1 < 32) {
            kv_load(kb + 1, sb + ASTG_BASE + (uint32_t)((kb + 1) & 1) * ASTG);
            CP_COMMIT();
            CP_WAIT(1);
        } else {
            CP_WAIT(0);
        }
        if (tid < 64) sbias[tid] = keepv ? 0.f : -1e30f;
        __syncthreads();

        // S = Q @ K^T (bf16x3)
        float s[4][4];
        #pragma unroll
        for (int nt = 0; nt < 4; nt++)
            #pragma unroll
            for (int r = 0; r < 4; r++) s[nt][r] = 0.f;

        #pragma unroll
        for (int kk = 0; kk < 4; kk++) {
            uint32_t rm = (uint32_t)(wm * 16 + (lane & 15));
            uint32_t soa = SW128(rm * 128 + kk * 32 + ((lane >> 4) << 4));
            uint32_t qh[4], ql[4];
            ldm_x4(qh, sb + AQ_H + soa);
            ldm_x4(ql, sb + AQ_L + soa);
            #pragma unroll
            for (int nt = 0; nt < 4; nt++) {
                uint32_t rn = (uint32_t)(wn * 32 + nt * 8 + (lane & 7));
                uint32_t sob = SW128(rn * 128 + kk * 32 + (((lane >> 3) & 1) << 4));
                uint32_t kh[2], kl[2];
                ldm_x2(kh, cur + 0 + sob);
                ldm_x2(kl, cur + 8192 + sob);
                mma_bf16(s[nt], qh, kh);
                mma_bf16(s[nt], qh, kl);
                mma_bf16(s[nt], ql, kh);
            }
        }

        // Scale + mask bias
        #pragma unroll
        for (int nt = 0; nt < 4; nt++) {
            int c = wn * 32 + nt * 8 + (lane & 3) * 2;
            float b0 = sbias[c], b1 = sbias[c + 1];
            s[nt][0] = s[nt][0] * 0.125f + b0;
            s[nt][1] = s[nt][1] * 0.125f + b1;
            s[nt][2] = s[nt][2] * 0.125f + b0;
            s[nt][3] = s[nt][3] * 0.125f + b1;
        }

        // Row max
        float mx0 = -INFINITY, mx1 = -INFINITY;
        #pragma unroll
        for (int nt = 0; nt < 4; nt++) {
            mx0 = fmaxf(mx0, fmaxf(s[nt][0], s[nt][1]));
            mx1 = fmaxf(mx1, fmaxf(s[nt][2], s[nt][3]));
        }
        mx0 = fmaxf(mx0, __shfl_xor_sync(0xffffffffu, mx0, 1));
        mx0 = fmaxf(mx0, __shfl_xor_sync(0xffffffffu, mx0, 2));
        mx1 = fmaxf(mx1, __shfl_xor_sync(0xffffffffu, mx1, 1));
        mx1 = fmaxf(mx1, __shfl_xor_sync(0xffffffffu, mx1, 2));
        if ((lane & 3) == 0) { redm[r0][wn] = mx0; redm[r1][wn] = mx1; }
        __syncthreads();
        float mnew0 = fmaxf(mrow[0], fmaxf(redm[r0][0], redm[r0][1]));
        float mnew1 = fmaxf(mrow[1], fmaxf(redm[r1][0], redm[r1][1]));
        float corr0 = __expf(mrow[0] - mnew0);
        float corr1 = __expf(mrow[1] - mnew1);
        mrow[0] = mnew0; mrow[1] = mnew1;

        float sm0 = 0.f, sm1 = 0.f;
        #pragma unroll
        for (int nt = 0; nt < 4; nt++) {
            s[nt][0] = __expf(s[nt][0] - mnew0);
            s[nt][1] = __expf(s[nt][1] - mnew0);
            s[nt][2] = __expf(s[nt][2] - mnew1);
            s[nt][3] = __expf(s[nt][3] - mnew1);
            sm0 += s[nt][0] + s[nt][1];
            sm1 += s[nt][2] + s[nt][3];
        }
        sm0 += __shfl_xor_sync(0xffffffffu, sm0, 1);
        sm0 += __shfl_xor_sync(0xffffffffu, sm0, 2);
        sm1 += __shfl_xor_sync(0xffffffffu, sm1, 1);
        sm1 += __shfl_xor_sync(0xffffffffu, sm1, 2);
        if ((lane & 3) == 0) { reds[r0][wn] = sm0; reds[r1][wn] = sm1; }
        __syncthreads();
        lrow[0] = lrow[0] * corr0 + reds[r0][0] + reds[r0][1];
        lrow[1] = lrow[1] * corr1 + reds[r1][0] + reds[r1][1];
        #pragma unroll
        for (int nt = 0; nt < 4; nt++) {
            o[nt][0] *= corr0; o[nt][1] *= corr0;
            o[nt][2] *= corr1; o[nt][3] *= corr1;
        }

        // P (hi/lo) to dedicated buffers
        #pragma unroll
        for (int nt = 0; nt < 4; nt++) {
            int c = wn * 32 + nt * 8 + (lane & 3) * 2;
            uint32_t so0 = SW128((uint32_t)(r0 * 128 + c * 2));
            uint32_t so1 = SW128((uint32_t)(r1 * 128 + c * 2));
            __nv_bfloat162 h2, l2;
            h2.x = __float2bfloat16(s[nt][0]);
            h2.y = __float2bfloat16(s[nt][1]);
            l2.x = __float2bfloat16(s[nt][0] - __bfloat162float(h2.x));
            l2.y = __float2bfloat16(s[nt][1] - __bfloat162float(h2.y));
            *(__nv_bfloat162*)(smem + AP_H + so0) = h2;
            *(__nv_bfloat162*)(smem + AP_L + so0) = l2;
            h2.x = __float2bfloat16(s[nt][2]);
            h2.y = __float2bfloat16(s[nt][3]);
            l2.x = __float2bfloat16(s[nt][2] - __bfloat162float(h2.x));
            l2.y = __float2bfloat16(s[nt][3] - __bfloat162float(h2.y));
            *(__nv_bfloat162*)(smem + AP_H + so1) = h2;
            *(__nv_bfloat162*)(smem + AP_L + so1) = l2;
        }
        __syncthreads();

        // O += P @ V (bf16x3)
        #pragma unroll
        for (int kk = 0; kk < 4; kk++) {
            uint32_t rm = (uint32_t)(wm * 16 + (lane & 15));
            uint32_t soa = SW128(rm * 128 + kk * 32 + ((lane >> 4) << 4));
            uint32_t ph[4], pl[4];
            ldm_x4(ph, sb + AP_H + soa);
            ldm_x4(pl, sb + AP_L + soa);
            #pragma unroll
            for (int nt = 0; nt < 4; nt++) {
                uint32_t rv = (uint32_t)(kk * 16 + (lane & 15));
                uint32_t sov = SW128(rv * 128 + (wn * 32 + nt * 8) * 2);
                uint32_t vh[2], vl[2];
                ldm_x2t(vh, cur + 16384 + sov);
                ldm_x2t(vl, cur + 24576 + sov);
                mma_bf16(o[nt], ph, vh);
                mma_bf16(o[nt], ph, vl);
                mma_bf16(o[nt], pl, vh);
            }
        }
        __syncthreads();  // all reads of cur/P done before refill at kb+2
    }

    float inv0 = 1.0f / lrow[0];
    float inv1 = 1.0f / lrow[1];
    #pragma unroll
    for (int nt = 0; nt < 4; nt++) {
        int c = h * D_ + wn * 32 + nt * 8 + (lane & 3) * 2;
        size_t g0 = (rowbase + q0 + r0) * C_ + c;
        size_t g1 = (rowbase + q0 + r1) * C_ + c;
        float v0 = o[nt][0] * inv0, v1 = o[nt][1] * inv0;
        float v2 = o[nt][2] * inv1, v3 = o[nt][3] * inv1;
        __nv_bfloat162 h2, l2;
        h2.x = __float2bfloat16(v0);
        h2.y = __float2bfloat16(v1);
        l2.x = __float2bfloat16(v0 - __bfloat162float(h2.x));
        l2.y = __float2bfloat16(v1 - __bfloat162float(h2.y));
        *(__nv_bfloat162*)&ch[g0] = h2;
        *(__nv_bfloat162*)&cl[g0] = l2;
        h2.x = __float2bfloat16(v2);
        h2.y = __float2bfloat16(v3);
        l2.x = __float2bfloat16(v2 - __bfloat162float(h2.x));
        l2.y = __float2bfloat16(v3 - __bfloat162float(h2.y));
        *(__nv_bfloat162*)&ch[g1] = h2;
        *(__nv_bfloat162*)&cl[g1] = l2;
    }
}

// ---------------------------------------------------------------------------
extern "C" void kernel_launch(void* const* d_in, const int* in_sizes, int n_in,
                              void* d_out, int out_size)
{
    const float* x    = (const float*)d_in[0];
    const int*   am   = (const int*)d_in[1];
    const float* Wqkv = (const float*)d_in[2];
    const float* bqkv = (const float*)d_in[3];
    const float* Wo   = (const float*)d_in[4];
    const float* bo   = (const float*)d_in[5];
    float* out = (float*)d_out;

    __nv_bfloat16 *xh, *xl, *qh, *ql, *ch, *cl, *wqh, *wql, *woh, *wol;
    cudaGetSymbolAddress((void**)&xh, g_xh);     cudaGetSymbolAddress((void**)&xl, g_xl);
    cudaGetSymbolAddress((void**)&qh, g_qkvh);   cudaGetSymbolAddress((void**)&ql, g_qkvl);
    cudaGetSymbolAddress((void**)&ch, g_ch);     cudaGetSymbolAddress((void**)&cl, g_cl);
    cudaGetSymbolAddress((void**)&wqh, g_wqh);   cudaGetSymbolAddress((void**)&wql, g_wql);
    cudaGetSymbolAddress((void**)&woh, g_woh);   cudaGetSymbolAddress((void**)&wol, g_wol);

    static bool attr_done = false;
    if (!attr_done) {
        cudaFuncSetAttribute(gemm_bf16x3,
                             cudaFuncAttributeMaxDynamicSharedMemorySize, GS_TOTAL);
        cudaFuncSetAttribute(attn_mma,
                             cudaFuncAttributeMaxDynamicSharedMemorySize, A_TOTAL);
        attr_done = true;
    }

    mask_norm<<<1, 1024>>>(am);
    split_rm<<<(BT_ * C_ + 255) / 256, 256>>>(x, xh, xl, BT_ * C_);
    split_tr<<<(C_ * C3_ + 255) / 256, 256>>>(Wqkv, wqh, wql, C_, C3_);

    gemm_bf16x3<<<dim3(C3_ / 128, BT_ / 128), 256, GS_TOTAL>>>(
        xh, xl, wqh, wql, bqkv, nullptr, qh, ql, BT_, C3_, C_);

    attn_mma<<<dim3(T_ / 64, H_, B_), 256, A_TOTAL>>>(qh, ql, ch, cl);

    split_tr<<<(C_ * C_ + 255) / 256, 256>>>(Wo, woh, wol, C_, C_);
    gemm_bf16x3<<<dim3(C_ / 128, BT_ / 128), 256, GS_TOTAL>>>(
        ch, cl, woh, wol, bo, out, nullptr, nullptr, BT_, C_, C_);
}

// round 7
// speedup vs baseline: 3.1716x; 1.0664x over previous
#include <cuda_runtime.h>
#include <cuda_bf16.h>
#include <cuda_fp16.h>
#include <math.h>
#include <stdint.h>

#define B_ 4
#define T_ 2048
#define C_ 768
#define H_ 12
#define D_ 64
#define BT_ (B_ * T_)
#define C3_ (3 * C_)

// ---------------------------------------------------------------------------
// Device scratch (no runtime allocation allowed)
// ---------------------------------------------------------------------------
__device__ int g_keep[BT_];

__device__ __nv_bfloat16 g_xh[(size_t)BT_ * C_],  g_xl[(size_t)BT_ * C_];
__device__ __half        g_qkvh[(size_t)BT_ * C3_], g_qkvl[(size_t)BT_ * C3_];
__device__ __nv_bfloat16 g_ch[(size_t)BT_ * C_],  g_cl[(size_t)BT_ * C_];
__device__ __nv_bfloat16 g_wqh[(size_t)C3_ * C_], g_wql[(size_t)C3_ * C_];
__device__ __nv_bfloat16 g_woh[(size_t)C_ * C_],  g_wol[(size_t)C_ * C_];

// ---------------------------------------------------------------------------
// PTX helpers
// ---------------------------------------------------------------------------
__device__ __forceinline__ uint32_t smem_u32(const void* p) {
    uint32_t a;
    asm("{ .reg .u64 t; cvta.to.shared.u64 t, %1; cvt.u32.u64 %0, t; }"
        : "=r"(a) : "l"(p));
    return a;
}
__device__ __forceinline__ void ldm_x4(uint32_t (&r)[4], uint32_t addr) {
    asm volatile("ldmatrix.sync.aligned.m8n8.x4.shared.b16 {%0,%1,%2,%3}, [%4];"
        : "=r"(r[0]), "=r"(r[1]), "=r"(r[2]), "=r"(r[3]) : "r"(addr));
}
__device__ __forceinline__ void ldm_x2(uint32_t (&r)[2], uint32_t addr) {
    asm volatile("ldmatrix.sync.aligned.m8n8.x2.shared.b16 {%0,%1}, [%2];"
        : "=r"(r[0]), "=r"(r[1]) : "r"(addr));
}
__device__ __forceinline__ void ldm_x2t(uint32_t (&r)[2], uint32_t addr) {
    asm volatile("ldmatrix.sync.aligned.m8n8.x2.trans.shared.b16 {%0,%1}, [%2];"
        : "=r"(r[0]), "=r"(r[1]) : "r"(addr));
}
__device__ __forceinline__ void mma_bf16(float (&d)[4], const uint32_t (&a)[4],
                                         const uint32_t (&b)[2]) {
    asm volatile(
        "mma.sync.aligned.m16n8k16.row.col.f32.bf16.bf16.f32 "
        "{%0,%1,%2,%3}, {%4,%5,%6,%7}, {%8,%9}, {%0,%1,%2,%3};"
        : "+f"(d[0]), "+f"(d[1]), "+f"(d[2]), "+f"(d[3])
        : "r"(a[0]), "r"(a[1]), "r"(a[2]), "r"(a[3]), "r"(b[0]), "r"(b[1]));
}
__device__ __forceinline__ void mma_f16(float (&d)[4], const uint32_t (&a)[4],
                                        const uint32_t (&b)[2]) {
    asm volatile(
        "mma.sync.aligned.m16n8k16.row.col.f32.f16.f16.f32 "
        "{%0,%1,%2,%3}, {%4,%5,%6,%7}, {%8,%9}, {%0,%1,%2,%3};"
        : "+f"(d[0]), "+f"(d[1]), "+f"(d[2]), "+f"(d[3])
        : "r"(a[0]), "r"(a[1]), "r"(a[2]), "r"(a[3]), "r"(b[0]), "r"(b[1]));
}
__device__ __forceinline__ void cp16(uint32_t saddr, const void* g) {
    asm volatile("cp.async.cg.shared.global [%0], [%1], 16;"
        :: "r"(saddr), "l"(g));
}
#define CP_COMMIT() asm volatile("cp.async.commit_group;" ::: "memory")
#define CP_WAIT(n)  asm volatile("cp.async.wait_group %0;" :: "n"(n) : "memory")
#define SW128(o) ((o) ^ (((o) >> 3) & 0x70))

// fp32 pair -> fp16 hi pair + fp16 residual pair (packed)
__device__ __forceinline__ void f2h2(float a, float b, uint32_t& h, uint32_t& l) {
    __half ha = __float2half_rn(a), hb = __float2half_rn(b);
    __half2 hh = __halves2half2(ha, hb);
    __half2 ll = __halves2half2(__float2half_rn(a - __half2float(ha)),
                                __float2half_rn(b - __half2float(hb)));
    h = *(uint32_t*)&hh;
    l = *(uint32_t*)&ll;
}

// ---------------------------------------------------------------------------
__global__ __launch_bounds__(1024) void mask_norm(const int* __restrict__ amw)
{
    const int tid = threadIdx.x;
    int allzero = 1;
    for (int i = tid; i < BT_; i += 1024)
        if (i & 1) allzero &= (amw[i] == 0);
    int is64 = __syncthreads_and(allzero);
    for (int i = tid; i < BT_; i += 1024) {
        int v = is64 ? amw[2 * i] : amw[i];
        g_keep[i] = (v == 0) ? 1 : 0;
    }
}

__global__ __launch_bounds__(256) void split_rm(
    const float* __restrict__ in, __nv_bfloat16* __restrict__ hi,
    __nv_bfloat16* __restrict__ lo, int n)
{
    int i = blockIdx.x * 256 + threadIdx.x;
    if (i >= n) return;
    float x = in[i];
    __nv_bfloat16 h = __float2bfloat16(x);
    hi[i] = h;
    lo[i] = __float2bfloat16(x - __bfloat162float(h));
}

__global__ __launch_bounds__(256) void split_tr(
    const float* __restrict__ in, __nv_bfloat16* __restrict__ hi,
    __nv_bfloat16* __restrict__ lo, int K, int N)
{
    int i = blockIdx.x * 256 + threadIdx.x;
    if (i >= K * N) return;
    int k = i / N, n = i - k * N;
    float x = in[i];
    __nv_bfloat16 h = __float2bfloat16(x);
    hi[(size_t)n * K + k] = h;
    lo[(size_t)n * K + k] = __float2bfloat16(x - __bfloat162float(h));
}

// ---------------------------------------------------------------------------
// bf16x3 HMMA GEMM, cp.async double-buffered. CTA 128x128, 8 warps.
// MODE 0: fp32 Out.  MODE 1: fp16 hi/lo pair (Hh/Hl).
// ---------------------------------------------------------------------------
#define GS_AH 0
#define GS_AL 16384
#define GS_BH 32768
#define GS_BL 49152
#define GSTG  65536
#define GS_TOTAL (2 * GSTG)

template <int MODE>
__global__ __launch_bounds__(256) void gemm_bf16x3(
    const __nv_bfloat16* __restrict__ Ah, const __nv_bfloat16* __restrict__ Al,
    const __nv_bfloat16* __restrict__ Bh, const __nv_bfloat16* __restrict__ Bl,
    const float* __restrict__ bias, float* __restrict__ Out,
    __half* __restrict__ Hh, __half* __restrict__ Hl,
    int M, int N, int K)
{
    extern __shared__ __align__(1024) char smem[];
    const uint32_t sb = smem_u32(smem);
    const int tid  = threadIdx.x;
    const int wid  = tid >> 5;
    const int lane = tid & 31;
    const int m0 = blockIdx.y * 128;
    const int n0 = blockIdx.x * 128;
    const int wm = wid >> 2;
    const int wn = wid & 3;

    int lr[4], luk[4];
    uint32_t lso[4];
    #pragma unroll
    for (int i = 0; i < 4; i++) {
        int u = tid + 256 * i;
        lr[i] = u >> 3; luk[i] = u & 7;
        lso[i] = SW128((uint32_t)(lr[i] * 128 + luk[i] * 16));
    }

    const int nstages = K / 64;
    auto stage_load = [&](int s, uint32_t dst) {
        const int k0 = s * 64;
        #pragma unroll
        for (int i = 0; i < 4; i++) {
            size_t ga = (size_t)(m0 + lr[i]) * K + k0 + luk[i] * 8;
            size_t gb = (size_t)(n0 + lr[i]) * K + k0 + luk[i] * 8;
            cp16(dst + GS_AH + lso[i], Ah + ga);
            cp16(dst + GS_AL + lso[i], Al + ga);
            cp16(dst + GS_BH + lso[i], Bh + gb);
            cp16(dst + GS_BL + lso[i], Bl + gb);
        }
    };

    float acc[4][4][4];
    #pragma unroll
    for (int i = 0; i < 4; i++)
        #pragma unroll
        for (int j = 0; j < 4; j++)
            #pragma unroll
            for (int r = 0; r < 4; r++) acc[i][j][r] = 0.f;

    stage_load(0, sb);
    CP_COMMIT();

    for (int s = 0; s < nstages; s++) {
        const uint32_t cur = sb + (uint32_t)(s & 1) * GSTG;
        if (s + 1 < nstages) {
            stage_load(s + 1, sb + (uint32_t)((s + 1) & 1) * GSTG);
            CP_COMMIT();
            CP_WAIT(1);
        } else {
            CP_WAIT(0);
        }
        __syncthreads();

        #pragma unroll
        for (int kk = 0; kk < 4; kk++) {
            uint32_t bh[4][2], bl[4][2];
            #pragma unroll
            for (int nt = 0; nt < 4; nt++) {
                uint32_t rn = (uint32_t)(wn * 32 + nt * 8 + (lane & 7));
                uint32_t so = SW128(rn * 128 + kk * 32 + (((lane >> 3) & 1) << 4));
                ldm_x2(bh[nt], cur + GS_BH + so);
                ldm_x2(bl[nt], cur + GS_BL + so);
            }
            #pragma unroll
            for (int mt = 0; mt < 4; mt++) {
                uint32_t rm = (uint32_t)(wm * 64 + mt * 16 + (lane & 15));
                uint32_t so = SW128(rm * 128 + kk * 32 + ((lane >> 4) << 4));
                uint32_t ah[4], al[4];
                ldm_x4(ah, cur + GS_AH + so);
                ldm_x4(al, cur + GS_AL + so);
                #pragma unroll
                for (int nt = 0; nt < 4; nt++) {
                    mma_bf16(acc[mt][nt], ah, bh[nt]);
                    mma_bf16(acc[mt][nt], ah, bl[nt]);
                    mma_bf16(acc[mt][nt], al, bh[nt]);
                }
            }
        }
        __syncthreads();
    }

    #pragma unroll
    for (int mt = 0; mt < 4; mt++) {
        #pragma unroll
        for (int nt = 0; nt < 4; nt++) {
            int grow = m0 + wm * 64 + mt * 16 + (lane >> 2);
            int gcol = n0 + wn * 32 + nt * 8 + (lane & 3) * 2;
            float2 bb = *(const float2*)&bias[gcol];
            float v0 = acc[mt][nt][0] + bb.x, v1 = acc[mt][nt][1] + bb.y;
            float v2 = acc[mt][nt][2] + bb.x, v3 = acc[mt][nt][3] + bb.y;
            if (MODE == 1) {
                uint32_t h, l;
                f2h2(v0, v1, h, l);
                *(uint32_t*)&Hh[(size_t)grow * N + gcol] = h;
                *(uint32_t*)&Hl[(size_t)grow * N + gcol] = l;
                f2h2(v2, v3, h, l);
                *(uint32_t*)&Hh[(size_t)(grow + 8) * N + gcol] = h;
                *(uint32_t*)&Hl[(size_t)(grow + 8) * N + gcol] = l;
            } else {
                *(float2*)&Out[(size_t)grow * N + gcol] = make_float2(v0, v1);
                *(float2*)&Out[(size_t)(grow + 8) * N + gcol] = make_float2(v2, v3);
            }
        }
    }
}

// ---------------------------------------------------------------------------
// Flash attention (FA2 layout): q-tile 128, 8 warps each own 16 rows x 64 cols.
// fp16 2-term: S = (Qh+Ql)Kh^T;  O = (Ph+Pl)Vh.  P stays in registers.
// One __syncthreads per k-tile. cp.async double-buffered KV (hi only).
// ---------------------------------------------------------------------------
#define AQ_H   0
#define AQ_L   16384
#define ASTG_BASE 32768
#define ASTG   16384          // per-stage: K_H(0), V_H(8192)
#define A_BIAS 65536          // float[2][64]
#define A_TOTAL 66048

__global__ __launch_bounds__(256) void attn_mma(
    const __half* __restrict__ qkvh, const __half* __restrict__ qkvl,
    __nv_bfloat16* __restrict__ ch, __nv_bfloat16* __restrict__ cl)
{
    extern __shared__ __align__(1024) char smem[];
    const uint32_t sb = smem_u32(smem);
    float (*sbias)[64] = (float(*)[64])(smem + A_BIAS);

    const int tid  = threadIdx.x;
    const int wid  = tid >> 5;
    const int lane = tid & 31;
    const int q0 = blockIdx.x * 128;
    const int h  = blockIdx.y;
    const int b  = blockIdx.z;

    const size_t rowbase = (size_t)b * T_;
    const int* keepb = g_keep + b * T_;

    // Q tile: 128 rows x 64 fp16 (hi/lo), 1024 16B units each -> 4 per thread
    #pragma unroll
    for (int i = 0; i < 4; i++) {
        int u = tid + 256 * i;
        int r = u >> 3, uk = u & 7;
        uint32_t so = SW128((uint32_t)(r * 128 + uk * 16));
        size_t g = (rowbase + q0 + r) * C3_ + h * D_ + uk * 8;
        cp16(sb + AQ_H + so, qkvh + g);
        cp16(sb + AQ_L + so, qkvl + g);
    }

    // KV staging coords: 64 rows x 8 units per tile -> 2 per thread
    int lr[2], luk[2];
    uint32_t lso[2];
    #pragma unroll
    for (int i = 0; i < 2; i++) {
        int u = tid + 256 * i;
        lr[i] = u >> 3; luk[i] = u & 7;
        lso[i] = SW128((uint32_t)(lr[i] * 128 + luk[i] * 16));
    }
    auto kv_load = [&](int kb, uint32_t dst) {
        const int k0 = kb * 64;
        #pragma unroll
        for (int i = 0; i < 2; i++) {
            size_t gk = (rowbase + k0 + lr[i]) * C3_ + C_ + h * D_ + luk[i] * 8;
            size_t gv = (rowbase + k0 + lr[i]) * C3_ + 2 * C_ + h * D_ + luk[i] * 8;
            cp16(dst + 0    + lso[i], qkvh + gk);
            cp16(dst + 8192 + lso[i], qkvh + gv);
        }
    };
    kv_load(0, sb + ASTG_BASE);
    CP_COMMIT();

    const int r0 = wid * 16 + (lane >> 2);   // q row (band-local row + band)
    const int r1 = r0 + 8;

    float mrow[2] = {-INFINITY, -INFINITY};
    float lrow[2] = {0.f, 0.f};
    float o[8][4];
    #pragma unroll
    for (int nt = 0; nt < 8; nt++)
        #pragma unroll
        for (int r = 0; r < 4; r++) o[nt][r] = 0.f;

    for (int kb = 0; kb < 32; kb++) {
        const int k0 = kb * 64;
        const uint32_t cur = sb + ASTG_BASE + (uint32_t)(kb & 1) * ASTG;

        int keepv = (tid < 64) ? keepb[k0 + tid] : 0;
        CP_WAIT(0);
        if (tid < 64) sbias[kb & 1][tid] = keepv ? 0.f : -1e30f;
        __syncthreads();
        if (kb + 1 < 32) {
            kv_load(kb + 1, sb + ASTG_BASE + (uint32_t)((kb + 1) & 1) * ASTG);
            CP_COMMIT();
        }

        // S = (Qh+Ql) @ Kh^T : warp covers 16 rows x 64 cols (8 n-tiles)
        float s[8][4];
        #pragma unroll
        for (int nt = 0; nt < 8; nt++)
            #pragma unroll
            for (int r = 0; r < 4; r++) s[nt][r] = 0.f;

        #pragma unroll
        for (int kk = 0; kk < 4; kk++) {
            uint32_t rm = (uint32_t)(wid * 16 + (lane & 15));
            uint32_t soa = SW128(rm * 128 + kk * 32 + ((lane >> 4) << 4));
            uint32_t qh[4], ql[4];
            ldm_x4(qh, sb + AQ_H + soa);
            ldm_x4(ql, sb + AQ_L + soa);
            #pragma unroll
            for (int nt = 0; nt < 8; nt++) {
                uint32_t rn = (uint32_t)(nt * 8 + (lane & 7));
                uint32_t sob = SW128(rn * 128 + kk * 32 + (((lane >> 3) & 1) << 4));
                uint32_t kh[2];
                ldm_x2(kh, cur + sob);
                mma_f16(s[nt], qh, kh);
                mma_f16(s[nt], ql, kh);
            }
        }

        // Scale + mask bias
        const float* bia = sbias[kb & 1];
        #pragma unroll
        for (int nt = 0; nt < 8; nt++) {
            int c = nt * 8 + (lane & 3) * 2;
            float b0 = bia[c], b1 = bia[c + 1];
            s[nt][0] = s[nt][0] * 0.125f + b0;
            s[nt][1] = s[nt][1] * 0.125f + b1;
            s[nt][2] = s[nt][2] * 0.125f + b0;
            s[nt][3] = s[nt][3] * 0.125f + b1;
        }

        // Row softmax, fully intra-warp (rows owned by quads)
        float mx0 = -INFINITY, mx1 = -INFINITY;
        #pragma unroll
        for (int nt = 0; nt < 8; nt++) {
            mx0 = fmaxf(mx0, fmaxf(s[nt][0], s[nt][1]));
            mx1 = fmaxf(mx1, fmaxf(s[nt][2], s[nt][3]));
        }
        mx0 = fmaxf(mx0, __shfl_xor_sync(0xffffffffu, mx0, 1));
        mx0 = fmaxf(mx0, __shfl_xor_sync(0xffffffffu, mx0, 2));
        mx1 = fmaxf(mx1, __shfl_xor_sync(0xffffffffu, mx1, 1));
        mx1 = fmaxf(mx1, __shfl_xor_sync(0xffffffffu, mx1, 2));
        float mnew0 = fmaxf(mrow[0], mx0);
        float mnew1 = fmaxf(mrow[1], mx1);
        float corr0 = __expf(mrow[0] - mnew0);
        float corr1 = __expf(mrow[1] - mnew1);
        mrow[0] = mnew0; mrow[1] = mnew1;

        float sm0 = 0.f, sm1 = 0.f;
        #pragma unroll
        for (int nt = 0; nt < 8; nt++) {
            s[nt][0] = __expf(s[nt][0] - mnew0);
            s[nt][1] = __expf(s[nt][1] - mnew0);
            s[nt][2] = __expf(s[nt][2] - mnew1);
            s[nt][3] = __expf(s[nt][3] - mnew1);
            sm0 += s[nt][0] + s[nt][1];
            sm1 += s[nt][2] + s[nt][3];
        }
        sm0 += __shfl_xor_sync(0xffffffffu, sm0, 1);
        sm0 += __shfl_xor_sync(0xffffffffu, sm0, 2);
        sm1 += __shfl_xor_sync(0xffffffffu, sm1, 1);
        sm1 += __shfl_xor_sync(0xffffffffu, sm1, 2);
        lrow[0] = lrow[0] * corr0 + sm0;
        lrow[1] = lrow[1] * corr1 + sm1;
        #pragma unroll
        for (int nt = 0; nt < 8; nt++) {
            o[nt][0] *= corr0; o[nt][1] *= corr0;
            o[nt][2] *= corr1; o[nt][3] *= corr1;
        }

        // O += (Ph+Pl) @ Vh — P taken directly from S fragments (registers)
        #pragma unroll
        for (int kc = 0; kc < 4; kc++) {
            uint32_t ph[4], pl[4];
            f2h2(s[2 * kc][0],     s[2 * kc][1],     ph[0], pl[0]);
            f2h2(s[2 * kc][2],     s[2 * kc][3],     ph[1], pl[1]);
            f2h2(s[2 * kc + 1][0], s[2 * kc + 1][1], ph[2], pl[2]);
            f2h2(s[2 * kc + 1][2], s[2 * kc + 1][3], ph[3], pl[3]);
            #pragma unroll
            for (int nt = 0; nt < 8; nt++) {
                uint32_t rv = (uint32_t)(kc * 16 + (lane & 15));
                uint32_t sov = SW128(rv * 128 + nt * 16);
                uint32_t vh[2];
                ldm_x2t(vh, cur + 8192 + sov);
                mma_f16(o[nt], ph, vh);
                mma_f16(o[nt], pl, vh);
            }
        }
    }

    // Epilogue: normalize, write ctx as bf16 hi/lo
    float inv0 = 1.0f / lrow[0];
    float inv1 = 1.0f / lrow[1];
    #pragma unroll
    for (int nt = 0; nt < 8; nt++) {
        int c = h * D_ + nt * 8 + (lane & 3) * 2;
        size_t g0 = (rowbase + q0 + r0) * C_ + c;
        size_t g1 = (rowbase + q0 + r1) * C_ + c;
        float v0 = o[nt][0] * inv0, v1 = o[nt][1] * inv0;
        float v2 = o[nt][2] * inv1, v3 = o[nt][3] * inv1;
        __nv_bfloat162 h2, l2;
        h2.x = __float2bfloat16(v0);
        h2.y = __float2bfloat16(v1);
        l2.x = __float2bfloat16(v0 - __bfloat162float(h2.x));
        l2.y = __float2bfloat16(v1 - __bfloat162float(h2.y));
        *(__nv_bfloat162*)&ch[g0] = h2;
        *(__nv_bfloat162*)&cl[g0] = l2;
        h2.x = __float2bfloat16(v2);
        h2.y = __float2bfloat16(v3);
        l2.x = __float2bfloat16(v2 - __bfloat162float(h2.x));
        l2.y = __float2bfloat16(v3 - __bfloat162float(h2.y));
        *(__nv_bfloat162*)&ch[g1] = h2;
        *(__nv_bfloat162*)&cl[g1] = l2;
    }
}

// ---------------------------------------------------------------------------
extern "C" void kernel_launch(void* const* d_in, const int* in_sizes, int n_in,
                              void* d_out, int out_size)
{
    const float* x    = (const float*)d_in[0];
    const int*   am   = (const int*)d_in[1];
    const float* Wqkv = (const float*)d_in[2];
    const float* bqkv = (const float*)d_in[3];
    const float* Wo   = (const float*)d_in[4];
    const float* bo   = (const float*)d_in[5];
    float* out = (float*)d_out;

    __nv_bfloat16 *xh, *xl, *ch, *cl, *wqh, *wql, *woh, *wol;
    __half *qh, *ql;
    cudaGetSymbolAddress((void**)&xh, g_xh);     cudaGetSymbolAddress((void**)&xl, g_xl);
    cudaGetSymbolAddress((void**)&qh, g_qkvh);   cudaGetSymbolAddress((void**)&ql, g_qkvl);
    cudaGetSymbolAddress((void**)&ch, g_ch);     cudaGetSymbolAddress((void**)&cl, g_cl);
    cudaGetSymbolAddress((void**)&wqh, g_wqh);   cudaGetSymbolAddress((void**)&wql, g_wql);
    cudaGetSymbolAddress((void**)&woh, g_woh);   cudaGetSymbolAddress((void**)&wol, g_wol);

    static bool attr_done = false;
    if (!attr_done) {
        cudaFuncSetAttribute(gemm_bf16x3<0>,
                             cudaFuncAttributeMaxDynamicSharedMemorySize, GS_TOTAL);
        cudaFuncSetAttribute(gemm_bf16x3<1>,
                             cudaFuncAttributeMaxDynamicSharedMemorySize, GS_TOTAL);
        cudaFuncSetAttribute(attn_mma,
                             cudaFuncAttributeMaxDynamicSharedMemorySize, A_TOTAL);
        attr_done = true;
    }

    mask_norm<<<1, 1024>>>(am);
    split_rm<<<(BT_ * C_ + 255) / 256, 256>>>(x, xh, xl, BT_ * C_);
    split_tr<<<(C_ * C3_ + 255) / 256, 256>>>(Wqkv, wqh, wql, C_, C3_);

    // 1) QKV projection -> fp16 hi/lo
    gemm_bf16x3<1><<<dim3(C3_ / 128, BT_ / 128), 256, GS_TOTAL>>>(
        xh, xl, wqh, wql, bqkv, nullptr, qh, ql, BT_, C3_, C_);

    // 2) Attention (FA2 layout, fp16 2-term) -> ctx bf16 hi/lo
    attn_mma<<<dim3(T_ / 128, H_, B_), 256, A_TOTAL>>>(qh, ql, ch, cl);

    // 3) Output projection -> fp32
    split_tr<<<(C_ * C_ + 255) / 256, 256>>>(Wo, woh, wol, C_, C_);
    gemm_bf16x3<0><<<dim3(C_ / 128, BT_ / 128), 256, GS_TOTAL>>>(
        ch, cl, woh, wol, bo, out, nullptr, nullptr, BT_, C_, C_);
}

// round 8
// speedup vs baseline: 3.3737x; 1.0637x over previous
#include <cuda_runtime.h>
#include <cuda_bf16.h>
#include <cuda_fp16.h>
#include <math.h>
#include <stdint.h>

#define B_ 4
#define T_ 2048
#define C_ 768
#define H_ 12
#define D_ 64
#define BT_ (B_ * T_)
#define C3_ (3 * C_)

// ---------------------------------------------------------------------------
// Device scratch (no runtime allocation allowed)
// ---------------------------------------------------------------------------
__device__ int g_keep[BT_];

__device__ __nv_bfloat16 g_xh[(size_t)BT_ * C_],  g_xl[(size_t)BT_ * C_];
__device__ __half        g_qkvh[(size_t)BT_ * C3_], g_qkvl[(size_t)BT_ * C3_];
__device__ __nv_bfloat16 g_ch[(size_t)BT_ * C_],  g_cl[(size_t)BT_ * C_];
__device__ __nv_bfloat16 g_wqh[(size_t)C3_ * C_], g_wql[(size_t)C3_ * C_];
__device__ __nv_bfloat16 g_woh[(size_t)C_ * C_],  g_wol[(size_t)C_ * C_];

// ---------------------------------------------------------------------------
// PTX helpers
// ---------------------------------------------------------------------------
__device__ __forceinline__ uint32_t smem_u32(const void* p) {
    uint32_t a;
    asm("{ .reg .u64 t; cvta.to.shared.u64 t, %1; cvt.u32.u64 %0, t; }"
        : "=r"(a) : "l"(p));
    return a;
}
__device__ __forceinline__ void ldm_x4(uint32_t (&r)[4], uint32_t addr) {
    asm volatile("ldmatrix.sync.aligned.m8n8.x4.shared.b16 {%0,%1,%2,%3}, [%4];"
        : "=r"(r[0]), "=r"(r[1]), "=r"(r[2]), "=r"(r[3]) : "r"(addr));
}
__device__ __forceinline__ void ldm_x2(uint32_t (&r)[2], uint32_t addr) {
    asm volatile("ldmatrix.sync.aligned.m8n8.x2.shared.b16 {%0,%1}, [%2];"
        : "=r"(r[0]), "=r"(r[1]) : "r"(addr));
}
__device__ __forceinline__ void ldm_x2t(uint32_t (&r)[2], uint32_t addr) {
    asm volatile("ldmatrix.sync.aligned.m8n8.x2.trans.shared.b16 {%0,%1}, [%2];"
        : "=r"(r[0]), "=r"(r[1]) : "r"(addr));
}
__device__ __forceinline__ void mma_bf16(float (&d)[4], const uint32_t (&a)[4],
                                         const uint32_t (&b)[2]) {
    asm volatile(
        "mma.sync.aligned.m16n8k16.row.col.f32.bf16.bf16.f32 "
        "{%0,%1,%2,%3}, {%4,%5,%6,%7}, {%8,%9}, {%0,%1,%2,%3};"
        : "+f"(d[0]), "+f"(d[1]), "+f"(d[2]), "+f"(d[3])
        : "r"(a[0]), "r"(a[1]), "r"(a[2]), "r"(a[3]), "r"(b[0]), "r"(b[1]));
}
__device__ __forceinline__ void mma_f16(float (&d)[4], const uint32_t (&a)[4],
                                        const uint32_t (&b)[2]) {
    asm volatile(
        "mma.sync.aligned.m16n8k16.row.col.f32.f16.f16.f32 "
        "{%0,%1,%2,%3}, {%4,%5,%6,%7}, {%8,%9}, {%0,%1,%2,%3};"
        : "+f"(d[0]), "+f"(d[1]), "+f"(d[2]), "+f"(d[3])
        : "r"(a[0]), "r"(a[1]), "r"(a[2]), "r"(a[3]), "r"(b[0]), "r"(b[1]));
}
__device__ __forceinline__ void cp16(uint32_t saddr, const void* g) {
    asm volatile("cp.async.cg.shared.global [%0], [%1], 16;"
        :: "r"(saddr), "l"(g));
}
#define CP_COMMIT() asm volatile("cp.async.commit_group;" ::: "memory")
#define CP_WAIT(n)  asm volatile("cp.async.wait_group %0;" :: "n"(n) : "memory")
#define SW128(o) ((o) ^ (((o) >> 3) & 0x70))

__device__ __forceinline__ void f2h2(float a, float b, uint32_t& h, uint32_t& l) {
    __half ha = __float2half_rn(a), hb = __float2half_rn(b);
    __half2 hh = __halves2half2(ha, hb);
    __half2 ll = __halves2half2(__float2half_rn(a - __half2float(ha)),
                                __float2half_rn(b - __half2float(hb)));
    h = *(uint32_t*)&hh;
    l = *(uint32_t*)&ll;
}

// ---------------------------------------------------------------------------
__global__ __launch_bounds__(1024) void mask_norm(const int* __restrict__ amw)
{
    const int tid = threadIdx.x;
    int allzero = 1;
    for (int i = tid; i < BT_; i += 1024)
        if (i & 1) allzero &= (amw[i] == 0);
    int is64 = __syncthreads_and(allzero);
    for (int i = tid; i < BT_; i += 1024) {
        int v = is64 ? amw[2 * i] : amw[i];
        g_keep[i] = (v == 0) ? 1 : 0;
    }
}

__global__ __launch_bounds__(256) void split_rm(
    const float* __restrict__ in, __nv_bfloat16* __restrict__ hi,
    __nv_bfloat16* __restrict__ lo, int n)
{
    int i = blockIdx.x * 256 + threadIdx.x;
    if (i >= n) return;
    float x = in[i];
    __nv_bfloat16 h = __float2bfloat16(x);
    hi[i] = h;
    lo[i] = __float2bfloat16(x - __bfloat162float(h));
}

__global__ __launch_bounds__(256) void split_tr(
    const float* __restrict__ in, __nv_bfloat16* __restrict__ hi,
    __nv_bfloat16* __restrict__ lo, int K, int N)
{
    int i = blockIdx.x * 256 + threadIdx.x;
    if (i >= K * N) return;
    int k = i / N, n = i - k * N;
    float x = in[i];
    __nv_bfloat16 h = __float2bfloat16(x);
    hi[(size_t)n * K + k] = h;
    lo[(size_t)n * K + k] = __float2bfloat16(x - __bfloat162float(h));
}

// ---------------------------------------------------------------------------
// bf16x3 HMMA GEMM, 3-stage cp.async pipeline. CTA 128x128, 8 warps.
// MODE 0: fp32 Out.  MODE 1: fp16 hi/lo pair (Hh/Hl).
// ---------------------------------------------------------------------------
#define GS_AH 0
#define GS_AL 16384
#define GS_BH 32768
#define GS_BL 49152
#define GSTG  65536
#define GS_TOTAL (3 * GSTG)

template <int MODE>
__global__ __launch_bounds__(256) void gemm_bf16x3(
    const __nv_bfloat16* __restrict__ Ah, const __nv_bfloat16* __restrict__ Al,
    const __nv_bfloat16* __restrict__ Bh, const __nv_bfloat16* __restrict__ Bl,
    const float* __restrict__ bias, float* __restrict__ Out,
    __half* __restrict__ Hh, __half* __restrict__ Hl,
    int M, int N, int K)
{
    extern __shared__ __align__(1024) char smem[];
    const uint32_t sb = smem_u32(smem);
    const int tid  = threadIdx.x;
    const int wid  = tid >> 5;
    const int lane = tid & 31;
    const int m0 = blockIdx.y * 128;
    const int n0 = blockIdx.x * 128;
    const int wm = wid >> 2;
    const int wn = wid & 3;

    int lr[4], luk[4];
    uint32_t lso[4];
    #pragma unroll
    for (int i = 0; i < 4; i++) {
        int u = tid + 256 * i;
        lr[i] = u >> 3; luk[i] = u & 7;
        lso[i] = SW128((uint32_t)(lr[i] * 128 + luk[i] * 16));
    }

    const int nstages = K / 64;
    auto stage_load = [&](int s, uint32_t dst) {
        const int k0 = s * 64;
        #pragma unroll
        for (int i = 0; i < 4; i++) {
            size_t ga = (size_t)(m0 + lr[i]) * K + k0 + luk[i] * 8;
            size_t gb = (size_t)(n0 + lr[i]) * K + k0 + luk[i] * 8;
            cp16(dst + GS_AH + lso[i], Ah + ga);
            cp16(dst + GS_AL + lso[i], Al + ga);
            cp16(dst + GS_BH + lso[i], Bh + gb);
            cp16(dst + GS_BL + lso[i], Bl + gb);
        }
    };

    float acc[4][4][4];
    #pragma unroll
    for (int i = 0; i < 4; i++)
        #pragma unroll
        for (int j = 0; j < 4; j++)
            #pragma unroll
            for (int r = 0; r < 4; r++) acc[i][j][r] = 0.f;

    // Prologue: 2 stages in flight
    stage_load(0, sb);
    CP_COMMIT();
    stage_load(1, sb + GSTG);
    CP_COMMIT();

    int buf = 0;
    for (int s = 0; s < nstages; s++) {
        const uint32_t cur = sb + (uint32_t)buf * GSTG;
        if (s + 2 < nstages) {
            int nb = buf + 2; if (nb >= 3) nb -= 3;
            stage_load(s + 2, sb + (uint32_t)nb * GSTG);
            CP_COMMIT();
            CP_WAIT(2);
        } else if (s + 1 < nstages) {
            CP_WAIT(1);
        } else {
            CP_WAIT(0);
        }
        __syncthreads();

        #pragma unroll
        for (int kk = 0; kk < 4; kk++) {
            uint32_t bh[4][2], bl[4][2];
            #pragma unroll
            for (int nt = 0; nt < 4; nt++) {
                uint32_t rn = (uint32_t)(wn * 32 + nt * 8 + (lane & 7));
                uint32_t so = SW128(rn * 128 + kk * 32 + (((lane >> 3) & 1) << 4));
                ldm_x2(bh[nt], cur + GS_BH + so);
                ldm_x2(bl[nt], cur + GS_BL + so);
            }
            #pragma unroll
            for (int mt = 0; mt < 4; mt++) {
                uint32_t rm = (uint32_t)(wm * 64 + mt * 16 + (lane & 15));
                uint32_t so = SW128(rm * 128 + kk * 32 + ((lane >> 4) << 4));
                uint32_t ah[4], al[4];
                ldm_x4(ah, cur + GS_AH + so);
                ldm_x4(al, cur + GS_AL + so);
                #pragma unroll
                for (int nt = 0; nt < 4; nt++) {
                    mma_bf16(acc[mt][nt], ah, bh[nt]);
                    mma_bf16(acc[mt][nt], ah, bl[nt]);
                    mma_bf16(acc[mt][nt], al, bh[nt]);
                }
            }
        }
        __syncthreads();
        if (++buf == 3) buf = 0;
    }

    #pragma unroll
    for (int mt = 0; mt < 4; mt++) {
        #pragma unroll
        for (int nt = 0; nt < 4; nt++) {
            int grow = m0 + wm * 64 + mt * 16 + (lane >> 2);
            int gcol = n0 + wn * 32 + nt * 8 + (lane & 3) * 2;
            float2 bb = *(const float2*)&bias[gcol];
            float v0 = acc[mt][nt][0] + bb.x, v1 = acc[mt][nt][1] + bb.y;
            float v2 = acc[mt][nt][2] + bb.x, v3 = acc[mt][nt][3] + bb.y;
            if (MODE == 1) {
                uint32_t h, l;
                f2h2(v0, v1, h, l);
                *(uint32_t*)&Hh[(size_t)grow * N + gcol] = h;
                *(uint32_t*)&Hl[(size_t)grow * N + gcol] = l;
                f2h2(v2, v3, h, l);
                *(uint32_t*)&Hh[(size_t)(grow + 8) * N + gcol] = h;
                *(uint32_t*)&Hl[(size_t)(grow + 8) * N + gcol] = l;
            } else {
                *(float2*)&Out[(size_t)grow * N + gcol] = make_float2(v0, v1);
                *(float2*)&Out[(size_t)(grow + 8) * N + gcol] = make_float2(v2, v3);
            }
        }
    }
}

// ---------------------------------------------------------------------------
// Flash attention: q-tile 256, 512 threads / 16 warps, each warp owns 16 rows.
// fp16 2-term: S = (Qh+Ql)Kh^T;  O = (Ph+Pl)Vh. P stays in registers.
// cp.async double-buffered KV; one __syncthreads per k-tile.
// ---------------------------------------------------------------------------
#define AQ_H   0
#define AQ_L   32768
#define ASTG_BASE 65536
#define ASTG   16384          // per-stage: K_H(0), V_H(8192)
#define A_BIAS 98304          // float[2][64]
#define A_TOTAL 98816

__global__ __launch_bounds__(512) void attn_mma(
    const __half* __restrict__ qkvh, const __half* __restrict__ qkvl,
    __nv_bfloat16* __restrict__ ch, __nv_bfloat16* __restrict__ cl)
{
    extern __shared__ __align__(1024) char smem[];
    const uint32_t sb = smem_u32(smem);
    float (*sbias)[64] = (float(*)[64])(smem + A_BIAS);

    const int tid  = threadIdx.x;
    const int wid  = tid >> 5;
    const int lane = tid & 31;
    const int q0 = blockIdx.x * 256;
    const int h  = blockIdx.y;
    const int b  = blockIdx.z;

    const size_t rowbase = (size_t)b * T_;
    const int* keepb = g_keep + b * T_;

    // Q tile: 256 rows x 64 fp16 (hi/lo) = 2048 16B units each; 4 per thread
    #pragma unroll
    for (int i = 0; i < 4; i++) {
        int u = tid + 512 * i;
        int r = u >> 3, uk = u & 7;
        uint32_t so = SW128((uint32_t)(r * 128 + uk * 16));
        size_t g = (rowbase + q0 + r) * C3_ + h * D_ + uk * 8;
        cp16(sb + AQ_H + so, qkvh + g);
        cp16(sb + AQ_L + so, qkvl + g);
    }

    // KV staging: 64 rows x 8 units per tile = 512 units; 1 per thread
    const int klr = tid >> 3, kuk = tid & 7;
    const uint32_t klso = SW128((uint32_t)(klr * 128 + kuk * 16));
    auto kv_load = [&](int kb, uint32_t dst) {
        const int k0 = kb * 64;
        size_t gk = (rowbase + k0 + klr) * C3_ + C_ + h * D_ + kuk * 8;
        size_t gv = (rowbase + k0 + klr) * C3_ + 2 * C_ + h * D_ + kuk * 8;
        cp16(dst + 0    + klso, qkvh + gk);
        cp16(dst + 8192 + klso, qkvh + gv);
    };
    kv_load(0, sb + ASTG_BASE);
    CP_COMMIT();

    const int r0 = wid * 16 + (lane >> 2);
    const int r1 = r0 + 8;

    float mrow[2] = {-INFINITY, -INFINITY};
    float lrow[2] = {0.f, 0.f};
    float o[8][4];
    #pragma unroll
    for (int nt = 0; nt < 8; nt++)
        #pragma unroll
        for (int r = 0; r < 4; r++) o[nt][r] = 0.f;

    for (int kb = 0; kb < 32; kb++) {
        const int k0 = kb * 64;
        const uint32_t cur = sb + ASTG_BASE + (uint32_t)(kb & 1) * ASTG;

        int keepv = (tid < 64) ? keepb[k0 + tid] : 0;
        CP_WAIT(0);
        if (tid < 64) sbias[kb & 1][tid] = keepv ? 0.f : -1e30f;
        __syncthreads();
        if (kb + 1 < 32) {
            kv_load(kb + 1, sb + ASTG_BASE + (uint32_t)((kb + 1) & 1) * ASTG);
            CP_COMMIT();
        }

        // S = (Qh+Ql) @ Kh^T
        float s[8][4];
        #pragma unroll
        for (int nt = 0; nt < 8; nt++)
            #pragma unroll
            for (int r = 0; r < 4; r++) s[nt][r] = 0.f;

        #pragma unroll
        for (int kk = 0; kk < 4; kk++) {
            uint32_t rm = (uint32_t)(wid * 16 + (lane & 15));
            uint32_t soa = SW128(rm * 128 + kk * 32 + ((lane >> 4) << 4));
            uint32_t qh[4], ql[4];
            ldm_x4(qh, sb + AQ_H + soa);
            ldm_x4(ql, sb + AQ_L + soa);
            #pragma unroll
            for (int nt = 0; nt < 8; nt++) {
                uint32_t rn = (uint32_t)(nt * 8 + (lane & 7));
                uint32_t sob = SW128(rn * 128 + kk * 32 + (((lane >> 3) & 1) << 4));
                uint32_t kh[2];
                ldm_x2(kh, cur + sob);
                mma_f16(s[nt], qh, kh);
                mma_f16(s[nt], ql, kh);
            }
        }

        const float* bia = sbias[kb & 1];
        #pragma unroll
        for (int nt = 0; nt < 8; nt++) {
            int c = nt * 8 + (lane & 3) * 2;
            float b0 = bia[c], b1 = bia[c + 1];
            s[nt][0] = s[nt][0] * 0.125f + b0;
            s[nt][1] = s[nt][1] * 0.125f + b1;
            s[nt][2] = s[nt][2] * 0.125f + b0;
            s[nt][3] = s[nt][3] * 0.125f + b1;
        }

        float mx0 = -INFINITY, mx1 = -INFINITY;
        #pragma unroll
        for (int nt = 0; nt < 8; nt++) {
            mx0 = fmaxf(mx0, fmaxf(s[nt][0], s[nt][1]));
            mx1 = fmaxf(mx1, fmaxf(s[nt][2], s[nt][3]));
        }
        mx0 = fmaxf(mx0, __shfl_xor_sync(0xffffffffu, mx0, 1));
        mx0 = fmaxf(mx0, __shfl_xor_sync(0xffffffffu, mx0, 2));
        mx1 = fmaxf(mx1, __shfl_xor_sync(0xffffffffu, mx1, 1));
        mx1 = fmaxf(mx1, __shfl_xor_sync(0xffffffffu, mx1, 2));
        float mnew0 = fmaxf(mrow[0], mx0);
        float mnew1 = fmaxf(mrow[1], mx1);
        float corr0 = __expf(mrow[0] - mnew0);
        float corr1 = __expf(mrow[1] - mnew1);
        mrow[0] = mnew0; mrow[1] = mnew1;

        float sm0 = 0.f, sm1 = 0.f;
        #pragma unroll
        for (int nt = 0; nt < 8; nt++) {
            s[nt][0] = __expf(s[nt][0] - mnew0);
            s[nt][1] = __expf(s[nt][1] - mnew0);
            s[nt][2] = __expf(s[nt][2] - mnew1);
            s[nt][3] = __expf(s[nt][3] - mnew1);
            sm0 += s[nt][0] + s[nt][1];
            sm1 += s[nt][2] + s[nt][3];
        }
        sm0 += __shfl_xor_sync(0xffffffffu, sm0, 1);
        sm0 += __shfl_xor_sync(0xffffffffu, sm0, 2);
        sm1 += __shfl_xor_sync(0xffffffffu, sm1, 1);
        sm1 += __shfl_xor_sync(0xffffffffu, sm1, 2);
        lrow[0] = lrow[0] * corr0 + sm0;
        lrow[1] = lrow[1] * corr1 + sm1;
        #pragma unroll
        for (int nt = 0; nt < 8; nt++) {
            o[nt][0] *= corr0; o[nt][1] *= corr0;
            o[nt][2] *= corr1; o[nt][3] *= corr1;
        }

        // O += (Ph+Pl) @ Vh — P from registers
        #pragma unroll
        for (int kc = 0; kc < 4; kc++) {
            uint32_t ph[4], pl[4];
            f2h2(s[2 * kc][0],     s[2 * kc][1],     ph[0], pl[0]);
            f2h2(s[2 * kc][2],     s[2 * kc][3],     ph[1], pl[1]);
            f2h2(s[2 * kc + 1][0], s[2 * kc + 1][1], ph[2], pl[2]);
            f2h2(s[2 * kc + 1][2], s[2 * kc + 1][3], ph[3], pl[3]);
            #pragma unroll
            for (int nt = 0; nt < 8; nt++) {
                uint32_t rv = (uint32_t)(kc * 16 + (lane & 15));
                uint32_t sov = SW128(rv * 128 + nt * 16);
                uint32_t vh[2];
                ldm_x2t(vh, cur + 8192 + sov);
                mma_f16(o[nt], ph, vh);
                mma_f16(o[nt], pl, vh);
            }
        }
    }

    float inv0 = 1.0f / lrow[0];
    float inv1 = 1.0f / lrow[1];
    #pragma unroll
    for (int nt = 0; nt < 8; nt++) {
        int c = h * D_ + nt * 8 + (lane & 3) * 2;
        size_t g0 = (rowbase + q0 + r0) * C_ + c;
        size_t g1 = (rowbase + q0 + r1) * C_ + c;
        float v0 = o[nt][0] * inv0, v1 = o[nt][1] * inv0;
        float v2 = o[nt][2] * inv1, v3 = o[nt][3] * inv1;
        __nv_bfloat162 h2, l2;
        h2.x = __float2bfloat16(v0);
        h2.y = __float2bfloat16(v1);
        l2.x = __float2bfloat16(v0 - __bfloat162float(h2.x));
        l2.y = __float2bfloat16(v1 - __bfloat162float(h2.y));
        *(__nv_bfloat162*)&ch[g0] = h2;
        *(__nv_bfloat162*)&cl[g0] = l2;
        h2.x = __float2bfloat16(v2);
        h2.y = __float2bfloat16(v3);
        l2.x = __float2bfloat16(v2 - __bfloat162float(h2.x));
        l2.y = __float2bfloat16(v3 - __bfloat162float(h2.y));
        *(__nv_bfloat162*)&ch[g1] = h2;
        *(__nv_bfloat162*)&cl[g1] = l2;
    }
}

// ---------------------------------------------------------------------------
extern "C" void kernel_launch(void* const* d_in, const int* in_sizes, int n_in,
                              void* d_out, int out_size)
{
    const float* x    = (const float*)d_in[0];
    const int*   am   = (const int*)d_in[1];
    const float* Wqkv = (const float*)d_in[2];
    const float* bqkv = (const float*)d_in[3];
    const float* Wo   = (const float*)d_in[4];
    const float* bo   = (const float*)d_in[5];
    float* out = (float*)d_out;

    __nv_bfloat16 *xh, *xl, *ch, *cl, *wqh, *wql, *woh, *wol;
    __half *qh, *ql;
    cudaGetSymbolAddress((void**)&xh, g_xh);     cudaGetSymbolAddress((void**)&xl, g_xl);
    cudaGetSymbolAddress((void**)&qh, g_qkvh);   cudaGetSymbolAddress((void**)&ql, g_qkvl);
    cudaGetSymbolAddress((void**)&ch, g_ch);     cudaGetSymbolAddress((void**)&cl, g_cl);
    cudaGetSymbolAddress((void**)&wqh, g_wqh);   cudaGetSymbolAddress((void**)&wql, g_wql);
    cudaGetSymbolAddress((void**)&woh, g_woh);   cudaGetSymbolAddress((void**)&wol, g_wol);

    static bool attr_done = false;
    if (!attr_done) {
        cudaFuncSetAttribute(gemm_bf16x3<0>,
                             cudaFuncAttributeMaxDynamicSharedMemorySize, GS_TOTAL);
        cudaFuncSetAttribute(gemm_bf16x3<1>,
                             cudaFuncAttributeMaxDynamicSharedMemorySize, GS_TOTAL);
        cudaFuncSetAttribute(attn_mma,
                             cudaFuncAttributeMaxDynamicSharedMemorySize, A_TOTAL);
        attr_done = true;
    }

    mask_norm<<<1, 1024>>>(am);
    split_rm<<<(BT_ * C_ + 255) / 256, 256>>>(x, xh, xl, BT_ * C_);
    split_tr<<<(C_ * C3_ + 255) / 256, 256>>>(Wqkv, wqh, wql, C_, C3_);

    // 1) QKV projection -> fp16 hi/lo
    gemm_bf16x3<1><<<dim3(C3_ / 128, BT_ / 128), 256, GS_TOTAL>>>(
        xh, xl, wqh, wql, bqkv, nullptr, qh, ql, BT_, C3_, C_);

    // 2) Attention (q-tile 256, 16 warps) -> ctx bf16 hi/lo
    attn_mma<<<dim3(T_ / 256, H_, B_), 512, A_TOTAL>>>(qh, ql, ch, cl);

    // 3) Output projection -> fp32
    split_tr<<<(C_ * C_ + 255) / 256, 256>>>(Wo, woh, wol, C_, C_);
    gemm_bf16x3<0><<<dim3(C_ / 128, BT_ / 128), 256, GS_TOTAL>>>(
        ch, cl, woh, wol, bo, out, nullptr, nullptr, BT_, C_, C_);
}

// round 9
// speedup vs baseline: 3.9859x; 1.1815x over previous
#include <cuda_runtime.h>
#include <cuda_bf16.h>
#include <cuda_fp16.h>
#include <math.h>
#include <stdint.h>

#define B_ 4
#define T_ 2048
#define C_ 768
#define H_ 12
#define D_ 64
#define BT_ (B_ * T_)
#define C3_ (3 * C_)

// ---------------------------------------------------------------------------
// Device scratch (no runtime allocation allowed)
// ---------------------------------------------------------------------------
__device__ int g_keep[BT_];

__device__ __half g_xh[(size_t)BT_ * C_],    g_xl[(size_t)BT_ * C_];
__device__ __half g_qkvh[(size_t)BT_ * C3_], g_qkvl[(size_t)BT_ * C3_];
__device__ __half g_ch[(size_t)BT_ * C_],    g_cl[(size_t)BT_ * C_];
__device__ __half g_wqh[(size_t)C3_ * C_];   // Wqkv^T hi only
__device__ __half g_woh[(size_t)C_ * C_];    // Wo^T   hi only

// ---------------------------------------------------------------------------
// PTX helpers
// ---------------------------------------------------------------------------
__device__ __forceinline__ uint32_t smem_u32(const void* p) {
    uint32_t a;
    asm("{ .reg .u64 t; cvta.to.shared.u64 t, %1; cvt.u32.u64 %0, t; }"
        : "=r"(a) : "l"(p));
    return a;
}
__device__ __forceinline__ void ldm_x4(uint32_t (&r)[4], uint32_t addr) {
    asm volatile("ldmatrix.sync.aligned.m8n8.x4.shared.b16 {%0,%1,%2,%3}, [%4];"
        : "=r"(r[0]), "=r"(r[1]), "=r"(r[2]), "=r"(r[3]) : "r"(addr));
}
__device__ __forceinline__ void ldm_x4t(uint32_t (&r)[4], uint32_t addr) {
    asm volatile("ldmatrix.sync.aligned.m8n8.x4.trans.shared.b16 {%0,%1,%2,%3}, [%4];"
        : "=r"(r[0]), "=r"(r[1]), "=r"(r[2]), "=r"(r[3]) : "r"(addr));
}
__device__ __forceinline__ void mma_f16(float (&d)[4], const uint32_t (&a)[4],
                                        uint32_t b0, uint32_t b1) {
    asm volatile(
        "mma.sync.aligned.m16n8k16.row.col.f32.f16.f16.f32 "
        "{%0,%1,%2,%3}, {%4,%5,%6,%7}, {%8,%9}, {%0,%1,%2,%3};"
        : "+f"(d[0]), "+f"(d[1]), "+f"(d[2]), "+f"(d[3])
        : "r"(a[0]), "r"(a[1]), "r"(a[2]), "r"(a[3]), "r"(b0), "r"(b1));
}
__device__ __forceinline__ void cp16(uint32_t saddr, const void* g) {
    asm volatile("cp.async.cg.shared.global [%0], [%1], 16;"
        :: "r"(saddr), "l"(g));
}
#define CP_COMMIT() asm volatile("cp.async.commit_group;" ::: "memory")
#define CP_WAIT(n)  asm volatile("cp.async.wait_group %0;" :: "n"(n) : "memory")
#define SW128(o) ((o) ^ (((o) >> 3) & 0x70))

__device__ __forceinline__ void f2h2(float a, float b, uint32_t& h, uint32_t& l) {
    __half ha = __float2half_rn(a), hb = __float2half_rn(b);
    __half2 hh = __halves2half2(ha, hb);
    __half2 ll = __halves2half2(__float2half_rn(a - __half2float(ha)),
                                __float2half_rn(b - __half2float(hb)));
    h = *(uint32_t*)&hh;
    l = *(uint32_t*)&ll;
}

// ---------------------------------------------------------------------------
__global__ __launch_bounds__(1024) void mask_norm(const int* __restrict__ amw)
{
    const int tid = threadIdx.x;
    int allzero = 1;
    for (int i = tid; i < BT_; i += 1024)
        if (i & 1) allzero &= (amw[i] == 0);
    int is64 = __syncthreads_and(allzero);
    for (int i = tid; i < BT_; i += 1024) {
        int v = is64 ? amw[2 * i] : amw[i];
        g_keep[i] = (v == 0) ? 1 : 0;
    }
}

// fp32 -> fp16 hi/lo split, same layout
__global__ __launch_bounds__(256) void split_rm_h(
    const float* __restrict__ in, __half* __restrict__ hi,
    __half* __restrict__ lo, int n)
{
    int i = blockIdx.x * 256 + threadIdx.x;
    if (i >= n) return;
    float x = in[i];
    __half h = __float2half_rn(x);
    hi[i] = h;
    lo[i] = __float2half_rn(x - __half2float(h));
}

// fp32 W[K][N] -> fp16 hi transposed [N][K]
__global__ __launch_bounds__(256) void split_tr_h(
    const float* __restrict__ in, __half* __restrict__ hi, int K, int N)
{
    int i = blockIdx.x * 256 + threadIdx.x;
    if (i >= K * N) return;
    int k = i / N, n = i - k * N;
    hi[(size_t)n * K + k] = __float2half_rn(in[i]);
}

// ---------------------------------------------------------------------------
// fp16 2-term HMMA GEMM: Out = (Ah+Al)[M][K] @ (Bh[N][K])^T + bias
// 3-stage cp.async pipeline. CTA 128x128, 8 warps, warp tile 64x32.
// MODE 0: fp32 Out.  MODE 1: fp16 hi/lo pair (Hh/Hl).
// ---------------------------------------------------------------------------
#define GS_AH 0
#define GS_AL 16384
#define GS_BH 32768
#define GSTG  49152
#define GS_TOTAL (3 * GSTG)

template <int MODE>
__global__ __launch_bounds__(256) void gemm_f16x2(
    const __half* __restrict__ Ah, const __half* __restrict__ Al,
    const __half* __restrict__ Bh,
    const float* __restrict__ bias, float* __restrict__ Out,
    __half* __restrict__ Hh, __half* __restrict__ Hl,
    int M, int N, int K)
{
    extern __shared__ __align__(1024) char smem[];
    const uint32_t sb = smem_u32(smem);
    const int tid  = threadIdx.x;
    const int wid  = tid >> 5;
    const int lane = tid & 31;
    const int m0 = blockIdx.y * 128;
    const int n0 = blockIdx.x * 128;
    const int wm = wid >> 2;
    const int wn = wid & 3;
    const int l8  = lane & 7;
    const int sel = lane >> 3;

    int lr[4], luk[4];
    uint32_t lso[4];
    #pragma unroll
    for (int i = 0; i < 4; i++) {
        int u = tid + 256 * i;
        lr[i] = u >> 3; luk[i] = u & 7;
        lso[i] = SW128((uint32_t)(lr[i] * 128 + luk[i] * 16));
    }

    const int nstages = K / 64;
    auto stage_load = [&](int s, uint32_t dst) {
        const int k0 = s * 64;
        #pragma unroll
        for (int i = 0; i < 4; i++) {
            size_t ga = (size_t)(m0 + lr[i]) * K + k0 + luk[i] * 8;
            size_t gb = (size_t)(n0 + lr[i]) * K + k0 + luk[i] * 8;
            cp16(dst + GS_AH + lso[i], Ah + ga);
            cp16(dst + GS_AL + lso[i], Al + ga);
            cp16(dst + GS_BH + lso[i], Bh + gb);
        }
    };

    float acc[4][4][4];
    #pragma unroll
    for (int i = 0; i < 4; i++)
        #pragma unroll
        for (int j = 0; j < 4; j++)
            #pragma unroll
            for (int r = 0; r < 4; r++) acc[i][j][r] = 0.f;

    stage_load(0, sb);
    CP_COMMIT();
    stage_load(1, sb + GSTG);
    CP_COMMIT();

    int buf = 0;
    for (int s = 0; s < nstages; s++) {
        const uint32_t cur = sb + (uint32_t)buf * GSTG;
        if (s + 2 < nstages) {
            int nb = buf + 2; if (nb >= 3) nb -= 3;
            stage_load(s + 2, sb + (uint32_t)nb * GSTG);
            CP_COMMIT();
            CP_WAIT(2);
        } else if (s + 1 < nstages) {
            CP_WAIT(1);
        } else {
            CP_WAIT(0);
        }
        __syncthreads();

        #pragma unroll
        for (int kk = 0; kk < 4; kk++) {
            // B fragments: 2 x4 loads cover 4 n-subtiles
            uint32_t bh4[2][4];
            #pragma unroll
            for (int nt2 = 0; nt2 < 2; nt2++) {
                uint32_t row = (uint32_t)(wn * 32 + nt2 * 16 + ((sel & 2) ? 8 : 0) + l8);
                uint32_t so = SW128(row * 128 + kk * 32 + ((sel & 1) << 4));
                ldm_x4(bh4[nt2], cur + GS_BH + so);
            }
            #pragma unroll
            for (int mt = 0; mt < 4; mt++) {
                uint32_t rm = (uint32_t)(wm * 64 + mt * 16 + (lane & 15));
                uint32_t so = SW128(rm * 128 + kk * 32 + ((lane >> 4) << 4));
                uint32_t ah[4], al[4];
                ldm_x4(ah, cur + GS_AH + so);
                ldm_x4(al, cur + GS_AL + so);
                #pragma unroll
                for (int nt = 0; nt < 4; nt++) {
                    uint32_t b0 = bh4[nt >> 1][(nt & 1) * 2];
                    uint32_t b1 = bh4[nt >> 1][(nt & 1) * 2 + 1];
                    mma_f16(acc[mt][nt], ah, b0, b1);
                    mma_f16(acc[mt][nt], al, b0, b1);
                }
            }
        }
        __syncthreads();
        if (++buf == 3) buf = 0;
    }

    #pragma unroll
    for (int mt = 0; mt < 4; mt++) {
        #pragma unroll
        for (int nt = 0; nt < 4; nt++) {
            int grow = m0 + wm * 64 + mt * 16 + (lane >> 2);
            int gcol = n0 + wn * 32 + nt * 8 + (lane & 3) * 2;
            float2 bb = *(const float2*)&bias[gcol];
            float v0 = acc[mt][nt][0] + bb.x, v1 = acc[mt][nt][1] + bb.y;
            float v2 = acc[mt][nt][2] + bb.x, v3 = acc[mt][nt][3] + bb.y;
            if (MODE == 1) {
                uint32_t h, l;
                f2h2(v0, v1, h, l);
                *(uint32_t*)&Hh[(size_t)grow * N + gcol] = h;
                *(uint32_t*)&Hl[(size_t)grow * N + gcol] = l;
                f2h2(v2, v3, h, l);
                *(uint32_t*)&Hh[(size_t)(grow + 8) * N + gcol] = h;
                *(uint32_t*)&Hl[(size_t)(grow + 8) * N + gcol] = l;
            } else {
                *(float2*)&Out[(size_t)grow * N + gcol] = make_float2(v0, v1);
                *(float2*)&Out[(size_t)(grow + 8) * N + gcol] = make_float2(v2, v3);
            }
        }
    }
}

// ---------------------------------------------------------------------------
// Flash attention: q-tile 256, 512 threads / 16 warps, warp owns 16 rows.
// fp16 2-term: S = (Qh+Ql)Kh^T;  O = (Ph+Pl)Vh. P in registers.
// K/V fragments via ldmatrix.x4 (2 n-tiles per instruction).
// ---------------------------------------------------------------------------
#define AQ_H   0
#define AQ_L   32768
#define ASTG_BASE 65536
#define ASTG   16384          // per-stage: K_H(0), V_H(8192)
#define A_BIAS 98304          // float[2][64]
#define A_TOTAL 98816

__global__ __launch_bounds__(512) void attn_mma(
    const __half* __restrict__ qkvh, const __half* __restrict__ qkvl,
    __half* __restrict__ ch, __half* __restrict__ cl)
{
    extern __shared__ __align__(1024) char smem[];
    const uint32_t sb = smem_u32(smem);
    float (*sbias)[64] = (float(*)[64])(smem + A_BIAS);

    const int tid  = threadIdx.x;
    const int wid  = tid >> 5;
    const int lane = tid & 31;
    const int l8   = lane & 7;
    const int sel  = lane >> 3;
    const int q0 = blockIdx.x * 256;
    const int h  = blockIdx.y;
    const int b  = blockIdx.z;

    const size_t rowbase = (size_t)b * T_;
    const int* keepb = g_keep + b * T_;

    // Q tile: 256 rows x 64 fp16 (hi/lo); 4 units per thread
    #pragma unroll
    for (int i = 0; i < 4; i++) {
        int u = tid + 512 * i;
        int r = u >> 3, uk = u & 7;
        uint32_t so = SW128((uint32_t)(r * 128 + uk * 16));
        size_t g = (rowbase + q0 + r) * C3_ + h * D_ + uk * 8;
        cp16(sb + AQ_H + so, qkvh + g);
        cp16(sb + AQ_L + so, qkvl + g);
    }

    const int klr = tid >> 3, kuk = tid & 7;
    const uint32_t klso = SW128((uint32_t)(klr * 128 + kuk * 16));
    auto kv_load = [&](int kb, uint32_t dst) {
        const int k0 = kb * 64;
        size_t gk = (rowbase + k0 + klr) * C3_ + C_ + h * D_ + kuk * 8;
        size_t gv = (rowbase + k0 + klr) * C3_ + 2 * C_ + h * D_ + kuk * 8;
        cp16(dst + 0    + klso, qkvh + gk);
        cp16(dst + 8192 + klso, qkvh + gv);
    };
    kv_load(0, sb + ASTG_BASE);
    CP_COMMIT();

    const int r0 = wid * 16 + (lane >> 2);
    const int r1 = r0 + 8;

    float mrow[2] = {-INFINITY, -INFINITY};
    float lrow[2] = {0.f, 0.f};
    float o[8][4];
    #pragma unroll
    for (int nt = 0; nt < 8; nt++)
        #pragma unroll
        for (int r = 0; r < 4; r++) o[nt][r] = 0.f;

    for (int kb = 0; kb < 32; kb++) {
        const int k0 = kb * 64;
        const uint32_t cur = sb + ASTG_BASE + (uint32_t)(kb & 1) * ASTG;

        int keepv = (tid < 64) ? keepb[k0 + tid] : 0;
        CP_WAIT(0);
        if (tid < 64) sbias[kb & 1][tid] = keepv ? 0.f : -1e30f;
        __syncthreads();
        if (kb + 1 < 32) {
            kv_load(kb + 1, sb + ASTG_BASE + (uint32_t)((kb + 1) & 1) * ASTG);
            CP_COMMIT();
        }

        // S = (Qh+Ql) @ Kh^T
        float s[8][4];
        #pragma unroll
        for (int nt = 0; nt < 8; nt++)
            #pragma unroll
            for (int r = 0; r < 4; r++) s[nt][r] = 0.f;

        #pragma unroll
        for (int kk = 0; kk < 4; kk++) {
            uint32_t rm = (uint32_t)(wid * 16 + (lane & 15));
            uint32_t soa = SW128(rm * 128 + kk * 32 + ((lane >> 4) << 4));
            uint32_t qh[4], ql[4];
            ldm_x4(qh, sb + AQ_H + soa);
            ldm_x4(ql, sb + AQ_L + soa);
            #pragma unroll
            for (int nt2 = 0; nt2 < 4; nt2++) {
                uint32_t row = (uint32_t)(nt2 * 16 + ((sel & 2) ? 8 : 0) + l8);
                uint32_t sob = SW128(row * 128 + kk * 32 + ((sel & 1) << 4));
                uint32_t kh4[4];
                ldm_x4(kh4, cur + sob);
                mma_f16(s[2 * nt2],     qh, kh4[0], kh4[1]);
                mma_f16(s[2 * nt2],     ql, kh4[0], kh4[1]);
                mma_f16(s[2 * nt2 + 1], qh, kh4[2], kh4[3]);
                mma_f16(s[2 * nt2 + 1], ql, kh4[2], kh4[3]);
            }
        }

        const float* bia = sbias[kb & 1];
        #pragma unroll
        for (int nt = 0; nt < 8; nt++) {
            int c = nt * 8 + (lane & 3) * 2;
            float b0 = bia[c], b1 = bia[c + 1];
            s[nt][0] = s[nt][0] * 0.125f + b0;
            s[nt][1] = s[nt][1] * 0.125f + b1;
            s[nt][2] = s[nt][2] * 0.125f + b0;
            s[nt][3] = s[nt][3] * 0.125f + b1;
        }

        float mx0 = -INFINITY, mx1 = -INFINITY;
        #pragma unroll
        for (int nt = 0; nt < 8; nt++) {
            mx0 = fmaxf(mx0, fmaxf(s[nt][0], s[nt][1]));
            mx1 = fmaxf(mx1, fmaxf(s[nt][2], s[nt][3]));
        }
        mx0 = fmaxf(mx0, __shfl_xor_sync(0xffffffffu, mx0, 1));
        mx0 = fmaxf(mx0, __shfl_xor_sync(0xffffffffu, mx0, 2));
        mx1 = fmaxf(mx1, __shfl_xor_sync(0xffffffffu, mx1, 1));
        mx1 = fmaxf(mx1, __shfl_xor_sync(0xffffffffu, mx1, 2));
        float mnew0 = fmaxf(mrow[0], mx0);
        float mnew1 = fmaxf(mrow[1], mx1);
        float corr0 = __expf(mrow[0] - mnew0);
        float corr1 = __expf(mrow[1] - mnew1);
        mrow[0] = mnew0; mrow[1] = mnew1;

        float sm0 = 0.f, sm1 = 0.f;
        #pragma unroll
        for (int nt = 0; nt < 8; nt++) {
            s[nt][0] = __expf(s[nt][0] - mnew0);
            s[nt][1] = __expf(s[nt][1] - mnew0);
            s[nt][2] = __expf(s[nt][2] - mnew1);
            s[nt][3] = __expf(s[nt][3] - mnew1);
            sm0 += s[nt][0] + s[nt][1];
            sm1 += s[nt][2] + s[nt][3];
        }
        sm0 += __shfl_xor_sync(0xffffffffu, sm0, 1);
        sm0 += __shfl_xor_sync(0xffffffffu, sm0, 2);
        sm1 += __shfl_xor_sync(0xffffffffu, sm1, 1);
        sm1 += __shfl_xor_sync(0xffffffffu, sm1, 2);
        lrow[0] = lrow[0] * corr0 + sm0;
        lrow[1] = lrow[1] * corr1 + sm1;
        #pragma unroll
        for (int nt = 0; nt < 8; nt++) {
            o[nt][0] *= corr0; o[nt][1] *= corr0;
            o[nt][2] *= corr1; o[nt][3] *= corr1;
        }

        // O += (Ph+Pl) @ Vh
        #pragma unroll
        for (int kc = 0; kc < 4; kc++) {
            uint32_t ph[4], pl[4];
            f2h2(s[2 * kc][0],     s[2 * kc][1],     ph[0], pl[0]);
            f2h2(s[2 * kc][2],     s[2 * kc][3],     ph[1], pl[1]);
            f2h2(s[2 * kc + 1][0], s[2 * kc + 1][1], ph[2], pl[2]);
            f2h2(s[2 * kc + 1][2], s[2 * kc + 1][3], ph[3], pl[3]);
            #pragma unroll
            for (int nt2 = 0; nt2 < 4; nt2++) {
                uint32_t row = (uint32_t)(kc * 16 + ((sel & 1) ? 8 : 0) + l8);
                uint32_t sov = SW128(row * 128 + nt2 * 32 + (((sel >> 1) & 1) << 4));
                uint32_t vh4[4];
                ldm_x4t(vh4, cur + 8192 + sov);
                mma_f16(o[2 * nt2],     ph, vh4[0], vh4[1]);
                mma_f16(o[2 * nt2],     pl, vh4[0], vh4[1]);
                mma_f16(o[2 * nt2 + 1], ph, vh4[2], vh4[3]);
                mma_f16(o[2 * nt2 + 1], pl, vh4[2], vh4[3]);
            }
        }
    }

    float inv0 = 1.0f / lrow[0];
    float inv1 = 1.0f / lrow[1];
    #pragma unroll
    for (int nt = 0; nt < 8; nt++) {
        int c = h * D_ + nt * 8 + (lane & 3) * 2;
        size_t g0 = (rowbase + q0 + r0) * C_ + c;
        size_t g1 = (rowbase + q0 + r1) * C_ + c;
        uint32_t hh, ll;
        f2h2(o[nt][0] * inv0, o[nt][1] * inv0, hh, ll);
        *(uint32_t*)&ch[g0] = hh;
        *(uint32_t*)&cl[g0] = ll;
        f2h2(o[nt][2] * inv1, o[nt][3] * inv1, hh, ll);
        *(uint32_t*)&ch[g1] = hh;
        *(uint32_t*)&cl[g1] = ll;
    }
}

// ---------------------------------------------------------------------------
extern "C" void kernel_launch(void* const* d_in, const int* in_sizes, int n_in,
                              void* d_out, int out_size)
{
    const float* x    = (const float*)d_in[0];
    const int*   am   = (const int*)d_in[1];
    const float* Wqkv = (const float*)d_in[2];
    const float* bqkv = (const float*)d_in[3];
    const float* Wo   = (const float*)d_in[4];
    const float* bo   = (const float*)d_in[5];
    float* out = (float*)d_out;

    __half *xh, *xl, *qh, *ql, *ch, *cl, *wqh, *woh;
    cudaGetSymbolAddress((void**)&xh, g_xh);     cudaGetSymbolAddress((void**)&xl, g_xl);
    cudaGetSymbolAddress((void**)&qh, g_qkvh);   cudaGetSymbolAddress((void**)&ql, g_qkvl);
    cudaGetSymbolAddress((void**)&ch, g_ch);     cudaGetSymbolAddress((void**)&cl, g_cl);
    cudaGetSymbolAddress((void**)&wqh, g_wqh);   cudaGetSymbolAddress((void**)&woh, g_woh);

    static bool attr_done = false;
    if (!attr_done) {
        cudaFuncSetAttribute(gemm_f16x2<0>,
                             cudaFuncAttributeMaxDynamicSharedMemorySize, GS_TOTAL);
        cudaFuncSetAttribute(gemm_f16x2<1>,
                             cudaFuncAttributeMaxDynamicSharedMemorySize, GS_TOTAL);
        cudaFuncSetAttribute(attn_mma,
                             cudaFuncAttributeMaxDynamicSharedMemorySize, A_TOTAL);
        attr_done = true;
    }

    mask_norm<<<1, 1024>>>(am);
    split_rm_h<<<(BT_ * C_ + 255) / 256, 256>>>(x, xh, xl, BT_ * C_);
    split_tr_h<<<(C_ * C3_ + 255) / 256, 256>>>(Wqkv, wqh, C_, C3_);

    // 1) QKV projection -> fp16 hi/lo
    gemm_f16x2<1><<<dim3(C3_ / 128, BT_ / 128), 256, GS_TOTAL>>>(
        xh, xl, wqh, bqkv, nullptr, qh, ql, BT_, C3_, C_);

    // 2) Attention (q-tile 256, 16 warps) -> ctx fp16 hi/lo
    attn_mma<<<dim3(T_ / 256, H_, B_), 512, A_TOTAL>>>(qh, ql, ch, cl);

    // 3) Output projection -> fp32
    split_tr_h<<<(C_ * C_ + 255) / 256, 256>>>(Wo, woh, C_, C_);
    gemm_f16x2<0><<<dim3(C_ / 128, BT_ / 128), 256, GS_TOTAL>>>(
        ch, cl, woh, bo, out, nullptr, nullptr, BT_, C_, C_);
}

// round 10
// speedup vs baseline: 4.5095x; 1.1313x over previous
#include <cuda_runtime.h>
#include <cuda_bf16.h>
#include <cuda_fp16.h>
#include <math.h>
#include <stdint.h>

#define B_ 4
#define T_ 2048
#define C_ 768
#define H_ 12
#define D_ 64
#define BT_ (B_ * T_)
#define C3_ (3 * C_)

// ---------------------------------------------------------------------------
// Device scratch (no runtime allocation allowed)
// ---------------------------------------------------------------------------
__device__ int g_keep[BT_];

__device__ __half g_xh[(size_t)BT_ * C_],    g_xl[(size_t)BT_ * C_];
__device__ __half g_qkvh[(size_t)BT_ * C3_], g_qkvl[(size_t)BT_ * C3_];
__device__ __half g_ch[(size_t)BT_ * C_],    g_cl[(size_t)BT_ * C_];
__device__ __half g_wqh[(size_t)C3_ * C_];   // Wqkv^T hi only
__device__ __half g_woh[(size_t)C_ * C_];    // Wo^T   hi only

// ---------------------------------------------------------------------------
// PTX helpers
// ---------------------------------------------------------------------------
__device__ __forceinline__ uint32_t smem_u32(const void* p) {
    uint32_t a;
    asm("{ .reg .u64 t; cvta.to.shared.u64 t, %1; cvt.u32.u64 %0, t; }"
        : "=r"(a) : "l"(p));
    return a;
}
__device__ __forceinline__ void ldm_x4(uint32_t (&r)[4], uint32_t addr) {
    asm volatile("ldmatrix.sync.aligned.m8n8.x4.shared.b16 {%0,%1,%2,%3}, [%4];"
        : "=r"(r[0]), "=r"(r[1]), "=r"(r[2]), "=r"(r[3]) : "r"(addr));
}
__device__ __forceinline__ void ldm_x4t(uint32_t (&r)[4], uint32_t addr) {
    asm volatile("ldmatrix.sync.aligned.m8n8.x4.trans.shared.b16 {%0,%1,%2,%3}, [%4];"
        : "=r"(r[0]), "=r"(r[1]), "=r"(r[2]), "=r"(r[3]) : "r"(addr));
}
__device__ __forceinline__ void mma_f16(float (&d)[4], const uint32_t (&a)[4],
                                        uint32_t b0, uint32_t b1) {
    asm volatile(
        "mma.sync.aligned.m16n8k16.row.col.f32.f16.f16.f32 "
        "{%0,%1,%2,%3}, {%4,%5,%6,%7}, {%8,%9}, {%0,%1,%2,%3};"
        : "+f"(d[0]), "+f"(d[1]), "+f"(d[2]), "+f"(d[3])
        : "r"(a[0]), "r"(a[1]), "r"(a[2]), "r"(a[3]), "r"(b0), "r"(b1));
}
__device__ __forceinline__ void cp16(uint32_t saddr, const void* g) {
    asm volatile("cp.async.cg.shared.global [%0], [%1], 16;"
        :: "r"(saddr), "l"(g));
}
#define CP_COMMIT() asm volatile("cp.async.commit_group;" ::: "memory")
#define CP_WAIT(n)  asm volatile("cp.async.wait_group %0;" :: "n"(n) : "memory")
#define SW128(o) ((o) ^ (((o) >> 3) & 0x70))

__device__ __forceinline__ void f2h2(float a, float b, uint32_t& h, uint32_t& l) {
    __half ha = __float2half_rn(a), hb = __float2half_rn(b);
    __half2 hh = __halves2half2(ha, hb);
    __half2 ll = __halves2half2(__float2half_rn(a - __half2float(ha)),
                                __float2half_rn(b - __half2float(hb)));
    h = *(uint32_t*)&hh;
    l = *(uint32_t*)&ll;
}
__device__ __forceinline__ uint32_t packh2(float a, float b) {
    __half2 hh = __floats2half2_rn(a, b);
    return *(uint32_t*)&hh;
}

// ---------------------------------------------------------------------------
__global__ __launch_bounds__(1024) void mask_norm(const int* __restrict__ amw)
{
    const int tid = threadIdx.x;
    int allzero = 1;
    for (int i = tid; i < BT_; i += 1024)
        if (i & 1) allzero &= (amw[i] == 0);
    int is64 = __syncthreads_and(allzero);
    for (int i = tid; i < BT_; i += 1024) {
        int v = is64 ? amw[2 * i] : amw[i];
        g_keep[i] = (v == 0) ? 1 : 0;
    }
}

__global__ __launch_bounds__(256) void split_rm_h(
    const float* __restrict__ in, __half* __restrict__ hi,
    __half* __restrict__ lo, int n)
{
    int i = blockIdx.x * 256 + threadIdx.x;
    if (i >= n) return;
    float x = in[i];
    __half h = __float2half_rn(x);
    hi[i] = h;
    lo[i] = __float2half_rn(x - __half2float(h));
}

__global__ __launch_bounds__(256) void split_tr_h(
    const float* __restrict__ in, __half* __restrict__ hi, int K, int N)
{
    int i = blockIdx.x * 256 + threadIdx.x;
    if (i >= K * N) return;
    int k = i / N, n = i - k * N;
    hi[(size_t)n * K + k] = __float2half_rn(in[i]);
}

// ---------------------------------------------------------------------------
// fp16 2-term HMMA GEMM: Out = (Ah+Al)[M][K] @ (Bh[N][K])^T + bias
// 3-stage cp.async pipeline. CTA 128x128, 512 threads / 16 warps (4x4),
// warp tile 32x32 (4 warps/SMSP for latency hiding).
// MODE 0: fp32 Out.  MODE 1: fp16 hi/lo pair (Hh/Hl).
// ---------------------------------------------------------------------------
#define GS_AH 0
#define GS_AL 16384
#define GS_BH 32768
#define GSTG  49152
#define GS_TOTAL (3 * GSTG)

template <int MODE>
__global__ __launch_bounds__(512) void gemm_f16x2(
    const __half* __restrict__ Ah, const __half* __restrict__ Al,
    const __half* __restrict__ Bh,
    const float* __restrict__ bias, float* __restrict__ Out,
    __half* __restrict__ Hh, __half* __restrict__ Hl,
    int M, int N, int K)
{
    extern __shared__ __align__(1024) char smem[];
    const uint32_t sb = smem_u32(smem);
    const int tid  = threadIdx.x;
    const int wid  = tid >> 5;
    const int lane = tid & 31;
    const int m0 = blockIdx.y * 128;
    const int n0 = blockIdx.x * 128;
    const int wm = wid >> 2;       // 0..3 -> rows wm*32
    const int wn = wid & 3;        // 0..3 -> cols wn*32
    const int l8  = lane & 7;
    const int sel = lane >> 3;

    // Staging: 3 tiles x 1024 16B-units, 512 threads -> 2 units/thread/tile
    int lr[2], luk[2];
    uint32_t lso[2];
    #pragma unroll
    for (int i = 0; i < 2; i++) {
        int u = tid + 512 * i;
        lr[i] = u >> 3; luk[i] = u & 7;
        lso[i] = SW128((uint32_t)(lr[i] * 128 + luk[i] * 16));
    }

    const int nstages = K / 64;
    auto stage_load = [&](int s, uint32_t dst) {
        const int k0 = s * 64;
        #pragma unroll
        for (int i = 0; i < 2; i++) {
            size_t ga = (size_t)(m0 + lr[i]) * K + k0 + luk[i] * 8;
            size_t gb = (size_t)(n0 + lr[i]) * K + k0 + luk[i] * 8;
            cp16(dst + GS_AH + lso[i], Ah + ga);
            cp16(dst + GS_AL + lso[i], Al + ga);
            cp16(dst + GS_BH + lso[i], Bh + gb);
        }
    };

    float acc[2][4][4];
    #pragma unroll
    for (int i = 0; i < 2; i++)
        #pragma unroll
        for (int j = 0; j < 4; j++)
            #pragma unroll
            for (int r = 0; r < 4; r++) acc[i][j][r] = 0.f;

    stage_load(0, sb);
    CP_COMMIT();
    stage_load(1, sb + GSTG);
    CP_COMMIT();

    int buf = 0;
    for (int s = 0; s < nstages; s++) {
        const uint32_t cur = sb + (uint32_t)buf * GSTG;
        if (s + 2 < nstages) {
            int nb = buf + 2; if (nb >= 3) nb -= 3;
            stage_load(s + 2, sb + (uint32_t)nb * GSTG);
            CP_COMMIT();
            CP_WAIT(2);
        } else if (s + 1 < nstages) {
            CP_WAIT(1);
        } else {
            CP_WAIT(0);
        }
        __syncthreads();

        #pragma unroll
        for (int kk = 0; kk < 4; kk++) {
            uint32_t bh4[2][4];
            #pragma unroll
            for (int nt2 = 0; nt2 < 2; nt2++) {
                uint32_t row = (uint32_t)(wn * 32 + nt2 * 16 + ((sel & 2) ? 8 : 0) + l8);
                uint32_t so = SW128(row * 128 + kk * 32 + ((sel & 1) << 4));
                ldm_x4(bh4[nt2], cur + GS_BH + so);
            }
            #pragma unroll
            for (int mt = 0; mt < 2; mt++) {
                uint32_t rm = (uint32_t)(wm * 32 + mt * 16 + (lane & 15));
                uint32_t so = SW128(rm * 128 + kk * 32 + ((lane >> 4) << 4));
                uint32_t ah[4], al[4];
                ldm_x4(ah, cur + GS_AH + so);
                ldm_x4(al, cur + GS_AL + so);
                #pragma unroll
                for (int nt = 0; nt < 4; nt++) {
                    uint32_t b0 = bh4[nt >> 1][(nt & 1) * 2];
                    uint32_t b1 = bh4[nt >> 1][(nt & 1) * 2 + 1];
                    mma_f16(acc[mt][nt], ah, b0, b1);
                    mma_f16(acc[mt][nt], al, b0, b1);
                }
            }
        }
        __syncthreads();
        if (++buf == 3) buf = 0;
    }

    #pragma unroll
    for (int mt = 0; mt < 2; mt++) {
        #pragma unroll
        for (int nt = 0; nt < 4; nt++) {
            int grow = m0 + wm * 32 + mt * 16 + (lane >> 2);
            int gcol = n0 + wn * 32 + nt * 8 + (lane & 3) * 2;
            float2 bb = *(const float2*)&bias[gcol];
            float v0 = acc[mt][nt][0] + bb.x, v1 = acc[mt][nt][1] + bb.y;
            float v2 = acc[mt][nt][2] + bb.x, v3 = acc[mt][nt][3] + bb.y;
            if (MODE == 1) {
                uint32_t h, l;
                f2h2(v0, v1, h, l);
                *(uint32_t*)&Hh[(size_t)grow * N + gcol] = h;
                *(uint32_t*)&Hl[(size_t)grow * N + gcol] = l;
                f2h2(v2, v3, h, l);
                *(uint32_t*)&Hh[(size_t)(grow + 8) * N + gcol] = h;
                *(uint32_t*)&Hl[(size_t)(grow + 8) * N + gcol] = l;
            } else {
                *(float2*)&Out[(size_t)grow * N + gcol] = make_float2(v0, v1);
                *(float2*)&Out[(size_t)(grow + 8) * N + gcol] = make_float2(v2, v3);
            }
        }
    }
}

// ---------------------------------------------------------------------------
// Flash attention: q-tile 256, 512 threads / 16 warps, warp owns 16 rows.
// S = (Qh+Ql)Kh^T (fp16 2-term);  O = P_fp16 @ Vh (single term).
// Softmax in log2 domain (exp2f, scale pre-folded). P in registers.
// ---------------------------------------------------------------------------
#define AQ_H   0
#define AQ_L   32768
#define ASTG_BASE 65536
#define ASTG   16384          // per-stage: K_H(0), V_H(8192)
#define A_BIAS 98304          // float[2][64]
#define A_TOTAL 98816

__global__ __launch_bounds__(512) void attn_mma(
    const __half* __restrict__ qkvh, const __half* __restrict__ qkvl,
    __half* __restrict__ ch, __half* __restrict__ cl)
{
    extern __shared__ __align__(1024) char smem[];
    const uint32_t sb = smem_u32(smem);
    float (*sbias)[64] = (float(*)[64])(smem + A_BIAS);

    const int tid  = threadIdx.x;
    const int wid  = tid >> 5;
    const int lane = tid & 31;
    const int l8   = lane & 7;
    const int sel  = lane >> 3;
    const int q0 = blockIdx.x * 256;
    const int h  = blockIdx.y;
    const int b  = blockIdx.z;

    const size_t rowbase = (size_t)b * T_;
    const int* keepb = g_keep + b * T_;
    const float SC = 0.125f * 1.44269504088896f;  // (1/sqrt(D)) * log2(e)

    // Q tile: 256 rows x 64 fp16 (hi/lo); 4 units per thread
    #pragma unroll
    for (int i = 0; i < 4; i++) {
        int u = tid + 512 * i;
        int r = u >> 3, uk = u & 7;
        uint32_t so = SW128((uint32_t)(r * 128 + uk * 16));
        size_t g = (rowbase + q0 + r) * C3_ + h * D_ + uk * 8;
        cp16(sb + AQ_H + so, qkvh + g);
        cp16(sb + AQ_L + so, qkvl + g);
    }

    const int klr = tid >> 3, kuk = tid & 7;
    const uint32_t klso = SW128((uint32_t)(klr * 128 + kuk * 16));
    auto kv_load = [&](int kb, uint32_t dst) {
        const int k0 = kb * 64;
        size_t gk = (rowbase + k0 + klr) * C3_ + C_ + h * D_ + kuk * 8;
        size_t gv = (rowbase + k0 + klr) * C3_ + 2 * C_ + h * D_ + kuk * 8;
        cp16(dst + 0    + klso, qkvh + gk);
        cp16(dst + 8192 + klso, qkvh + gv);
    };
    kv_load(0, sb + ASTG_BASE);
    CP_COMMIT();

    const int r0 = wid * 16 + (lane >> 2);
    const int r1 = r0 + 8;

    float mrow[2] = {-INFINITY, -INFINITY};
    float lrow[2] = {0.f, 0.f};
    float o[8][4];
    #pragma unroll
    for (int nt = 0; nt < 8; nt++)
        #pragma unroll
        for (int r = 0; r < 4; r++) o[nt][r] = 0.f;

    for (int kb = 0; kb < 32; kb++) {
        const int k0 = kb * 64;
        const uint32_t cur = sb + ASTG_BASE + (uint32_t)(kb & 1) * ASTG;

        int keepv = (tid < 64) ? keepb[k0 + tid] : 0;
        CP_WAIT(0);
        if (tid < 64) sbias[kb & 1][tid] = keepv ? 0.f : -1e30f;
        __syncthreads();
        if (kb + 1 < 32) {
            kv_load(kb + 1, sb + ASTG_BASE + (uint32_t)((kb + 1) & 1) * ASTG);
            CP_COMMIT();
        }

        // S = (Qh+Ql) @ Kh^T
        float s[8][4];
        #pragma unroll
        for (int nt = 0; nt < 8; nt++)
            #pragma unroll
            for (int r = 0; r < 4; r++) s[nt][r] = 0.f;

        #pragma unroll
        for (int kk = 0; kk < 4; kk++) {
            uint32_t rm = (uint32_t)(wid * 16 + (lane & 15));
            uint32_t soa = SW128(rm * 128 + kk * 32 + ((lane >> 4) << 4));
            uint32_t qh[4], ql[4];
            ldm_x4(qh, sb + AQ_H + soa);
            ldm_x4(ql, sb + AQ_L + soa);
            #pragma unroll
            for (int nt2 = 0; nt2 < 4; nt2++) {
                uint32_t row = (uint32_t)(nt2 * 16 + ((sel & 2) ? 8 : 0) + l8);
                uint32_t sob = SW128(row * 128 + kk * 32 + ((sel & 1) << 4));
                uint32_t kh4[4];
                ldm_x4(kh4, cur + sob);
                mma_f16(s[2 * nt2],     qh, kh4[0], kh4[1]);
                mma_f16(s[2 * nt2],     ql, kh4[0], kh4[1]);
                mma_f16(s[2 * nt2 + 1], qh, kh4[2], kh4[3]);
                mma_f16(s[2 * nt2 + 1], ql, kh4[2], kh4[3]);
            }
        }

        // Scale into log2 domain + mask bias
        const float* bia = sbias[kb & 1];
        #pragma unroll
        for (int nt = 0; nt < 8; nt++) {
            int c = nt * 8 + (lane & 3) * 2;
            float b0 = bia[c], b1 = bia[c + 1];
            s[nt][0] = s[nt][0] * SC + b0;
            s[nt][1] = s[nt][1] * SC + b1;
            s[nt][2] = s[nt][2] * SC + b0;
            s[nt][3] = s[nt][3] * SC + b1;
        }

        float mx0 = -INFINITY, mx1 = -INFINITY;
        #pragma unroll
        for (int nt = 0; nt < 8; nt++) {
            mx0 = fmaxf(mx0, fmaxf(s[nt][0], s[nt][1]));
            mx1 = fmaxf(mx1, fmaxf(s[nt][2], s[nt][3]));
        }
        mx0 = fmaxf(mx0, __shfl_xor_sync(0xffffffffu, mx0, 1));
        mx0 = fmaxf(mx0, __shfl_xor_sync(0xffffffffu, mx0, 2));
        mx1 = fmaxf(mx1, __shfl_xor_sync(0xffffffffu, mx1, 1));
        mx1 = fmaxf(mx1, __shfl_xor_sync(0xffffffffu, mx1, 2));
        float mnew0 = fmaxf(mrow[0], mx0);
        float mnew1 = fmaxf(mrow[1], mx1);
        float corr0 = exp2f(mrow[0] - mnew0);
        float corr1 = exp2f(mrow[1] - mnew1);
        mrow[0] = mnew0; mrow[1] = mnew1;

        float sm0 = 0.f, sm1 = 0.f;
        #pragma unroll
        for (int nt = 0; nt < 8; nt++) {
            s[nt][0] = exp2f(s[nt][0] - mnew0);
            s[nt][1] = exp2f(s[nt][1] - mnew0);
            s[nt][2] = exp2f(s[nt][2] - mnew1);
            s[nt][3] = exp2f(s[nt][3] - mnew1);
            sm0 += s[nt][0] + s[nt][1];
            sm1 += s[nt][2] + s[nt][3];
        }
        sm0 += __shfl_xor_sync(0xffffffffu, sm0, 1);
        sm0 += __shfl_xor_sync(0xffffffffu, sm0, 2);
        sm1 += __shfl_xor_sync(0xffffffffu, sm1, 1);
        sm1 += __shfl_xor_sync(0xffffffffu, sm1, 2);
        lrow[0] = lrow[0] * corr0 + sm0;
        lrow[1] = lrow[1] * corr1 + sm1;
        #pragma unroll
        for (int nt = 0; nt < 8; nt++) {
            o[nt][0] *= corr0; o[nt][1] *= corr0;
            o[nt][2] *= corr1; o[nt][3] *= corr1;
        }

        // O += P @ Vh (P single fp16, from registers)
        #pragma unroll
        for (int kc = 0; kc < 4; kc++) {
            uint32_t ph[4];
            ph[0] = packh2(s[2 * kc][0],     s[2 * kc][1]);
            ph[1] = packh2(s[2 * kc][2],     s[2 * kc][3]);
            ph[2] = packh2(s[2 * kc + 1][0], s[2 * kc + 1][1]);
            ph[3] = packh2(s[2 * kc + 1][2], s[2 * kc + 1][3]);
            #pragma unroll
            for (int nt2 = 0; nt2 < 4; nt2++) {
                uint32_t row = (uint32_t)(kc * 16 + ((sel & 1) ? 8 : 0) + l8);
                uint32_t sov = SW128(row * 128 + nt2 * 32 + (((sel >> 1) & 1) << 4));
                uint32_t vh4[4];
                ldm_x4t(vh4, cur + 8192 + sov);
                mma_f16(o[2 * nt2],     ph, vh4[0], vh4[1]);
                mma_f16(o[2 * nt2 + 1], ph, vh4[2], vh4[3]);
            }
        }
    }

    float inv0 = 1.0f / lrow[0];
    float inv1 = 1.0f / lrow[1];
    #pragma unroll
    for (int nt = 0; nt < 8; nt++) {
        int c = h * D_ + nt * 8 + (lane & 3) * 2;
        size_t g0 = (rowbase + q0 + r0) * C_ + c;
        size_t g1 = (rowbase + q0 + r1) * C_ + c;
        uint32_t hh, ll;
        f2h2(o[nt][0] * inv0, o[nt][1] * inv0, hh, ll);
        *(uint32_t*)&ch[g0] = hh;
        *(uint32_t*)&cl[g0] = ll;
        f2h2(o[nt][2] * inv1, o[nt][3] * inv1, hh, ll);
        *(uint32_t*)&ch[g1] = hh;
        *(uint32_t*)&cl[g1] = ll;
    }
}

// ---------------------------------------------------------------------------
extern "C" void kernel_launch(void* const* d_in, const int* in_sizes, int n_in,
                              void* d_out, int out_size)
{
    const float* x    = (const float*)d_in[0];
    const int*   am   = (const int*)d_in[1];
    const float* Wqkv = (const float*)d_in[2];
    const float* bqkv = (const float*)d_in[3];
    const float* Wo   = (const float*)d_in[4];
    const float* bo   = (const float*)d_in[5];
    float* out = (float*)d_out;

    __half *xh, *xl, *qh, *ql, *ch, *cl, *wqh, *woh;
    cudaGetSymbolAddress((void**)&xh, g_xh);     cudaGetSymbolAddress((void**)&xl, g_xl);
    cudaGetSymbolAddress((void**)&qh, g_qkvh);   cudaGetSymbolAddress((void**)&ql, g_qkvl);
    cudaGetSymbolAddress((void**)&ch, g_ch);     cudaGetSymbolAddress((void**)&cl, g_cl);
    cudaGetSymbolAddress((void**)&wqh, g_wqh);   cudaGetSymbolAddress((void**)&woh, g_woh);

    static bool attr_done = false;
    if (!attr_done) {
        cudaFuncSetAttribute(gemm_f16x2<0>,
                             cudaFuncAttributeMaxDynamicSharedMemorySize, GS_TOTAL);
        cudaFuncSetAttribute(gemm_f16x2<1>,
                             cudaFuncAttributeMaxDynamicSharedMemorySize, GS_TOTAL);
        cudaFuncSetAttribute(attn_mma,
                             cudaFuncAttributeMaxDynamicSharedMemorySize, A_TOTAL);
        attr_done = true;
    }

    mask_norm<<<1, 1024>>>(am);
    split_rm_h<<<(BT_ * C_ + 255) / 256, 256>>>(x, xh, xl, BT_ * C_);
    split_tr_h<<<(C_ * C3_ + 255) / 256, 256>>>(Wqkv, wqh, C_, C3_);

    // 1) QKV projection -> fp16 hi/lo
    gemm_f16x2<1><<<dim3(C3_ / 128, BT_ / 128), 512, GS_TOTAL>>>(
        xh, xl, wqh, bqkv, nullptr, qh, ql, BT_, C3_, C_);

    // 2) Attention (q-tile 256, 16 warps) -> ctx fp16 hi/lo
    attn_mma<<<dim3(T_ / 256, H_, B_), 512, A_TOTAL>>>(qh, ql, ch, cl);

    // 3) Output projection -> fp32
    split_tr_h<<<(C_ * C_ + 255) / 256, 256>>>(Wo, woh, C_, C_);
    gemm_f16x2<0><<<dim3(C_ / 128, BT_ / 128), 512, GS_TOTAL>>>(
        ch, cl, woh, bo, out, nullptr, nullptr, BT_, C_, C_);
}

// round 11
// speedup vs baseline: 4.6028x; 1.0207x over previous
#include <cuda_runtime.h>
#include <cuda_bf16.h>
#include <cuda_fp16.h>
#include <math.h>
#include <stdint.h>

#define B_ 4
#define T_ 2048
#define C_ 768
#define H_ 12
#define D_ 64
#define BT_ (B_ * T_)
#define C3_ (3 * C_)

// ---------------------------------------------------------------------------
// Device scratch (no runtime allocation allowed)
// ---------------------------------------------------------------------------
__device__ int g_keep[BT_];

__device__ __half g_xh[(size_t)BT_ * C_],    g_xl[(size_t)BT_ * C_];
__device__ __half g_qkvh[(size_t)BT_ * C3_], g_qkvl[(size_t)BT_ * C3_];
__device__ __half g_ch[(size_t)BT_ * C_],    g_cl[(size_t)BT_ * C_];
__device__ __half g_wqh[(size_t)C3_ * C_];   // Wqkv^T hi only
__device__ __half g_woh[(size_t)C_ * C_];    // Wo^T   hi only

// ---------------------------------------------------------------------------
// PTX helpers
// ---------------------------------------------------------------------------
__device__ __forceinline__ uint32_t smem_u32(const void* p) {
    uint32_t a;
    asm("{ .reg .u64 t; cvta.to.shared.u64 t, %1; cvt.u32.u64 %0, t; }"
        : "=r"(a) : "l"(p));
    return a;
}
__device__ __forceinline__ void ldm_x4(uint32_t (&r)[4], uint32_t addr) {
    asm volatile("ldmatrix.sync.aligned.m8n8.x4.shared.b16 {%0,%1,%2,%3}, [%4];"
        : "=r"(r[0]), "=r"(r[1]), "=r"(r[2]), "=r"(r[3]) : "r"(addr));
}
__device__ __forceinline__ void ldm_x4t(uint32_t (&r)[4], uint32_t addr) {
    asm volatile("ldmatrix.sync.aligned.m8n8.x4.trans.shared.b16 {%0,%1,%2,%3}, [%4];"
        : "=r"(r[0]), "=r"(r[1]), "=r"(r[2]), "=r"(r[3]) : "r"(addr));
}
__device__ __forceinline__ void mma_f16(float (&d)[4], const uint32_t (&a)[4],
                                        uint32_t b0, uint32_t b1) {
    asm volatile(
        "mma.sync.aligned.m16n8k16.row.col.f32.f16.f16.f32 "
        "{%0,%1,%2,%3}, {%4,%5,%6,%7}, {%8,%9}, {%0,%1,%2,%3};"
        : "+f"(d[0]), "+f"(d[1]), "+f"(d[2]), "+f"(d[3])
        : "r"(a[0]), "r"(a[1]), "r"(a[2]), "r"(a[3]), "r"(b0), "r"(b1));
}
__device__ __forceinline__ void cp16(uint32_t saddr, const void* g) {
    asm volatile("cp.async.cg.shared.global [%0], [%1], 16;"
        :: "r"(saddr), "l"(g));
}
#define CP_COMMIT() asm volatile("cp.async.commit_group;" ::: "memory")
#define CP_WAIT(n)  asm volatile("cp.async.wait_group %0;" :: "n"(n) : "memory")
#define SW128(o) ((o) ^ (((o) >> 3) & 0x70))

__device__ __forceinline__ void f2h2(float a, float b, uint32_t& h, uint32_t& l) {
    __half ha = __float2half_rn(a), hb = __float2half_rn(b);
    __half2 hh = __halves2half2(ha, hb);
    __half2 ll = __halves2half2(__float2half_rn(a - __half2float(ha)),
                                __float2half_rn(b - __half2float(hb)));
    h = *(uint32_t*)&hh;
    l = *(uint32_t*)&ll;
}
__device__ __forceinline__ uint32_t packh2(float a, float b) {
    __half2 hh = __floats2half2_rn(a, b);
    return *(uint32_t*)&hh;
}

// ---------------------------------------------------------------------------
__global__ __launch_bounds__(1024) void mask_norm(const int* __restrict__ amw)
{
    const int tid = threadIdx.x;
    int allzero = 1;
    for (int i = tid; i < BT_; i += 1024)
        if (i & 1) allzero &= (amw[i] == 0);
    int is64 = __syncthreads_and(allzero);
    for (int i = tid; i < BT_; i += 1024) {
        int v = is64 ? amw[2 * i] : amw[i];
        g_keep[i] = (v == 0) ? 1 : 0;
    }
}

__global__ __launch_bounds__(256) void split_rm_h(
    const float* __restrict__ in, __half* __restrict__ hi,
    __half* __restrict__ lo, int n)
{
    int i = blockIdx.x * 256 + threadIdx.x;
    if (i >= n) return;
    float x = in[i];
    __half h = __float2half_rn(x);
    hi[i] = h;
    lo[i] = __float2half_rn(x - __half2float(h));
}

__global__ __launch_bounds__(256) void split_tr_h(
    const float* __restrict__ in, __half* __restrict__ hi, int K, int N)
{
    int i = blockIdx.x * 256 + threadIdx.x;
    if (i >= K * N) return;
    int k = i / N, n = i - k * N;
    hi[(size_t)n * K + k] = __float2half_rn(in[i]);
}

// ---------------------------------------------------------------------------
// fp16 2-term HMMA GEMM: Out = (Ah+Al)[M][K] @ (Bh[N][K])^T + bias
// CTA 128x256, 8 warps (2x4), warp tile 64x64 -> 12 ldmatrix : 64 MMA per k16.
// 2-stage cp.async pipeline (64KB/stage).
// MODE 0: fp32 Out.  MODE 1: fp16 hi/lo (lo written only for cols < C_).
// ---------------------------------------------------------------------------
#define GS_AH 0
#define GS_AL 16384
#define GS_BH 32768
#define GSTG  65536
#define GS_TOTAL (2 * GSTG)

template <int MODE>
__global__ __launch_bounds__(256) void gemm_f16x2(
    const __half* __restrict__ Ah, const __half* __restrict__ Al,
    const __half* __restrict__ Bh,
    const float* __restrict__ bias, float* __restrict__ Out,
    __half* __restrict__ Hh, __half* __restrict__ Hl,
    int M, int N, int K)
{
    extern __shared__ __align__(1024) char smem[];
    const uint32_t sb = smem_u32(smem);
    const int tid  = threadIdx.x;
    const int wid  = tid >> 5;
    const int lane = tid & 31;
    const int m0 = blockIdx.y * 128;
    const int n0 = blockIdx.x * 256;
    const int wm = wid >> 2;       // 0..1 -> rows wm*64
    const int wn = wid & 3;        // 0..3 -> cols wn*64
    const int l8  = lane & 7;
    const int sel = lane >> 3;

    const int nstages = K / 64;
    auto stage_load = [&](int s, uint32_t dst) {
        const int k0 = s * 64;
        #pragma unroll
        for (int i = 0; i < 4; i++) {          // A: 1024 units
            int u = tid + 256 * i;
            int r = u >> 3, uk = u & 7;
            uint32_t so = SW128((uint32_t)(r * 128 + uk * 16));
            size_t ga = (size_t)(m0 + r) * K + k0 + uk * 8;
            cp16(dst + GS_AH + so, Ah + ga);
            cp16(dst + GS_AL + so, Al + ga);
        }
        #pragma unroll
        for (int i = 0; i < 8; i++) {          // B: 2048 units
            int u = tid + 256 * i;
            int r = u >> 3, uk = u & 7;
            uint32_t so = SW128((uint32_t)(r * 128 + uk * 16));
            size_t gb = (size_t)(n0 + r) * K + k0 + uk * 8;
            cp16(dst + GS_BH + so, Bh + gb);
        }
    };

    float acc[4][8][4];
    #pragma unroll
    for (int i = 0; i < 4; i++)
        #pragma unroll
        for (int j = 0; j < 8; j++)
            #pragma unroll
            for (int r = 0; r < 4; r++) acc[i][j][r] = 0.f;

    stage_load(0, sb);
    CP_COMMIT();
    stage_load(1, sb + GSTG);
    CP_COMMIT();

    for (int s = 0; s < nstages; s++) {
        const uint32_t cur = sb + (uint32_t)(s & 1) * GSTG;
        if (s + 1 < nstages) { CP_WAIT(1); } else { CP_WAIT(0); }
        __syncthreads();

        #pragma unroll
        for (int kk = 0; kk < 4; kk++) {
            uint32_t bh4[4][4];
            #pragma unroll
            for (int nt2 = 0; nt2 < 4; nt2++) {
                uint32_t row = (uint32_t)(wn * 64 + nt2 * 16 + ((sel & 2) ? 8 : 0) + l8);
                uint32_t so = SW128(row * 128 + kk * 32 + ((sel & 1) << 4));
                ldm_x4(bh4[nt2], cur + GS_BH + so);
            }
            #pragma unroll
            for (int mt = 0; mt < 4; mt++) {
                uint32_t rm = (uint32_t)(wm * 64 + mt * 16 + (lane & 15));
                uint32_t so = SW128(rm * 128 + kk * 32 + ((lane >> 4) << 4));
                uint32_t ah[4], al[4];
                ldm_x4(ah, cur + GS_AH + so);
                ldm_x4(al, cur + GS_AL + so);
                #pragma unroll
                for (int nt = 0; nt < 8; nt++) {
                    uint32_t b0 = bh4[nt >> 1][(nt & 1) * 2];
                    uint32_t b1 = bh4[nt >> 1][(nt & 1) * 2 + 1];
                    mma_f16(acc[mt][nt], ah, b0, b1);
                    mma_f16(acc[mt][nt], al, b0, b1);
                }
            }
        }
        __syncthreads();
        if (s + 2 < nstages) {
            stage_load(s + 2, cur);
            CP_COMMIT();
        }
    }

    #pragma unroll
    for (int mt = 0; mt < 4; mt++) {
        #pragma unroll
        for (int nt = 0; nt < 8; nt++) {
            int grow = m0 + wm * 64 + mt * 16 + (lane >> 2);
            int gcol = n0 + wn * 64 + nt * 8 + (lane & 3) * 2;
            float2 bb = *(const float2*)&bias[gcol];
            float v0 = acc[mt][nt][0] + bb.x, v1 = acc[mt][nt][1] + bb.y;
            float v2 = acc[mt][nt][2] + bb.x, v3 = acc[mt][nt][3] + bb.y;
            if (MODE == 1) {
                bool wantlo = (gcol < C_);   // lo residual only read for Q cols
                uint32_t h, l;
                f2h2(v0, v1, h, l);
                *(uint32_t*)&Hh[(size_t)grow * N + gcol] = h;
                if (wantlo) *(uint32_t*)&Hl[(size_t)grow * N + gcol] = l;
                f2h2(v2, v3, h, l);
                *(uint32_t*)&Hh[(size_t)(grow + 8) * N + gcol] = h;
                if (wantlo) *(uint32_t*)&Hl[(size_t)(grow + 8) * N + gcol] = l;
            } else {
                *(float2*)&Out[(size_t)grow * N + gcol] = make_float2(v0, v1);
                *(float2*)&Out[(size_t)(grow + 8) * N + gcol] = make_float2(v2, v3);
            }
        }
    }
}

// ---------------------------------------------------------------------------
// Flash attention: q-tile 256, 512 threads / 16 warps, warp owns 16 rows.
// K staged 128 at a time (two 64-wide sub-iterations per stage) -> half the
// barriers/waits. S = (Qh+Ql)Kh^T; O = P_fp16 @ Vh; log2-domain softmax.
// ---------------------------------------------------------------------------
#define AQ_H   0
#define AQ_L   32768
#define ASTG_BASE 65536
#define ASTG   32768          // per-stage: K_H(0..16K), V_H(16K..32K)
#define A_BIAS 131072         // float[2][128]
#define A_TOTAL 132096

__global__ __launch_bounds__(512) void attn_mma(
    const __half* __restrict__ qkvh, const __half* __restrict__ qkvl,
    __half* __restrict__ ch, __half* __restrict__ cl)
{
    extern __shared__ __align__(1024) char smem[];
    const uint32_t sb = smem_u32(smem);
    float (*sbias)[128] = (float(*)[128])(smem + A_BIAS);

    const int tid  = threadIdx.x;
    const int wid  = tid >> 5;
    const int lane = tid & 31;
    const int l8   = lane & 7;
    const int sel  = lane >> 3;
    const int q0 = blockIdx.x * 256;
    const int h  = blockIdx.y;
    const int b  = blockIdx.z;

    const size_t rowbase = (size_t)b * T_;
    const int* keepb = g_keep + b * T_;
    const float SC = 0.125f * 1.44269504088896f;  // (1/sqrt(D)) * log2(e)

    // Q tile: 256 rows x 64 fp16 (hi/lo); 4 units per thread
    #pragma unroll
    for (int i = 0; i < 4; i++) {
        int u = tid + 512 * i;
        int r = u >> 3, uk = u & 7;
        uint32_t so = SW128((uint32_t)(r * 128 + uk * 16));
        size_t g = (rowbase + q0 + r) * C3_ + h * D_ + uk * 8;
        cp16(sb + AQ_H + so, qkvh + g);
        cp16(sb + AQ_L + so, qkvl + g);
    }

    // KV staging: 128 rows x 8 units per tile; 2 units/thread/tile
    auto kv_load = [&](int kb2, uint32_t dst) {
        const int k0 = kb2 * 128;
        #pragma unroll
        for (int i = 0; i < 2; i++) {
            int u = tid + 512 * i;
            int r = u >> 3, uk = u & 7;
            uint32_t so = SW128((uint32_t)(r * 128 + uk * 16));
            size_t gk = (rowbase + k0 + r) * C3_ + C_ + h * D_ + uk * 8;
            size_t gv = (rowbase + k0 + r) * C3_ + 2 * C_ + h * D_ + uk * 8;
            cp16(dst + 0     + so, qkvh + gk);
            cp16(dst + 16384 + so, qkvh + gv);
        }
    };
    kv_load(0, sb + ASTG_BASE);
    CP_COMMIT();

    const int r0 = wid * 16 + (lane >> 2);
    const int r1 = r0 + 8;

    float mrow[2] = {-INFINITY, -INFINITY};
    float lrow[2] = {0.f, 0.f};
    float o[8][4];
    #pragma unroll
    for (int nt = 0; nt < 8; nt++)
        #pragma unroll
        for (int r = 0; r < 4; r++) o[nt][r] = 0.f;

    for (int kb2 = 0; kb2 < 16; kb2++) {
        const int k0 = kb2 * 128;
        const uint32_t cur = sb + ASTG_BASE + (uint32_t)(kb2 & 1) * ASTG;

        int keepv = (tid < 128) ? keepb[k0 + tid] : 0;
        CP_WAIT(0);
        if (tid < 128) sbias[kb2 & 1][tid] = keepv ? 0.f : -1e30f;
        __syncthreads();
        if (kb2 + 1 < 16) {
            kv_load(kb2 + 1, sb + ASTG_BASE + (uint32_t)((kb2 + 1) & 1) * ASTG);
            CP_COMMIT();
        }

        #pragma unroll
        for (int half = 0; half < 2; half++) {
            const uint32_t curK = cur + (uint32_t)half * 8192;
            const uint32_t curV = cur + 16384 + (uint32_t)half * 8192;
            const float* bia = sbias[kb2 & 1] + half * 64;

            // S = (Qh+Ql) @ Kh^T
            float s[8][4];
            #pragma unroll
            for (int nt = 0; nt < 8; nt++)
                #pragma unroll
                for (int r = 0; r < 4; r++) s[nt][r] = 0.f;

            #pragma unroll
            for (int kk = 0; kk < 4; kk++) {
                uint32_t rm = (uint32_t)(wid * 16 + (lane & 15));
                uint32_t soa = SW128(rm * 128 + kk * 32 + ((lane >> 4) << 4));
                uint32_t qh[4], ql[4];
                ldm_x4(qh, sb + AQ_H + soa);
                ldm_x4(ql, sb + AQ_L + soa);
                #pragma unroll
                for (int nt2 = 0; nt2 < 4; nt2++) {
                    uint32_t row = (uint32_t)(nt2 * 16 + ((sel & 2) ? 8 : 0) + l8);
                    uint32_t sob = SW128(row * 128 + kk * 32 + ((sel & 1) << 4));
                    uint32_t kh4[4];
                    ldm_x4(kh4, curK + sob);
                    mma_f16(s[2 * nt2],     qh, kh4[0], kh4[1]);
                    mma_f16(s[2 * nt2],     ql, kh4[0], kh4[1]);
                    mma_f16(s[2 * nt2 + 1], qh, kh4[2], kh4[3]);
                    mma_f16(s[2 * nt2 + 1], ql, kh4[2], kh4[3]);
                }
            }

            #pragma unroll
            for (int nt = 0; nt < 8; nt++) {
                int c = nt * 8 + (lane & 3) * 2;
                float b0 = bia[c], b1 = bia[c + 1];
                s[nt][0] = s[nt][0] * SC + b0;
                s[nt][1] = s[nt][1] * SC + b1;
                s[nt][2] = s[nt][2] * SC + b0;
                s[nt][3] = s[nt][3] * SC + b1;
            }

            float mx0 = -INFINITY, mx1 = -INFINITY;
            #pragma unroll
            for (int nt = 0; nt < 8; nt++) {
                mx0 = fmaxf(mx0, fmaxf(s[nt][0], s[nt][1]));
                mx1 = fmaxf(mx1, fmaxf(s[nt][2], s[nt][3]));
            }
            mx0 = fmaxf(mx0, __shfl_xor_sync(0xffffffffu, mx0, 1));
            mx0 = fmaxf(mx0, __shfl_xor_sync(0xffffffffu, mx0, 2));
            mx1 = fmaxf(mx1, __shfl_xor_sync(0xffffffffu, mx1, 1));
            mx1 = fmaxf(mx1, __shfl_xor_sync(0xffffffffu, mx1, 2));
            float mnew0 = fmaxf(mrow[0], mx0);
            float mnew1 = fmaxf(mrow[1], mx1);
            float corr0 = exp2f(mrow[0] - mnew0);
            float corr1 = exp2f(mrow[1] - mnew1);
            mrow[0] = mnew0; mrow[1] = mnew1;

            float sm0 = 0.f, sm1 = 0.f;
            #pragma unroll
            for (int nt = 0; nt < 8; nt++) {
                s[nt][0] = exp2f(s[nt][0] - mnew0);
                s[nt][1] = exp2f(s[nt][1] - mnew0);
                s[nt][2] = exp2f(s[nt][2] - mnew1);
                s[nt][3] = exp2f(s[nt][3] - mnew1);
                sm0 += s[nt][0] + s[nt][1];
                sm1 += s[nt][2] + s[nt][3];
            }
            sm0 += __shfl_xor_sync(0xffffffffu, sm0, 1);
            sm0 += __shfl_xor_sync(0xffffffffu, sm0, 2);
            sm1 += __shfl_xor_sync(0xffffffffu, sm1, 1);
            sm1 += __shfl_xor_sync(0xffffffffu, sm1, 2);
            lrow[0] = lrow[0] * corr0 + sm0;
            lrow[1] = lrow[1] * corr1 + sm1;
            #pragma unroll
            for (int nt = 0; nt < 8; nt++) {
                o[nt][0] *= corr0; o[nt][1] *= corr0;
                o[nt][2] *= corr1; o[nt][3] *= corr1;
            }

            // O += P @ Vh (P single fp16, from registers)
            #pragma unroll
            for (int kc = 0; kc < 4; kc++) {
                uint32_t ph[4];
                ph[0] = packh2(s[2 * kc][0],     s[2 * kc][1]);
                ph[1] = packh2(s[2 * kc][2],     s[2 * kc][3]);
                ph[2] = packh2(s[2 * kc + 1][0], s[2 * kc + 1][1]);
                ph[3] = packh2(s[2 * kc + 1][2], s[2 * kc + 1][3]);
                #pragma unroll
                for (int nt2 = 0; nt2 < 4; nt2++) {
                    uint32_t row = (uint32_t)(kc * 16 + ((sel & 1) ? 8 : 0) + l8);
                    uint32_t sov = SW128(row * 128 + nt2 * 32 + (((sel >> 1) & 1) << 4));
                    uint32_t vh4[4];
                    ldm_x4t(vh4, curV + sov);
                    mma_f16(o[2 * nt2],     ph, vh4[0], vh4[1]);
                    mma_f16(o[2 * nt2 + 1], ph, vh4[2], vh4[3]);
                }
            }
        }
    }

    float inv0 = 1.0f / lrow[0];
    float inv1 = 1.0f / lrow[1];
    #pragma unroll
    for (int nt = 0; nt < 8; nt++) {
        int c = h * D_ + nt * 8 + (lane & 3) * 2;
        size_t g0 = (rowbase + q0 + r0) * C_ + c;
        size_t g1 = (rowbase + q0 + r1) * C_ + c;
        uint32_t hh, ll;
        f2h2(o[nt][0] * inv0, o[nt][1] * inv0, hh, ll);
        *(uint32_t*)&ch[g0] = hh;
        *(uint32_t*)&cl[g0] = ll;
        f2h2(o[nt][2] * inv1, o[nt][3] * inv1, hh, ll);
        *(uint32_t*)&ch[g1] = hh;
        *(uint32_t*)&cl[g1] = ll;
    }
}

// ---------------------------------------------------------------------------
extern "C" void kernel_launch(void* const* d_in, const int* in_sizes, int n_in,
                              void* d_out, int out_size)
{
    const float* x    = (const float*)d_in[0];
    const int*   am   = (const int*)d_in[1];
    const float* Wqkv = (const float*)d_in[2];
    const float* bqkv = (const float*)d_in[3];
    const float* Wo   = (const float*)d_in[4];
    const float* bo   = (const float*)d_in[5];
    float* out = (float*)d_out;

    __half *xh, *xl, *qh, *ql, *ch, *cl, *wqh, *woh;
    cudaGetSymbolAddress((void**)&xh, g_xh);     cudaGetSymbolAddress((void**)&xl, g_xl);
    cudaGetSymbolAddress((void**)&qh, g_qkvh);   cudaGetSymbolAddress((void**)&ql, g_qkvl);
    cudaGetSymbolAddress((void**)&ch, g_ch);     cudaGetSymbolAddress((void**)&cl, g_cl);
    cudaGetSymbolAddress((void**)&wqh, g_wqh);   cudaGetSymbolAddress((void**)&woh, g_woh);

    static bool attr_done = false;
    if (!attr_done) {
        cudaFuncSetAttribute(gemm_f16x2<0>,
                             cudaFuncAttributeMaxDynamicSharedMemorySize, GS_TOTAL);
        cudaFuncSetAttribute(gemm_f16x2<1>,
                             cudaFuncAttributeMaxDynamicSharedMemorySize, GS_TOTAL);
        cudaFuncSetAttribute(attn_mma,
                             cudaFuncAttributeMaxDynamicSharedMemorySize, A_TOTAL);
        attr_done = true;
    }

    mask_norm<<<1, 1024>>>(am);
    split_rm_h<<<(BT_ * C_ + 255) / 256, 256>>>(x, xh, xl, BT_ * C_);
    split_tr_h<<<(C_ * C3_ + 255) / 256, 256>>>(Wqkv, wqh, C_, C3_);

    // 1) QKV projection -> fp16 hi/lo
    gemm_f16x2<1><<<dim3(C3_ / 256, BT_ / 128), 256, GS_TOTAL>>>(
        xh, xl, wqh, bqkv, nullptr, qh, ql, BT_, C3_, C_);

    // 2) Attention (q-tile 256, K staged 128) -> ctx fp16 hi/lo
    attn_mma<<<dim3(T_ / 256, H_, B_), 512, A_TOTAL>>>(qh, ql, ch, cl);

    // 3) Output projection -> fp32
    split_tr_h<<<(C_ * C_ + 255) / 256, 256>>>(Wo, woh, C_, C_);
    gemm_f16x2<0><<<dim3(C_ / 256, BT_ / 128), 256, GS_TOTAL>>>(
        ch, cl, woh, bo, out, nullptr, nullptr, BT_, C_, C_);
}

// round 12
// speedup vs baseline: 5.4445x; 1.1829x over previous
#include <cuda_runtime.h>
#include <cuda_bf16.h>
#include <cuda_fp16.h>
#include <math.h>
#include <stdint.h>

#define B_ 4
#define T_ 2048
#define C_ 768
#define H_ 12
#define D_ 64
#define BT_ (B_ * T_)
#define C3_ (3 * C_)

// ---------------------------------------------------------------------------
// Device scratch (no runtime allocation allowed)
// ---------------------------------------------------------------------------
__device__ int g_keep[BT_];

__device__ __half g_xh[(size_t)BT_ * C_],    g_xl[(size_t)BT_ * C_];
__device__ __half g_qkvh[(size_t)BT_ * C3_];
__device__ __half g_ch[(size_t)BT_ * C_],    g_cl[(size_t)BT_ * C_];
__device__ __half g_wqh[(size_t)C3_ * C_];   // Wqkv^T hi only
__device__ __half g_woh[(size_t)C_ * C_];    // Wo^T   hi only

// ---------------------------------------------------------------------------
// PTX helpers
// ---------------------------------------------------------------------------
__device__ __forceinline__ uint32_t smem_u32(const void* p) {
    uint32_t a;
    asm("{ .reg .u64 t; cvta.to.shared.u64 t, %1; cvt.u32.u64 %0, t; }"
        : "=r"(a) : "l"(p));
    return a;
}
__device__ __forceinline__ void ldm_x4(uint32_t (&r)[4], uint32_t addr) {
    asm volatile("ldmatrix.sync.aligned.m8n8.x4.shared.b16 {%0,%1,%2,%3}, [%4];"
        : "=r"(r[0]), "=r"(r[1]), "=r"(r[2]), "=r"(r[3]) : "r"(addr));
}
__device__ __forceinline__ void ldm_x4t(uint32_t (&r)[4], uint32_t addr) {
    asm volatile("ldmatrix.sync.aligned.m8n8.x4.trans.shared.b16 {%0,%1,%2,%3}, [%4];"
        : "=r"(r[0]), "=r"(r[1]), "=r"(r[2]), "=r"(r[3]) : "r"(addr));
}
__device__ __forceinline__ void mma_f16(float (&d)[4], const uint32_t (&a)[4],
                                        uint32_t b0, uint32_t b1) {
    asm volatile(
        "mma.sync.aligned.m16n8k16.row.col.f32.f16.f16.f32 "
        "{%0,%1,%2,%3}, {%4,%5,%6,%7}, {%8,%9}, {%0,%1,%2,%3};"
        : "+f"(d[0]), "+f"(d[1]), "+f"(d[2]), "+f"(d[3])
        : "r"(a[0]), "r"(a[1]), "r"(a[2]), "r"(a[3]), "r"(b0), "r"(b1));
}
__device__ __forceinline__ void cp16(uint32_t saddr, const void* g) {
    asm volatile("cp.async.cg.shared.global [%0], [%1], 16;"
        :: "r"(saddr), "l"(g));
}
#define CP_COMMIT() asm volatile("cp.async.commit_group;" ::: "memory")
#define CP_WAIT(n)  asm volatile("cp.async.wait_group %0;" :: "n"(n) : "memory")
#define SW128(o) ((o) ^ (((o) >> 3) & 0x70))

__device__ __forceinline__ void f2h2(float a, float b, uint32_t& h, uint32_t& l) {
    __half ha = __float2half_rn(a), hb = __float2half_rn(b);
    __half2 hh = __halves2half2(ha, hb);
    __half2 ll = __halves2half2(__float2half_rn(a - __half2float(ha)),
                                __float2half_rn(b - __half2float(hb)));
    h = *(uint32_t*)&hh;
    l = *(uint32_t*)&ll;
}
__device__ __forceinline__ uint32_t packh2(float a, float b) {
    __half2 hh = __floats2half2_rn(a, b);
    return *(uint32_t*)&hh;
}

// ---------------------------------------------------------------------------
__global__ __launch_bounds__(1024) void mask_norm(const int* __restrict__ amw)
{
    const int tid = threadIdx.x;
    int allzero = 1;
    for (int i = tid; i < BT_; i += 1024)
        if (i & 1) allzero &= (amw[i] == 0);
    int is64 = __syncthreads_and(allzero);
    for (int i = tid; i < BT_; i += 1024) {
        int v = is64 ? amw[2 * i] : amw[i];
        g_keep[i] = (v == 0) ? 1 : 0;
    }
}

__global__ __launch_bounds__(256) void split_rm_h(
    const float* __restrict__ in, __half* __restrict__ hi,
    __half* __restrict__ lo, int n)
{
    int i = blockIdx.x * 256 + threadIdx.x;
    if (i >= n) return;
    float x = in[i];
    __half h = __float2half_rn(x);
    hi[i] = h;
    lo[i] = __float2half_rn(x - __half2float(h));
}

// Tiled transpose: fp32 W[K][N] -> fp16 Wt[N][K], coalesced both sides.
__global__ __launch_bounds__(256) void split_tr_h(
    const float* __restrict__ in, __half* __restrict__ out, int K, int N)
{
    __shared__ __half tile[32][34];
    const int k0 = blockIdx.y * 32;
    const int n0 = blockIdx.x * 32;
    #pragma unroll
    for (int p = 0; p < 4; p++) {
        int idx = threadIdx.x + 256 * p;
        int kk = idx >> 5, nn = idx & 31;
        tile[nn][kk] = __float2half_rn(in[(size_t)(k0 + kk) * N + n0 + nn]);
    }
    __syncthreads();
    #pragma unroll
    for (int p = 0; p < 4; p++) {
        int idx = threadIdx.x + 256 * p;
        int nn = idx >> 5, kk = idx & 31;
        out[(size_t)(n0 + nn) * K + k0 + kk] = tile[nn][kk];
    }
}

// ---------------------------------------------------------------------------
// fp16 2-term HMMA GEMM: Out = (Ah+Al)[M][K] @ (Bh[N][K])^T + bias
// CTA 128x256, 8 warps (2x4), warp tile 64x64. 2-stage cp.async pipeline.
// MODE 0: fp32 Out.  MODE 1: fp16 hi only (Hh).
// ---------------------------------------------------------------------------
#define GS_AH 0
#define GS_AL 16384
#define GS_BH 32768
#define GSTG  65536
#define GS_TOTAL (2 * GSTG)

template <int MODE>
__global__ __launch_bounds__(256) void gemm_f16x2(
    const __half* __restrict__ Ah, const __half* __restrict__ Al,
    const __half* __restrict__ Bh,
    const float* __restrict__ bias, float* __restrict__ Out,
    __half* __restrict__ Hh,
    int M, int N, int K)
{
    extern __shared__ __align__(1024) char smem[];
    const uint32_t sb = smem_u32(smem);
    const int tid  = threadIdx.x;
    const int wid  = tid >> 5;
    const int lane = tid & 31;
    const int m0 = blockIdx.y * 128;
    const int n0 = blockIdx.x * 256;
    const int wm = wid >> 2;
    const int wn = wid & 3;
    const int l8  = lane & 7;
    const int sel = lane >> 3;

    const int nstages = K / 64;
    auto stage_load = [&](int s, uint32_t dst) {
        const int k0 = s * 64;
        #pragma unroll
        for (int i = 0; i < 4; i++) {          // A: 1024 units
            int u = tid + 256 * i;
            int r = u >> 3, uk = u & 7;
            uint32_t so = SW128((uint32_t)(r * 128 + uk * 16));
            size_t ga = (size_t)(m0 + r) * K + k0 + uk * 8;
            cp16(dst + GS_AH + so, Ah + ga);
            cp16(dst + GS_AL + so, Al + ga);
        }
        #pragma unroll
        for (int i = 0; i < 8; i++) {          // B: 2048 units
            int u = tid + 256 * i;
            int r = u >> 3, uk = u & 7;
            uint32_t so = SW128((uint32_t)(r * 128 + uk * 16));
            size_t gb = (size_t)(n0 + r) * K + k0 + uk * 8;
            cp16(dst + GS_BH + so, Bh + gb);
        }
    };

    float acc[4][8][4];
    #pragma unroll
    for (int i = 0; i < 4; i++)
        #pragma unroll
        for (int j = 0; j < 8; j++)
            #pragma unroll
            for (int r = 0; r < 4; r++) acc[i][j][r] = 0.f;

    stage_load(0, sb);
    CP_COMMIT();
    stage_load(1, sb + GSTG);
    CP_COMMIT();

    for (int s = 0; s < nstages; s++) {
        const uint32_t cur = sb + (uint32_t)(s & 1) * GSTG;
        if (s + 1 < nstages) { CP_WAIT(1); } else { CP_WAIT(0); }
        __syncthreads();

        #pragma unroll
        for (int kk = 0; kk < 4; kk++) {
            uint32_t bh4[4][4];
            #pragma unroll
            for (int nt2 = 0; nt2 < 4; nt2++) {
                uint32_t row = (uint32_t)(wn * 64 + nt2 * 16 + ((sel & 2) ? 8 : 0) + l8);
                uint32_t so = SW128(row * 128 + kk * 32 + ((sel & 1) << 4));
                ldm_x4(bh4[nt2], cur + GS_BH + so);
            }
            #pragma unroll
            for (int mt = 0; mt < 4; mt++) {
                uint32_t rm = (uint32_t)(wm * 64 + mt * 16 + (lane & 15));
                uint32_t so = SW128(rm * 128 + kk * 32 + ((lane >> 4) << 4));
                uint32_t ah[4], al[4];
                ldm_x4(ah, cur + GS_AH + so);
                ldm_x4(al, cur + GS_AL + so);
                #pragma unroll
                for (int nt = 0; nt < 8; nt++) {
                    uint32_t b0 = bh4[nt >> 1][(nt & 1) * 2];
                    uint32_t b1 = bh4[nt >> 1][(nt & 1) * 2 + 1];
                    mma_f16(acc[mt][nt], ah, b0, b1);
                    mma_f16(acc[mt][nt], al, b0, b1);
                }
            }
        }
        __syncthreads();
        if (s + 2 < nstages) {
            stage_load(s + 2, cur);
            CP_COMMIT();
        }
    }

    #pragma unroll
    for (int mt = 0; mt < 4; mt++) {
        #pragma unroll
        for (int nt = 0; nt < 8; nt++) {
            int grow = m0 + wm * 64 + mt * 16 + (lane >> 2);
            int gcol = n0 + wn * 64 + nt * 8 + (lane & 3) * 2;
            float2 bb = *(const float2*)&bias[gcol];
            float v0 = acc[mt][nt][0] + bb.x, v1 = acc[mt][nt][1] + bb.y;
            float v2 = acc[mt][nt][2] + bb.x, v3 = acc[mt][nt][3] + bb.y;
            if (MODE == 1) {
                *(uint32_t*)&Hh[(size_t)grow * N + gcol] = packh2(v0, v1);
                *(uint32_t*)&Hh[(size_t)(grow + 8) * N + gcol] = packh2(v2, v3);
            } else {
                *(float2*)&Out[(size_t)grow * N + gcol] = make_float2(v0, v1);
                *(float2*)&Out[(size_t)(grow + 8) * N + gcol] = make_float2(v2, v3);
            }
        }
    }
}

// ---------------------------------------------------------------------------
// Flash attention: q-tile 256, 512 threads / 16 warps, warp owns 16 rows.
// fp16 single-term: S = Qh Kh^T;  O = P_fp16 @ Vh. Log2-domain softmax.
// K staged 128 at a time, two 64-wide sub-iterations per stage.
// ---------------------------------------------------------------------------
#define AQ_H   0
#define ASTG_BASE 32768
#define ASTG   32768          // per-stage: K_H(0..16K), V_H(16K..32K)
#define A_BIAS 98304          // float[2][128]
#define A_TOTAL 99328

__global__ __launch_bounds__(512) void attn_mma(
    const __half* __restrict__ qkvh,
    __half* __restrict__ ch, __half* __restrict__ cl)
{
    extern __shared__ __align__(1024) char smem[];
    const uint32_t sb = smem_u32(smem);
    float (*sbias)[128] = (float(*)[128])(smem + A_BIAS);

    const int tid  = threadIdx.x;
    const int wid  = tid >> 5;
    const int lane = tid & 31;
    const int l8   = lane & 7;
    const int sel  = lane >> 3;
    const int q0 = blockIdx.x * 256;
    const int h  = blockIdx.y;
    const int b  = blockIdx.z;

    const size_t rowbase = (size_t)b * T_;
    const int* keepb = g_keep + b * T_;
    const float SC = 0.125f * 1.44269504088896f;  // (1/sqrt(D)) * log2(e)

    // Q tile: 256 rows x 64 fp16 (hi only); 4 units per thread
    #pragma unroll
    for (int i = 0; i < 4; i++) {
        int u = tid + 512 * i;
        int r = u >> 3, uk = u & 7;
        uint32_t so = SW128((uint32_t)(r * 128 + uk * 16));
        size_t g = (rowbase + q0 + r) * C3_ + h * D_ + uk * 8;
        cp16(sb + AQ_H + so, qkvh + g);
    }

    // KV staging: 128 rows x 8 units per tile; 2 units/thread/tile
    auto kv_load = [&](int kb2, uint32_t dst) {
        const int k0 = kb2 * 128;
        #pragma unroll
        for (int i = 0; i < 2; i++) {
            int u = tid + 512 * i;
            int r = u >> 3, uk = u & 7;
            uint32_t so = SW128((uint32_t)(r * 128 + uk * 16));
            size_t gk = (rowbase + k0 + r) * C3_ + C_ + h * D_ + uk * 8;
            size_t gv = (rowbase + k0 + r) * C3_ + 2 * C_ + h * D_ + uk * 8;
            cp16(dst + 0     + so, qkvh + gk);
            cp16(dst + 16384 + so, qkvh + gv);
        }
    };
    kv_load(0, sb + ASTG_BASE);
    CP_COMMIT();

    const int r0 = wid * 16 + (lane >> 2);
    const int r1 = r0 + 8;

    float mrow[2] = {-INFINITY, -INFINITY};
    float lrow[2] = {0.f, 0.f};
    float o[8][4];
    #pragma unroll
    for (int nt = 0; nt < 8; nt++)
        #pragma unroll
        for (int r = 0; r < 4; r++) o[nt][r] = 0.f;

    for (int kb2 = 0; kb2 < 16; kb2++) {
        const int k0 = kb2 * 128;
        const uint32_t cur = sb + ASTG_BASE + (uint32_t)(kb2 & 1) * ASTG;

        int keepv = (tid < 128) ? keepb[k0 + tid] : 0;
        CP_WAIT(0);
        if (tid < 128) sbias[kb2 & 1][tid] = keepv ? 0.f : -1e30f;
        __syncthreads();
        if (kb2 + 1 < 16) {
            kv_load(kb2 + 1, sb + ASTG_BASE + (uint32_t)((kb2 + 1) & 1) * ASTG);
            CP_COMMIT();
        }

        #pragma unroll
        for (int half = 0; half < 2; half++) {
            const uint32_t curK = cur + (uint32_t)half * 8192;
            const uint32_t curV = cur + 16384 + (uint32_t)half * 8192;
            const float* bia = sbias[kb2 & 1] + half * 64;

            // S = Qh @ Kh^T (single term)
            float s[8][4];
            #pragma unroll
            for (int nt = 0; nt < 8; nt++)
                #pragma unroll
                for (int r = 0; r < 4; r++) s[nt][r] = 0.f;

            #pragma unroll
            for (int kk = 0; kk < 4; kk++) {
                uint32_t rm = (uint32_t)(wid * 16 + (lane & 15));
                uint32_t soa = SW128(rm * 128 + kk * 32 + ((lane >> 4) << 4));
                uint32_t qh[4];
                ldm_x4(qh, sb + AQ_H + soa);
                #pragma unroll
                for (int nt2 = 0; nt2 < 4; nt2++) {
                    uint32_t row = (uint32_t)(nt2 * 16 + ((sel & 2) ? 8 : 0) + l8);
                    uint32_t sob = SW128(row * 128 + kk * 32 + ((sel & 1) << 4));
                    uint32_t kh4[4];
                    ldm_x4(kh4, curK + sob);
                    mma_f16(s[2 * nt2],     qh, kh4[0], kh4[1]);
                    mma_f16(s[2 * nt2 + 1], qh, kh4[2], kh4[3]);
                }
            }

            #pragma unroll
            for (int nt = 0; nt < 8; nt++) {
                int c = nt * 8 + (lane & 3) * 2;
                float b0 = bia[c], b1 = bia[c + 1];
                s[nt][0] = s[nt][0] * SC + b0;
                s[nt][1] = s[nt][1] * SC + b1;
                s[nt][2] = s[nt][2] * SC + b0;
                s[nt][3] = s[nt][3] * SC + b1;
            }

            float mx0 = -INFINITY, mx1 = -INFINITY;
            #pragma unroll
            for (int nt = 0; nt < 8; nt++) {
                mx0 = fmaxf(mx0, fmaxf(s[nt][0], s[nt][1]));
                mx1 = fmaxf(mx1, fmaxf(s[nt][2], s[nt][3]));
            }
            mx0 = fmaxf(mx0, __shfl_xor_sync(0xffffffffu, mx0, 1));
            mx0 = fmaxf(mx0, __shfl_xor_sync(0xffffffffu, mx0, 2));
            mx1 = fmaxf(mx1, __shfl_xor_sync(0xffffffffu, mx1, 1));
            mx1 = fmaxf(mx1, __shfl_xor_sync(0xffffffffu, mx1, 2));
            float mnew0 = fmaxf(mrow[0], mx0);
            float mnew1 = fmaxf(mrow[1], mx1);
            float corr0 = exp2f(mrow[0] - mnew0);
            float corr1 = exp2f(mrow[1] - mnew1);
            mrow[0] = mnew0; mrow[1] = mnew1;

            float sm0 = 0.f, sm1 = 0.f;
            #pragma unroll
            for (int nt = 0; nt < 8; nt++) {
                s[nt][0] = exp2f(s[nt][0] - mnew0);
                s[nt][1] = exp2f(s[nt][1] - mnew0);
                s[nt][2] = exp2f(s[nt][2] - mnew1);
                s[nt][3] = exp2f(s[nt][3] - mnew1);
                sm0 += s[nt][0] + s[nt][1];
                sm1 += s[nt][2] + s[nt][3];
            }
            sm0 += __shfl_xor_sync(0xffffffffu, sm0, 1);
            sm0 += __shfl_xor_sync(0xffffffffu, sm0, 2);
            sm1 += __shfl_xor_sync(0xffffffffu, sm1, 1);
            sm1 += __shfl_xor_sync(0xffffffffu, sm1, 2);
            lrow[0] = lrow[0] * corr0 + sm0;
            lrow[1] = lrow[1] * corr1 + sm1;
            #pragma unroll
            for (int nt = 0; nt < 8; nt++) {
                o[nt][0] *= corr0; o[nt][1] *= corr0;
                o[nt][2] *= corr1; o[nt][3] *= corr1;
            }

            // O += P @ Vh (P single fp16, from registers)
            #pragma unroll
            for (int kc = 0; kc < 4; kc++) {
                uint32_t ph[4];
                ph[0] = packh2(s[2 * kc][0],     s[2 * kc][1]);
                ph[1] = packh2(s[2 * kc][2],     s[2 * kc][3]);
                ph[2] = packh2(s[2 * kc + 1][0], s[2 * kc + 1][1]);
                ph[3] = packh2(s[2 * kc + 1][2], s[2 * kc + 1][3]);
                #pragma unroll
                for (int nt2 = 0; nt2 < 4; nt2++) {
                    uint32_t row = (uint32_t)(kc * 16 + ((sel & 1) ? 8 : 0) + l8);
                    uint32_t sov = SW128(row * 128 + nt2 * 32 + (((sel >> 1) & 1) << 4));
                    uint32_t vh4[4];
                    ldm_x4t(vh4, curV + sov);
                    mma_f16(o[2 * nt2],     ph, vh4[0], vh4[1]);
                    mma_f16(o[2 * nt2 + 1], ph, vh4[2], vh4[3]);
                }
            }
        }
    }

    float inv0 = 1.0f / lrow[0];
    float inv1 = 1.0f / lrow[1];
    #pragma unroll
    for (int nt = 0; nt < 8; nt++) {
        int c = h * D_ + nt * 8 + (lane & 3) * 2;
        size_t g0 = (rowbase + q0 + r0) * C_ + c;
        size_t g1 = (rowbase + q0 + r1) * C_ + c;
        uint32_t hh, ll;
        f2h2(o[nt][0] * inv0, o[nt][1] * inv0, hh, ll);
        *(uint32_t*)&ch[g0] = hh;
        *(uint32_t*)&cl[g0] = ll;
        f2h2(o[nt][2] * inv1, o[nt][3] * inv1, hh, ll);
        *(uint32_t*)&ch[g1] = hh;
        *(uint32_t*)&cl[g1] = ll;
    }
}

// ---------------------------------------------------------------------------
extern "C" void kernel_launch(void* const* d_in, const int* in_sizes, int n_in,
                              void* d_out, int out_size)
{
    const float* x    = (const float*)d_in[0];
    const int*   am   = (const int*)d_in[1];
    const float* Wqkv = (const float*)d_in[2];
    const float* bqkv = (const float*)d_in[3];
    const float* Wo   = (const float*)d_in[4];
    const float* bo   = (const float*)d_in[5];
    float* out = (float*)d_out;

    __half *xh, *xl, *qh, *ch, *cl, *wqh, *woh;
    cudaGetSymbolAddress((void**)&xh, g_xh);     cudaGetSymbolAddress((void**)&xl, g_xl);
    cudaGetSymbolAddress((void**)&qh, g_qkvh);
    cudaGetSymbolAddress((void**)&ch, g_ch);     cudaGetSymbolAddress((void**)&cl, g_cl);
    cudaGetSymbolAddress((void**)&wqh, g_wqh);   cudaGetSymbolAddress((void**)&woh, g_woh);

    static bool attr_done = false;
    if (!attr_done) {
        cudaFuncSetAttribute(gemm_f16x2<0>,
                             cudaFuncAttributeMaxDynamicSharedMemorySize, GS_TOTAL);
        cudaFuncSetAttribute(gemm_f16x2<1>,
                             cudaFuncAttributeMaxDynamicSharedMemorySize, GS_TOTAL);
        cudaFuncSetAttribute(attn_mma,
                             cudaFuncAttributeMaxDynamicSharedMemorySize, A_TOTAL);
        attr_done = true;
    }

    mask_norm<<<1, 1024>>>(am);
    split_rm_h<<<(BT_ * C_ + 255) / 256, 256>>>(x, xh, xl, BT_ * C_);
    split_tr_h<<<dim3(C3_ / 32, C_ / 32), 256>>>(Wqkv, wqh, C_, C3_);

    // 1) QKV projection -> fp16 hi
    gemm_f16x2<1><<<dim3(C3_ / 256, BT_ / 128), 256, GS_TOTAL>>>(
        xh, xl, wqh, bqkv, nullptr, qh, BT_, C3_, C_);

    // 2) Attention (q-tile 256, K staged 128) -> ctx fp16 hi/lo
    attn_mma<<<dim3(T_ / 256, H_, B_), 512, A_TOTAL>>>(qh, ch, cl);

    // 3) Output projection -> fp32
    split_tr_h<<<dim3(C_ / 32, C_ / 32), 256>>>(Wo, woh, C_, C_);
    gemm_f16x2<0><<<dim3(C_ / 256, BT_ / 128), 256, GS_TOTAL>>>(
        ch, cl, woh, bo, out, nullptr, BT_, C_, C_);
}

// round 13
// speedup vs baseline: 6.9227x; 1.2715x over previous
#include <cuda_runtime.h>
#include <cuda_bf16.h>
#include <cuda_fp16.h>
#include <math.h>
#include <stdint.h>

#define B_ 4
#define T_ 2048
#define C_ 768
#define H_ 12
#define D_ 64
#define BT_ (B_ * T_)
#define C3_ (3 * C_)

// ---------------------------------------------------------------------------
// Device scratch (no runtime allocation allowed)
// ---------------------------------------------------------------------------
__device__ int g_keep[BT_];

__device__ __half g_xh[(size_t)BT_ * C_];
__device__ __half g_qkvh[(size_t)BT_ * C3_];
__device__ __half g_ch[(size_t)BT_ * C_];
__device__ __half g_wqh[(size_t)C3_ * C_];   // Wqkv^T hi
__device__ __half g_woh[(size_t)C_ * C_];    // Wo^T   hi

// ---------------------------------------------------------------------------
// PTX helpers
// ---------------------------------------------------------------------------
__device__ __forceinline__ uint32_t smem_u32(const void* p) {
    uint32_t a;
    asm("{ .reg .u64 t; cvta.to.shared.u64 t, %1; cvt.u32.u64 %0, t; }"
        : "=r"(a) : "l"(p));
    return a;
}
__device__ __forceinline__ void ldm_x4(uint32_t (&r)[4], uint32_t addr) {
    asm volatile("ldmatrix.sync.aligned.m8n8.x4.shared.b16 {%0,%1,%2,%3}, [%4];"
        : "=r"(r[0]), "=r"(r[1]), "=r"(r[2]), "=r"(r[3]) : "r"(addr));
}
__device__ __forceinline__ void ldm_x4t(uint32_t (&r)[4], uint32_t addr) {
    asm volatile("ldmatrix.sync.aligned.m8n8.x4.trans.shared.b16 {%0,%1,%2,%3}, [%4];"
        : "=r"(r[0]), "=r"(r[1]), "=r"(r[2]), "=r"(r[3]) : "r"(addr));
}
__device__ __forceinline__ void mma_f16(float (&d)[4], const uint32_t (&a)[4],
                                        uint32_t b0, uint32_t b1) {
    asm volatile(
        "mma.sync.aligned.m16n8k16.row.col.f32.f16.f16.f32 "
        "{%0,%1,%2,%3}, {%4,%5,%6,%7}, {%8,%9}, {%0,%1,%2,%3};"
        : "+f"(d[0]), "+f"(d[1]), "+f"(d[2]), "+f"(d[3])
        : "r"(a[0]), "r"(a[1]), "r"(a[2]), "r"(a[3]), "r"(b0), "r"(b1));
}
__device__ __forceinline__ void cp16(uint32_t saddr, const void* g) {
    asm volatile("cp.async.cg.shared.global [%0], [%1], 16;"
        :: "r"(saddr), "l"(g));
}
#define CP_COMMIT() asm volatile("cp.async.commit_group;" ::: "memory")
#define CP_WAIT(n)  asm volatile("cp.async.wait_group %0;" :: "n"(n) : "memory")
#define SW128(o) ((o) ^ (((o) >> 3) & 0x70))

__device__ __forceinline__ uint32_t packh2(float a, float b) {
    __half2 hh = __floats2half2_rn(a, b);
    return *(uint32_t*)&hh;
}

// ---------------------------------------------------------------------------
__global__ __launch_bounds__(1024) void mask_norm(const int* __restrict__ amw)
{
    const int tid = threadIdx.x;
    int allzero = 1;
    for (int i = tid; i < BT_; i += 1024)
        if (i & 1) allzero &= (amw[i] == 0);
    int is64 = __syncthreads_and(allzero);
    for (int i = tid; i < BT_; i += 1024) {
        int v = is64 ? amw[2 * i] : amw[i];
        g_keep[i] = (v == 0) ? 1 : 0;
    }
}

// fp32 -> fp16 convert (hi only), vectorized
__global__ __launch_bounds__(256) void conv_h(
    const float* __restrict__ in, __half* __restrict__ hi, int n4)
{
    int i = blockIdx.x * 256 + threadIdx.x;
    if (i >= n4) return;
    float4 v = *(const float4*)(in + 4 * (size_t)i);
    uint32_t p0 = packh2(v.x, v.y);
    uint32_t p1 = packh2(v.z, v.w);
    uint2 o = make_uint2(p0, p1);
    *(uint2*)(hi + 4 * (size_t)i) = o;
}

// Tiled transpose: fp32 W[K][N] -> fp16 Wt[N][K], coalesced both sides.
__global__ __launch_bounds__(256) void split_tr_h(
    const float* __restrict__ in, __half* __restrict__ out, int K, int N)
{
    __shared__ __half tile[32][34];
    const int k0 = blockIdx.y * 32;
    const int n0 = blockIdx.x * 32;
    #pragma unroll
    for (int p = 0; p < 4; p++) {
        int idx = threadIdx.x + 256 * p;
        int kk = idx >> 5, nn = idx & 31;
        tile[nn][kk] = __float2half_rn(in[(size_t)(k0 + kk) * N + n0 + nn]);
    }
    __syncthreads();
    #pragma unroll
    for (int p = 0; p < 4; p++) {
        int idx = threadIdx.x + 256 * p;
        int nn = idx >> 5, kk = idx & 31;
        out[(size_t)(n0 + nn) * K + k0 + kk] = tile[nn][kk];
    }
}

// ---------------------------------------------------------------------------
// fp16 single-term HMMA GEMM: Out = Ah[M][K] @ (Bh[N][K])^T + bias
// CTA 128x256, 8 warps (2x4), warp tile 64x64. 2-stage cp.async pipeline.
// MODE 0: fp32 Out.  MODE 1: fp16 (Hh).
// ---------------------------------------------------------------------------
#define GS_A  0
#define GS_B  16384
#define GSTG  49152
#define GS_TOTAL (2 * GSTG)

template <int MODE>
__global__ __launch_bounds__(256) void gemm_f16(
    const __half* __restrict__ Ah, const __half* __restrict__ Bh,
    const float* __restrict__ bias, float* __restrict__ Out,
    __half* __restrict__ Hh,
    int M, int N, int K)
{
    extern __shared__ __align__(1024) char smem[];
    const uint32_t sb = smem_u32(smem);
    const int tid  = threadIdx.x;
    const int wid  = tid >> 5;
    const int lane = tid & 31;
    const int m0 = blockIdx.y * 128;
    const int n0 = blockIdx.x * 256;
    const int wm = wid >> 2;
    const int wn = wid & 3;
    const int l8  = lane & 7;
    const int sel = lane >> 3;

    const int nstages = K / 64;
    auto stage_load = [&](int s, uint32_t dst) {
        const int k0 = s * 64;
        #pragma unroll
        for (int i = 0; i < 4; i++) {          // A: 1024 units
            int u = tid + 256 * i;
            int r = u >> 3, uk = u & 7;
            uint32_t so = SW128((uint32_t)(r * 128 + uk * 16));
            cp16(dst + GS_A + so, Ah + (size_t)(m0 + r) * K + k0 + uk * 8);
        }
        #pragma unroll
        for (int i = 0; i < 8; i++) {          // B: 2048 units
            int u = tid + 256 * i;
            int r = u >> 3, uk = u & 7;
            uint32_t so = SW128((uint32_t)(r * 128 + uk * 16));
            cp16(dst + GS_B + so, Bh + (size_t)(n0 + r) * K + k0 + uk * 8);
        }
    };

    float acc[4][8][4];
    #pragma unroll
    for (int i = 0; i < 4; i++)
        #pragma unroll
        for (int j = 0; j < 8; j++)
            #pragma unroll
            for (int r = 0; r < 4; r++) acc[i][j][r] = 0.f;

    stage_load(0, sb);
    CP_COMMIT();
    stage_load(1, sb + GSTG);
    CP_COMMIT();

    for (int s = 0; s < nstages; s++) {
        const uint32_t cur = sb + (uint32_t)(s & 1) * GSTG;
        if (s + 1 < nstages) { CP_WAIT(1); } else { CP_WAIT(0); }
        __syncthreads();

        #pragma unroll
        for (int kk = 0; kk < 4; kk++) {
            uint32_t bh4[4][4];
            #pragma unroll
            for (int nt2 = 0; nt2 < 4; nt2++) {
                uint32_t row = (uint32_t)(wn * 64 + nt2 * 16 + ((sel & 2) ? 8 : 0) + l8);
                uint32_t so = SW128(row * 128 + kk * 32 + ((sel & 1) << 4));
                ldm_x4(bh4[nt2], cur + GS_B + so);
            }
            #pragma unroll
            for (int mt = 0; mt < 4; mt++) {
                uint32_t rm = (uint32_t)(wm * 64 + mt * 16 + (lane & 15));
                uint32_t so = SW128(rm * 128 + kk * 32 + ((lane >> 4) << 4));
                uint32_t ah[4];
                ldm_x4(ah, cur + GS_A + so);
                #pragma unroll
                for (int nt = 0; nt < 8; nt++) {
                    mma_f16(acc[mt][nt], ah,
                            bh4[nt >> 1][(nt & 1) * 2], bh4[nt >> 1][(nt & 1) * 2 + 1]);
                }
            }
        }
        __syncthreads();
        if (s + 2 < nstages) {
            stage_load(s + 2, cur);
            CP_COMMIT();
        }
    }

    #pragma unroll
    for (int mt = 0; mt < 4; mt++) {
        #pragma unroll
        for (int nt = 0; nt < 8; nt++) {
            int grow = m0 + wm * 64 + mt * 16 + (lane >> 2);
            int gcol = n0 + wn * 64 + nt * 8 + (lane & 3) * 2;
            float2 bb = *(const float2*)&bias[gcol];
            float v0 = acc[mt][nt][0] + bb.x, v1 = acc[mt][nt][1] + bb.y;
            float v2 = acc[mt][nt][2] + bb.x, v3 = acc[mt][nt][3] + bb.y;
            if (MODE == 1) {
                *(uint32_t*)&Hh[(size_t)grow * N + gcol] = packh2(v0, v1);
                *(uint32_t*)&Hh[(size_t)(grow + 8) * N + gcol] = packh2(v2, v3);
            } else {
                *(float2*)&Out[(size_t)grow * N + gcol] = make_float2(v0, v1);
                *(float2*)&Out[(size_t)(grow + 8) * N + gcol] = make_float2(v2, v3);
            }
        }
    }
}

// ---------------------------------------------------------------------------
// Flash attention: q-tile 256, 512 threads / 16 warps, warp owns 16 rows.
// fp16 single-term S = Qh Kh^T, O = P_fp16 @ Vh, log2-domain softmax.
// K staged 128 at a time, two 64-wide sub-iterations per stage.
// ---------------------------------------------------------------------------
#define AQ_H   0
#define ASTG_BASE 32768
#define ASTG   32768          // per-stage: K_H(0..16K), V_H(16K..32K)
#define A_BIAS 98304          // float[2][128]
#define A_TOTAL 99328

__global__ __launch_bounds__(512) void attn_mma(
    const __half* __restrict__ qkvh, __half* __restrict__ ch)
{
    extern __shared__ __align__(1024) char smem[];
    const uint32_t sb = smem_u32(smem);
    float (*sbias)[128] = (float(*)[128])(smem + A_BIAS);

    const int tid  = threadIdx.x;
    const int wid  = tid >> 5;
    const int lane = tid & 31;
    const int l8   = lane & 7;
    const int sel  = lane >> 3;
    const int q0 = blockIdx.x * 256;
    const int h  = blockIdx.y;
    const int b  = blockIdx.z;

    const size_t rowbase = (size_t)b * T_;
    const int* keepb = g_keep + b * T_;
    const float SC = 0.125f * 1.44269504088896f;  // (1/sqrt(D)) * log2(e)

    // Q tile: 256 rows x 64 fp16; 4 units per thread
    #pragma unroll
    for (int i = 0; i < 4; i++) {
        int u = tid + 512 * i;
        int r = u >> 3, uk = u & 7;
        uint32_t so = SW128((uint32_t)(r * 128 + uk * 16));
        cp16(sb + AQ_H + so, qkvh + (rowbase + q0 + r) * C3_ + h * D_ + uk * 8);
    }

    auto kv_load = [&](int kb2, uint32_t dst) {
        const int k0 = kb2 * 128;
        #pragma unroll
        for (int i = 0; i < 2; i++) {
            int u = tid + 512 * i;
            int r = u >> 3, uk = u & 7;
            uint32_t so = SW128((uint32_t)(r * 128 + uk * 16));
            size_t gk = (rowbase + k0 + r) * C3_ + C_ + h * D_ + uk * 8;
            size_t gv = (rowbase + k0 + r) * C3_ + 2 * C_ + h * D_ + uk * 8;
            cp16(dst + 0     + so, qkvh + gk);
            cp16(dst + 16384 + so, qkvh + gv);
        }
    };
    kv_load(0, sb + ASTG_BASE);
    CP_COMMIT();

    const int r0 = wid * 16 + (lane >> 2);
    const int r1 = r0 + 8;

    float mrow[2] = {-INFINITY, -INFINITY};
    float lrow[2] = {0.f, 0.f};
    float o[8][4];
    #pragma unroll
    for (int nt = 0; nt < 8; nt++)
        #pragma unroll
        for (int r = 0; r < 4; r++) o[nt][r] = 0.f;

    for (int kb2 = 0; kb2 < 16; kb2++) {
        const int k0 = kb2 * 128;
        const uint32_t cur = sb + ASTG_BASE + (uint32_t)(kb2 & 1) * ASTG;

        int keepv = (tid < 128) ? keepb[k0 + tid] : 0;
        CP_WAIT(0);
        if (tid < 128) sbias[kb2 & 1][tid] = keepv ? 0.f : -1e30f;
        __syncthreads();
        if (kb2 + 1 < 16) {
            kv_load(kb2 + 1, sb + ASTG_BASE + (uint32_t)((kb2 + 1) & 1) * ASTG);
            CP_COMMIT();
        }

        #pragma unroll
        for (int half = 0; half < 2; half++) {
            const uint32_t curK = cur + (uint32_t)half * 8192;
            const uint32_t curV = cur + 16384 + (uint32_t)half * 8192;
            const float* bia = sbias[kb2 & 1] + half * 64;

            float s[8][4];
            #pragma unroll
            for (int nt = 0; nt < 8; nt++)
                #pragma unroll
                for (int r = 0; r < 4; r++) s[nt][r] = 0.f;

            #pragma unroll
            for (int kk = 0; kk < 4; kk++) {
                uint32_t rm = (uint32_t)(wid * 16 + (lane & 15));
                uint32_t soa = SW128(rm * 128 + kk * 32 + ((lane >> 4) << 4));
                uint32_t qh[4];
                ldm_x4(qh, sb + AQ_H + soa);
                #pragma unroll
                for (int nt2 = 0; nt2 < 4; nt2++) {
                    uint32_t row = (uint32_t)(nt2 * 16 + ((sel & 2) ? 8 : 0) + l8);
                    uint32_t sob = SW128(row * 128 + kk * 32 + ((sel & 1) << 4));
                    uint32_t kh4[4];
                    ldm_x4(kh4, curK + sob);
                    mma_f16(s[2 * nt2],     qh, kh4[0], kh4[1]);
                    mma_f16(s[2 * nt2 + 1], qh, kh4[2], kh4[3]);
                }
            }

            #pragma unroll
            for (int nt = 0; nt < 8; nt++) {
                int c = nt * 8 + (lane & 3) * 2;
                float b0 = bia[c], b1 = bia[c + 1];
                s[nt][0] = s[nt][0] * SC + b0;
                s[nt][1] = s[nt][1] * SC + b1;
                s[nt][2] = s[nt][2] * SC + b0;
                s[nt][3] = s[nt][3] * SC + b1;
            }

            float mx0 = -INFINITY, mx1 = -INFINITY;
            #pragma unroll
            for (int nt = 0; nt < 8; nt++) {
                mx0 = fmaxf(mx0, fmaxf(s[nt][0], s[nt][1]));
                mx1 = fmaxf(mx1, fmaxf(s[nt][2], s[nt][3]));
            }
            mx0 = fmaxf(mx0, __shfl_xor_sync(0xffffffffu, mx0, 1));
            mx0 = fmaxf(mx0, __shfl_xor_sync(0xffffffffu, mx0, 2));
            mx1 = fmaxf(mx1, __shfl_xor_sync(0xffffffffu, mx1, 1));
            mx1 = fmaxf(mx1, __shfl_xor_sync(0xffffffffu, mx1, 2));
            float mnew0 = fmaxf(mrow[0], mx0);
            float mnew1 = fmaxf(mrow[1], mx1);
            float corr0 = exp2f(mrow[0] - mnew0);
            float corr1 = exp2f(mrow[1] - mnew1);
            mrow[0] = mnew0; mrow[1] = mnew1;

            float sm0 = 0.f, sm1 = 0.f;
            #pragma unroll
            for (int nt = 0; nt < 8; nt++) {
                s[nt][0] = exp2f(s[nt][0] - mnew0);
                s[nt][1] = exp2f(s[nt][1] - mnew0);
                s[nt][2] = exp2f(s[nt][2] - mnew1);
                s[nt][3] = exp2f(s[nt][3] - mnew1);
                sm0 += s[nt][0] + s[nt][1];
                sm1 += s[nt][2] + s[nt][3];
            }
            sm0 += __shfl_xor_sync(0xffffffffu, sm0, 1);
            sm0 += __shfl_xor_sync(0xffffffffu, sm0, 2);
            sm1 += __shfl_xor_sync(0xffffffffu, sm1, 1);
            sm1 += __shfl_xor_sync(0xffffffffu, sm1, 2);
            lrow[0] = lrow[0] * corr0 + sm0;
            lrow[1] = lrow[1] * corr1 + sm1;
            #pragma unroll
            for (int nt = 0; nt < 8; nt++) {
                o[nt][0] *= corr0; o[nt][1] *= corr0;
                o[nt][2] *= corr1; o[nt][3] *= corr1;
            }

            #pragma unroll
            for (int kc = 0; kc < 4; kc++) {
                uint32_t ph[4];
                ph[0] = packh2(s[2 * kc][0],     s[2 * kc][1]);
                ph[1] = packh2(s[2 * kc][2],     s[2 * kc][3]);
                ph[2] = packh2(s[2 * kc + 1][0], s[2 * kc + 1][1]);
                ph[3] = packh2(s[2 * kc + 1][2], s[2 * kc + 1][3]);
                #pragma unroll
                for (int nt2 = 0; nt2 < 4; nt2++) {
                    uint32_t row = (uint32_t)(kc * 16 + ((sel & 1) ? 8 : 0) + l8);
                    uint32_t sov = SW128(row * 128 + nt2 * 32 + (((sel >> 1) & 1) << 4));
                    uint32_t vh4[4];
                    ldm_x4t(vh4, curV + sov);
                    mma_f16(o[2 * nt2],     ph, vh4[0], vh4[1]);
                    mma_f16(o[2 * nt2 + 1], ph, vh4[2], vh4[3]);
                }
            }
        }
    }

    float inv0 = 1.0f / lrow[0];
    float inv1 = 1.0f / lrow[1];
    #pragma unroll
    for (int nt = 0; nt < 8; nt++) {
        int c = h * D_ + nt * 8 + (lane & 3) * 2;
        size_t g0 = (rowbase + q0 + r0) * C_ + c;
        size_t g1 = (rowbase + q0 + r1) * C_ + c;
        *(uint32_t*)&ch[g0] = packh2(o[nt][0] * inv0, o[nt][1] * inv0);
        *(uint32_t*)&ch[g1] = packh2(o[nt][2] * inv1, o[nt][3] * inv1);
    }
}

// ---------------------------------------------------------------------------
extern "C" void kernel_launch(void* const* d_in, const int* in_sizes, int n_in,
                              void* d_out, int out_size)
{
    const float* x    = (const float*)d_in[0];
    const int*   am   = (const int*)d_in[1];
    const float* Wqkv = (const float*)d_in[2];
    const float* bqkv = (const float*)d_in[3];
    const float* Wo   = (const float*)d_in[4];
    const float* bo   = (const float*)d_in[5];
    float* out = (float*)d_out;

    __half *xh, *qh, *ch, *wqh, *woh;
    cudaGetSymbolAddress((void**)&xh, g_xh);
    cudaGetSymbolAddress((void**)&qh, g_qkvh);
    cudaGetSymbolAddress((void**)&ch, g_ch);
    cudaGetSymbolAddress((void**)&wqh, g_wqh);
    cudaGetSymbolAddress((void**)&woh, g_woh);

    static bool attr_done = false;
    if (!attr_done) {
        cudaFuncSetAttribute(gemm_f16<0>,
                             cudaFuncAttributeMaxDynamicSharedMemorySize, GS_TOTAL);
        cudaFuncSetAttribute(gemm_f16<1>,
                             cudaFuncAttributeMaxDynamicSharedMemorySize, GS_TOTAL);
        cudaFuncSetAttribute(attn_mma,
                             cudaFuncAttributeMaxDynamicSharedMemorySize, A_TOTAL);
        attr_done = true;
    }

    mask_norm<<<1, 1024>>>(am);
    conv_h<<<(BT_ * C_ / 4 + 255) / 256, 256>>>(x, xh, BT_ * C_ / 4);
    split_tr_h<<<dim3(C3_ / 32, C_ / 32), 256>>>(Wqkv, wqh, C_, C3_);

    // 1) QKV projection -> fp16
    gemm_f16<1><<<dim3(C3_ / 256, BT_ / 128), 256, GS_TOTAL>>>(
        xh, wqh, bqkv, nullptr, qh, BT_, C3_, C_);

    // 2) Attention (q-tile 256, K staged 128) -> ctx fp16
    attn_mma<<<dim3(T_ / 256, H_, B_), 512, A_TOTAL>>>(qh, ch);

    // 3) Output projection -> fp32
    split_tr_h<<<dim3(C_ / 32, C_ / 32), 256>>>(Wo, woh, C_, C_);
    gemm_f16<0><<<dim3(C_ / 256, BT_ / 128), 256, GS_TOTAL>>>(
        ch, woh, bo, out, nullptr, BT_, C_, C_);
}

// round 14
// speedup vs baseline: 7.3286x; 1.0586x over previous
#include <cuda_runtime.h>
#include <cuda_bf16.h>
#include <cuda_fp16.h>
#include <math.h>
#include <stdint.h>

#define B_ 4
#define T_ 2048
#define C_ 768
#define H_ 12
#define D_ 64
#define BT_ (B_ * T_)
#define C3_ (3 * C_)

// ---------------------------------------------------------------------------
// Device scratch (no runtime allocation allowed)
// ---------------------------------------------------------------------------
__device__ int g_keep[BT_];

__device__ __half g_xh[(size_t)BT_ * C_];
__device__ __half g_qkvh[(size_t)BT_ * C3_];
__device__ __half g_ch[(size_t)BT_ * C_];
__device__ __half g_wqh[(size_t)C3_ * C_];   // Wqkv^T hi
__device__ __half g_woh[(size_t)C_ * C_];    // Wo^T   hi

// ---------------------------------------------------------------------------
// PTX helpers
// ---------------------------------------------------------------------------
__device__ __forceinline__ uint32_t smem_u32(const void* p) {
    uint32_t a;
    asm("{ .reg .u64 t; cvta.to.shared.u64 t, %1; cvt.u32.u64 %0, t; }"
        : "=r"(a) : "l"(p));
    return a;
}
__device__ __forceinline__ void ldm_x4(uint32_t (&r)[4], uint32_t addr) {
    asm volatile("ldmatrix.sync.aligned.m8n8.x4.shared.b16 {%0,%1,%2,%3}, [%4];"
        : "=r"(r[0]), "=r"(r[1]), "=r"(r[2]), "=r"(r[3]) : "r"(addr));
}
__device__ __forceinline__ void ldm_x4t(uint32_t (&r)[4], uint32_t addr) {
    asm volatile("ldmatrix.sync.aligned.m8n8.x4.trans.shared.b16 {%0,%1,%2,%3}, [%4];"
        : "=r"(r[0]), "=r"(r[1]), "=r"(r[2]), "=r"(r[3]) : "r"(addr));
}
__device__ __forceinline__ void mma_f16(float (&d)[4], const uint32_t (&a)[4],
                                        uint32_t b0, uint32_t b1) {
    asm volatile(
        "mma.sync.aligned.m16n8k16.row.col.f32.f16.f16.f32 "
        "{%0,%1,%2,%3}, {%4,%5,%6,%7}, {%8,%9}, {%0,%1,%2,%3};"
        : "+f"(d[0]), "+f"(d[1]), "+f"(d[2]), "+f"(d[3])
        : "r"(a[0]), "r"(a[1]), "r"(a[2]), "r"(a[3]), "r"(b0), "r"(b1));
}
__device__ __forceinline__ void cp16(uint32_t saddr, const void* g) {
    asm volatile("cp.async.cg.shared.global [%0], [%1], 16;"
        :: "r"(saddr), "l"(g));
}
#define CP_COMMIT() asm volatile("cp.async.commit_group;" ::: "memory")
#define CP_WAIT(n)  asm volatile("cp.async.wait_group %0;" :: "n"(n) : "memory")
#define SW128(o) ((o) ^ (((o) >> 3) & 0x70))

__device__ __forceinline__ uint32_t packh2(float a, float b) {
    __half2 hh = __floats2half2_rn(a, b);
    return *(uint32_t*)&hh;
}
// pack two fp32 to half2, then 2^x elementwise (fp16 approx)
__device__ __forceinline__ uint32_t ex2h2(float a, float b) {
    uint32_t t = packh2(a, b), r;
    asm("ex2.approx.f16x2 %0, %1;" : "=r"(r) : "r"(t));
    return r;
}

// ---------------------------------------------------------------------------
__global__ __launch_bounds__(1024) void mask_norm(const int* __restrict__ amw)
{
    const int tid = threadIdx.x;
    int allzero = 1;
    for (int i = tid; i < BT_; i += 1024)
        if (i & 1) allzero &= (amw[i] == 0);
    int is64 = __syncthreads_and(allzero);
    for (int i = tid; i < BT_; i += 1024) {
        int v = is64 ? amw[2 * i] : amw[i];
        g_keep[i] = (v == 0) ? 1 : 0;
    }
}

__global__ __launch_bounds__(256) void conv_h(
    const float* __restrict__ in, __half* __restrict__ hi, int n4)
{
    int i = blockIdx.x * 256 + threadIdx.x;
    if (i >= n4) return;
    float4 v = *(const float4*)(in + 4 * (size_t)i);
    uint2 o = make_uint2(packh2(v.x, v.y), packh2(v.z, v.w));
    *(uint2*)(hi + 4 * (size_t)i) = o;
}

__global__ __launch_bounds__(256) void split_tr_h(
    const float* __restrict__ in, __half* __restrict__ out, int K, int N)
{
    __shared__ __half tile[32][34];
    const int k0 = blockIdx.y * 32;
    const int n0 = blockIdx.x * 32;
    #pragma unroll
    for (int p = 0; p < 4; p++) {
        int idx = threadIdx.x + 256 * p;
        int kk = idx >> 5, nn = idx & 31;
        tile[nn][kk] = __float2half_rn(in[(size_t)(k0 + kk) * N + n0 + nn]);
    }
    __syncthreads();
    #pragma unroll
    for (int p = 0; p < 4; p++) {
        int idx = threadIdx.x + 256 * p;
        int nn = idx >> 5, kk = idx & 31;
        out[(size_t)(n0 + nn) * K + k0 + kk] = tile[nn][kk];
    }
}

// ---------------------------------------------------------------------------
// fp16 HMMA GEMM: Out = Ah[M][K] @ (Bh[N][K])^T + bias
// CTA 128x256, 8 warps (2x4), warp tile 64x64. 2-stage cp.async pipeline.
// ---------------------------------------------------------------------------
#define GS_A  0
#define GS_B  16384
#define GSTG  49152
#define GS_TOTAL (2 * GSTG)

template <int MODE>
__global__ __launch_bounds__(256) void gemm_f16(
    const __half* __restrict__ Ah, const __half* __restrict__ Bh,
    const float* __restrict__ bias, float* __restrict__ Out,
    __half* __restrict__ Hh,
    int M, int N, int K)
{
    extern __shared__ __align__(1024) char smem[];
    const uint32_t sb = smem_u32(smem);
    const int tid  = threadIdx.x;
    const int wid  = tid >> 5;
    const int lane = tid & 31;
    const int m0 = blockIdx.y * 128;
    const int n0 = blockIdx.x * 256;
    const int wm = wid >> 2;
    const int wn = wid & 3;
    const int l8  = lane & 7;
    const int sel = lane >> 3;

    const int nstages = K / 64;
    auto stage_load = [&](int s, uint32_t dst) {
        const int k0 = s * 64;
        #pragma unroll
        for (int i = 0; i < 4; i++) {
            int u = tid + 256 * i;
            int r = u >> 3, uk = u & 7;
            uint32_t so = SW128((uint32_t)(r * 128 + uk * 16));
            cp16(dst + GS_A + so, Ah + (size_t)(m0 + r) * K + k0 + uk * 8);
        }
        #pragma unroll
        for (int i = 0; i < 8; i++) {
            int u = tid + 256 * i;
            int r = u >> 3, uk = u & 7;
            uint32_t so = SW128((uint32_t)(r * 128 + uk * 16));
            cp16(dst + GS_B + so, Bh + (size_t)(n0 + r) * K + k0 + uk * 8);
        }
    };

    float acc[4][8][4];
    #pragma unroll
    for (int i = 0; i < 4; i++)
        #pragma unroll
        for (int j = 0; j < 8; j++)
            #pragma unroll
            for (int r = 0; r < 4; r++) acc[i][j][r] = 0.f;

    stage_load(0, sb);
    CP_COMMIT();
    stage_load(1, sb + GSTG);
    CP_COMMIT();

    for (int s = 0; s < nstages; s++) {
        const uint32_t cur = sb + (uint32_t)(s & 1) * GSTG;
        if (s + 1 < nstages) { CP_WAIT(1); } else { CP_WAIT(0); }
        __syncthreads();

        #pragma unroll
        for (int kk = 0; kk < 4; kk++) {
            uint32_t bh4[4][4];
            #pragma unroll
            for (int nt2 = 0; nt2 < 4; nt2++) {
                uint32_t row = (uint32_t)(wn * 64 + nt2 * 16 + ((sel & 2) ? 8 : 0) + l8);
                uint32_t so = SW128(row * 128 + kk * 32 + ((sel & 1) << 4));
                ldm_x4(bh4[nt2], cur + GS_B + so);
            }
            #pragma unroll
            for (int mt = 0; mt < 4; mt++) {
                uint32_t rm = (uint32_t)(wm * 64 + mt * 16 + (lane & 15));
                uint32_t so = SW128(rm * 128 + kk * 32 + ((lane >> 4) << 4));
                uint32_t ah[4];
                ldm_x4(ah, cur + GS_A + so);
                #pragma unroll
                for (int nt = 0; nt < 8; nt++) {
                    mma_f16(acc[mt][nt], ah,
                            bh4[nt >> 1][(nt & 1) * 2], bh4[nt >> 1][(nt & 1) * 2 + 1]);
                }
            }
        }
        __syncthreads();
        if (s + 2 < nstages) {
            stage_load(s + 2, cur);
            CP_COMMIT();
        }
    }

    #pragma unroll
    for (int mt = 0; mt < 4; mt++) {
        #pragma unroll
        for (int nt = 0; nt < 8; nt++) {
            int grow = m0 + wm * 64 + mt * 16 + (lane >> 2);
            int gcol = n0 + wn * 64 + nt * 8 + (lane & 3) * 2;
            float2 bb = *(const float2*)&bias[gcol];
            float v0 = acc[mt][nt][0] + bb.x, v1 = acc[mt][nt][1] + bb.y;
            float v2 = acc[mt][nt][2] + bb.x, v3 = acc[mt][nt][3] + bb.y;
            if (MODE == 1) {
                *(uint32_t*)&Hh[(size_t)grow * N + gcol] = packh2(v0, v1);
                *(uint32_t*)&Hh[(size_t)(grow + 8) * N + gcol] = packh2(v2, v3);
            } else {
                *(float2*)&Out[(size_t)grow * N + gcol] = make_float2(v0, v1);
                *(float2*)&Out[(size_t)(grow + 8) * N + gcol] = make_float2(v2, v3);
            }
        }
    }
}

// ---------------------------------------------------------------------------
// Flash attention: q-tile 256, 512 threads / 16 warps, warp owns 16 rows.
// S = Qh Kh^T; P = ex2.approx.f16x2(s - m); row sums via ones-MMA;
// O = P @ Vh. K staged 128 at a time, two 64-wide sub-iterations per stage.
// ---------------------------------------------------------------------------
#define AQ_H   0
#define ASTG_BASE 32768
#define ASTG   32768          // per-stage: K_H(0..16K), V_H(16K..32K)
#define A_BIAS 98304          // float[2][128]
#define A_TOTAL 99328
#define ONES_H2 0x3C003C00u   // half2(1.0, 1.0)

__global__ __launch_bounds__(512) void attn_mma(
    const __half* __restrict__ qkvh, __half* __restrict__ ch)
{
    extern __shared__ __align__(1024) char smem[];
    const uint32_t sb = smem_u32(smem);
    float (*sbias)[128] = (float(*)[128])(smem + A_BIAS);

    const int tid  = threadIdx.x;
    const int wid  = tid >> 5;
    const int lane = tid & 31;
    const int l8   = lane & 7;
    const int sel  = lane >> 3;
    const int q0 = blockIdx.x * 256;
    const int h  = blockIdx.y;
    const int b  = blockIdx.z;

    const size_t rowbase = (size_t)b * T_;
    const int* keepb = g_keep + b * T_;
    const float SC = 0.125f * 1.44269504088896f;  // (1/sqrt(D)) * log2(e)

    #pragma unroll
    for (int i = 0; i < 4; i++) {
        int u = tid + 512 * i;
        int r = u >> 3, uk = u & 7;
        uint32_t so = SW128((uint32_t)(r * 128 + uk * 16));
        cp16(sb + AQ_H + so, qkvh + (rowbase + q0 + r) * C3_ + h * D_ + uk * 8);
    }

    auto kv_load = [&](int kb2, uint32_t dst) {
        const int k0 = kb2 * 128;
        #pragma unroll
        for (int i = 0; i < 2; i++) {
            int u = tid + 512 * i;
            int r = u >> 3, uk = u & 7;
            uint32_t so = SW128((uint32_t)(r * 128 + uk * 16));
            size_t gk = (rowbase + k0 + r) * C3_ + C_ + h * D_ + uk * 8;
            size_t gv = (rowbase + k0 + r) * C3_ + 2 * C_ + h * D_ + uk * 8;
            cp16(dst + 0     + so, qkvh + gk);
            cp16(dst + 16384 + so, qkvh + gv);
        }
    };
    kv_load(0, sb + ASTG_BASE);
    CP_COMMIT();

    const int r0 = wid * 16 + (lane >> 2);
    const int r1 = r0 + 8;

    float mrow[2] = {-INFINITY, -INFINITY};
    float lrow[2] = {0.f, 0.f};
    float o[8][4];
    #pragma unroll
    for (int nt = 0; nt < 8; nt++)
        #pragma unroll
        for (int r = 0; r < 4; r++) o[nt][r] = 0.f;

    for (int kb2 = 0; kb2 < 16; kb2++) {
        const int k0 = kb2 * 128;
        const uint32_t cur = sb + ASTG_BASE + (uint32_t)(kb2 & 1) * ASTG;

        int keepv = (tid < 128) ? keepb[k0 + tid] : 0;
        CP_WAIT(0);
        if (tid < 128) sbias[kb2 & 1][tid] = keepv ? 0.f : -1e30f;
        __syncthreads();
        if (kb2 + 1 < 16) {
            kv_load(kb2 + 1, sb + ASTG_BASE + (uint32_t)((kb2 + 1) & 1) * ASTG);
            CP_COMMIT();
        }

        #pragma unroll
        for (int half = 0; half < 2; half++) {
            const uint32_t curK = cur + (uint32_t)half * 8192;
            const uint32_t curV = cur + 16384 + (uint32_t)half * 8192;
            const float* bia = sbias[kb2 & 1] + half * 64;

            // S = Qh @ Kh^T
            float s[8][4];
            #pragma unroll
            for (int nt = 0; nt < 8; nt++)
                #pragma unroll
                for (int r = 0; r < 4; r++) s[nt][r] = 0.f;

            #pragma unroll
            for (int kk = 0; kk < 4; kk++) {
                uint32_t rm = (uint32_t)(wid * 16 + (lane & 15));
                uint32_t soa = SW128(rm * 128 + kk * 32 + ((lane >> 4) << 4));
                uint32_t qh[4];
                ldm_x4(qh, sb + AQ_H + soa);
                #pragma unroll
                for (int nt2 = 0; nt2 < 4; nt2++) {
                    uint32_t row = (uint32_t)(nt2 * 16 + ((sel & 2) ? 8 : 0) + l8);
                    uint32_t sob = SW128(row * 128 + kk * 32 + ((sel & 1) << 4));
                    uint32_t kh4[4];
                    ldm_x4(kh4, curK + sob);
                    mma_f16(s[2 * nt2],     qh, kh4[0], kh4[1]);
                    mma_f16(s[2 * nt2 + 1], qh, kh4[2], kh4[3]);
                }
            }

            // Scale (log2 domain) + mask bias
            #pragma unroll
            for (int nt = 0; nt < 8; nt++) {
                int c = nt * 8 + (lane & 3) * 2;
                float b0 = bia[c], b1 = bia[c + 1];
                s[nt][0] = s[nt][0] * SC + b0;
                s[nt][1] = s[nt][1] * SC + b1;
                s[nt][2] = s[nt][2] * SC + b0;
                s[nt][3] = s[nt][3] * SC + b1;
            }

            // Row max (intra-quad)
            float mx0 = -INFINITY, mx1 = -INFINITY;
            #pragma unroll
            for (int nt = 0; nt < 8; nt++) {
                mx0 = fmaxf(mx0, fmaxf(s[nt][0], s[nt][1]));
                mx1 = fmaxf(mx1, fmaxf(s[nt][2], s[nt][3]));
            }
            mx0 = fmaxf(mx0, __shfl_xor_sync(0xffffffffu, mx0, 1));
            mx0 = fmaxf(mx0, __shfl_xor_sync(0xffffffffu, mx0, 2));
            mx1 = fmaxf(mx1, __shfl_xor_sync(0xffffffffu, mx1, 1));
            mx1 = fmaxf(mx1, __shfl_xor_sync(0xffffffffu, mx1, 2));
            float mnew0 = fmaxf(mrow[0], mx0);
            float mnew1 = fmaxf(mrow[1], mx1);
            float corr0 = exp2f(mrow[0] - mnew0);
            float corr1 = exp2f(mrow[1] - mnew1);
            mrow[0] = mnew0; mrow[1] = mnew1;

            // Rescale O
            #pragma unroll
            for (int nt = 0; nt < 8; nt++) {
                o[nt][0] *= corr0; o[nt][1] *= corr0;
                o[nt][2] *= corr1; o[nt][3] *= corr1;
            }

            // P = 2^(s - m) as half2 fragments (directly usable by PV MMA)
            uint32_t p2[16];
            #pragma unroll
            for (int nt = 0; nt < 8; nt++) {
                p2[2 * nt]     = ex2h2(s[nt][0] - mnew0, s[nt][1] - mnew0);
                p2[2 * nt + 1] = ex2h2(s[nt][2] - mnew1, s[nt][3] - mnew1);
            }

            // PV MMAs + row-sum via constant-ones B fragment
            float dsum[4] = {0.f, 0.f, 0.f, 0.f};
            #pragma unroll
            for (int kc = 0; kc < 4; kc++) {
                uint32_t ph[4] = {p2[4 * kc], p2[4 * kc + 1],
                                  p2[4 * kc + 2], p2[4 * kc + 3]};
                #pragma unroll
                for (int nt2 = 0; nt2 < 4; nt2++) {
                    uint32_t row = (uint32_t)(kc * 16 + ((sel & 1) ? 8 : 0) + l8);
                    uint32_t sov = SW128(row * 128 + nt2 * 32 + (((sel >> 1) & 1) << 4));
                    uint32_t vh4[4];
                    ldm_x4t(vh4, curV + sov);
                    mma_f16(o[2 * nt2],     ph, vh4[0], vh4[1]);
                    mma_f16(o[2 * nt2 + 1], ph, vh4[2], vh4[3]);
                }
                mma_f16(dsum, ph, ONES_H2, ONES_H2);
            }
            lrow[0] = lrow[0] * corr0 + dsum[0];
            lrow[1] = lrow[1] * corr1 + dsum[2];
        }
    }

    float inv0 = 1.0f / lrow[0];
    float inv1 = 1.0f / lrow[1];
    #pragma unroll
    for (int nt = 0; nt < 8; nt++) {
        int c = h * D_ + nt * 8 + (lane & 3) * 2;
        size_t g0 = (rowbase + q0 + r0) * C_ + c;
        size_t g1 = (rowbase + q0 + r1) * C_ + c;
        *(uint32_t*)&ch[g0] = packh2(o[nt][0] * inv0, o[nt][1] * inv0);
        *(uint32_t*)&ch[g1] = packh2(o[nt][2] * inv1, o[nt][3] * inv1);
    }
}

// ---------------------------------------------------------------------------
extern "C" void kernel_launch(void* const* d_in, const int* in_sizes, int n_in,
                              void* d_out, int out_size)
{
    const float* x    = (const float*)d_in[0];
    const int*   am   = (const int*)d_in[1];
    const float* Wqkv = (const float*)d_in[2];
    const float* bqkv = (const float*)d_in[3];
    const float* Wo   = (const float*)d_in[4];
    const float* bo   = (const float*)d_in[5];
    float* out = (float*)d_out;

    __half *xh, *qh, *ch, *wqh, *woh;
    cudaGetSymbolAddress((void**)&xh, g_xh);
    cudaGetSymbolAddress((void**)&qh, g_qkvh);
    cudaGetSymbolAddress((void**)&ch, g_ch);
    cudaGetSymbolAddress((void**)&wqh, g_wqh);
    cudaGetSymbolAddress((void**)&woh, g_woh);

    static bool attr_done = false;
    if (!attr_done) {
        cudaFuncSetAttribute(gemm_f16<0>,
                             cudaFuncAttributeMaxDynamicSharedMemorySize, GS_TOTAL);
        cudaFuncSetAttribute(gemm_f16<1>,
                             cudaFuncAttributeMaxDynamicSharedMemorySize, GS_TOTAL);
        cudaFuncSetAttribute(attn_mma,
                             cudaFuncAttributeMaxDynamicSharedMemorySize, A_TOTAL);
        attr_done = true;
    }

    mask_norm<<<1, 1024>>>(am);
    conv_h<<<(BT_ * C_ / 4 + 255) / 256, 256>>>(x, xh, BT_ * C_ / 4);
    split_tr_h<<<dim3(C3_ / 32, C_ / 32), 256>>>(Wqkv, wqh, C_, C3_);

    gemm_f16<1><<<dim3(C3_ / 256, BT_ / 128), 256, GS_TOTAL>>>(
        xh, wqh, bqkv, nullptr, qh, BT_, C3_, C_);

    attn_mma<<<dim3(T_ / 256, H_, B_), 512, A_TOTAL>>>(qh, ch);

    split_tr_h<<<dim3(C_ / 32, C_ / 32), 256>>>(Wo, woh, C_, C_);
    gemm_f16<0><<<dim3(C_ / 256, BT_ / 128), 256, GS_TOTAL>>>(
        ch, woh, bo, out, nullptr, BT_, C_, C_);
}

// round 15
// speedup vs baseline: 9.5392x; 1.3016x over previous
#include <cuda_runtime.h>
#include <cuda_bf16.h>
#include <cuda_fp16.h>
#include <math.h>
#include <stdint.h>

#define B_ 4
#define T_ 2048
#define C_ 768
#define H_ 12
#define D_ 64
#define BT_ (B_ * T_)
#define C3_ (3 * C_)

// ---------------------------------------------------------------------------
// Device scratch (no runtime allocation allowed)
// ---------------------------------------------------------------------------
__device__ int   g_keep[BT_];
__device__ int   g_cidx[BT_];     // compacted attended-key indices per batch
__device__ int   g_cnt[B_];       // attended count per batch
__device__ float g_biasval[B_];   // 0 normally; -1e30 for all-masked fallback

__device__ __half g_xh[(size_t)BT_ * C_];
__device__ __half g_qkvh[(size_t)BT_ * C3_];
__device__ __half g_ch[(size_t)BT_ * C_];
__device__ __half g_wqh[(size_t)C3_ * C_];   // Wqkv^T hi
__device__ __half g_woh[(size_t)C_ * C_];    // Wo^T   hi

// ---------------------------------------------------------------------------
// PTX helpers
// ---------------------------------------------------------------------------
__device__ __forceinline__ uint32_t smem_u32(const void* p) {
    uint32_t a;
    asm("{ .reg .u64 t; cvta.to.shared.u64 t, %1; cvt.u32.u64 %0, t; }"
        : "=r"(a) : "l"(p));
    return a;
}
__device__ __forceinline__ void ldm_x4(uint32_t (&r)[4], uint32_t addr) {
    asm volatile("ldmatrix.sync.aligned.m8n8.x4.shared.b16 {%0,%1,%2,%3}, [%4];"
        : "=r"(r[0]), "=r"(r[1]), "=r"(r[2]), "=r"(r[3]) : "r"(addr));
}
__device__ __forceinline__ void ldm_x4t(uint32_t (&r)[4], uint32_t addr) {
    asm volatile("ldmatrix.sync.aligned.m8n8.x4.trans.shared.b16 {%0,%1,%2,%3}, [%4];"
        : "=r"(r[0]), "=r"(r[1]), "=r"(r[2]), "=r"(r[3]) : "r"(addr));
}
__device__ __forceinline__ void mma_f16(float (&d)[4], const uint32_t (&a)[4],
                                        uint32_t b0, uint32_t b1) {
    asm volatile(
        "mma.sync.aligned.m16n8k16.row.col.f32.f16.f16.f32 "
        "{%0,%1,%2,%3}, {%4,%5,%6,%7}, {%8,%9}, {%0,%1,%2,%3};"
        : "+f"(d[0]), "+f"(d[1]), "+f"(d[2]), "+f"(d[3])
        : "r"(a[0]), "r"(a[1]), "r"(a[2]), "r"(a[3]), "r"(b0), "r"(b1));
}
__device__ __forceinline__ void cp16(uint32_t saddr, const void* g) {
    asm volatile("cp.async.cg.shared.global [%0], [%1], 16;"
        :: "r"(saddr), "l"(g));
}
#define CP_COMMIT() asm volatile("cp.async.commit_group;" ::: "memory")
#define CP_WAIT(n)  asm volatile("cp.async.wait_group %0;" :: "n"(n) : "memory")
#define SW128(o) ((o) ^ (((o) >> 3) & 0x70))

__device__ __forceinline__ uint32_t packh2(float a, float b) {
    __half2 hh = __floats2half2_rn(a, b);
    return *(uint32_t*)&hh;
}
__device__ __forceinline__ uint32_t ex2h2(float a, float b) {
    uint32_t t = packh2(a, b), r;
    asm("ex2.approx.f16x2 %0, %1;" : "=r"(r) : "r"(t));
    return r;
}

// ---------------------------------------------------------------------------
__global__ __launch_bounds__(1024) void mask_norm(const int* __restrict__ amw)
{
    const int tid = threadIdx.x;
    int allzero = 1;
    for (int i = tid; i < BT_; i += 1024)
        if (i & 1) allzero &= (amw[i] == 0);
    int is64 = __syncthreads_and(allzero);
    for (int i = tid; i < BT_; i += 1024) {
        int v = is64 ? amw[2 * i] : amw[i];
        g_keep[i] = (v == 0) ? 1 : 0;
    }
}

// Stable compaction of attended key indices. One block (256 thr) per batch.
__global__ __launch_bounds__(256) void mask_compact()
{
    const int b = blockIdx.x;
    const int tid = threadIdx.x;
    const int lane = tid & 31, w = tid >> 5;
    __shared__ int wsum[8];
    const int* keep = g_keep + b * T_;
    const int base = tid * 8;

    int loc[8], s = 0;
    #pragma unroll
    for (int i = 0; i < 8; i++) { loc[i] = keep[base + i]; s += loc[i]; }

    // inclusive warp scan of per-thread sums
    int pre = s;
    #pragma unroll
    for (int off = 1; off < 32; off <<= 1) {
        int t = __shfl_up_sync(0xffffffffu, pre, off);
        if (lane >= off) pre += t;
    }
    if (lane == 31) wsum[w] = pre;
    __syncthreads();

    int total = 0;
    #pragma unroll
    for (int i = 0; i < 8; i++) total += wsum[i];

    if (total == 0) {
        // all-masked batch: uniform softmax over all keys (matches reference)
        for (int i = tid; i < T_; i += 256) g_cidx[b * T_ + i] = i;
        if (tid == 0) { g_cnt[b] = T_; g_biasval[b] = -1e30f; }
    } else {
        int woff = 0;
        for (int i = 0; i < w; i++) woff += wsum[i];
        int excl = woff + pre - s;
        #pragma unroll
        for (int i = 0; i < 8; i++) {
            if (loc[i]) { g_cidx[b * T_ + excl] = base + i; excl++; }
        }
        if (tid == 0) { g_cnt[b] = total; g_biasval[b] = 0.f; }
    }
}

__global__ __launch_bounds__(256) void conv_h(
    const float* __restrict__ in, __half* __restrict__ hi, int n4)
{
    int i = blockIdx.x * 256 + threadIdx.x;
    if (i >= n4) return;
    float4 v = *(const float4*)(in + 4 * (size_t)i);
    uint2 o = make_uint2(packh2(v.x, v.y), packh2(v.z, v.w));
    *(uint2*)(hi + 4 * (size_t)i) = o;
}

__global__ __launch_bounds__(256) void split_tr_h(
    const float* __restrict__ in, __half* __restrict__ out, int K, int N)
{
    __shared__ __half tile[32][34];
    const int k0 = blockIdx.y * 32;
    const int n0 = blockIdx.x * 32;
    #pragma unroll
    for (int p = 0; p < 4; p++) {
        int idx = threadIdx.x + 256 * p;
        int kk = idx >> 5, nn = idx & 31;
        tile[nn][kk] = __float2half_rn(in[(size_t)(k0 + kk) * N + n0 + nn]);
    }
    __syncthreads();
    #pragma unroll
    for (int p = 0; p < 4; p++) {
        int idx = threadIdx.x + 256 * p;
        int nn = idx >> 5, kk = idx & 31;
        out[(size_t)(n0 + nn) * K + k0 + kk] = tile[nn][kk];
    }
}

// ---------------------------------------------------------------------------
// fp16 HMMA GEMM: Out = Ah[M][K] @ (Bh[N][K])^T + bias
// CTA 128x256, 8 warps (2x4), warp tile 64x64. 2-stage cp.async pipeline.
// ---------------------------------------------------------------------------
#define GS_A  0
#define GS_B  16384
#define GSTG  49152
#define GS_TOTAL (2 * GSTG)

template <int MODE>
__global__ __launch_bounds__(256) void gemm_f16(
    const __half* __restrict__ Ah, const __half* __restrict__ Bh,
    const float* __restrict__ bias, float* __restrict__ Out,
    __half* __restrict__ Hh,
    int M, int N, int K)
{
    extern __shared__ __align__(1024) char smem[];
    const uint32_t sb = smem_u32(smem);
    const int tid  = threadIdx.x;
    const int wid  = tid >> 5;
    const int lane = tid & 31;
    const int m0 = blockIdx.y * 128;
    const int n0 = blockIdx.x * 256;
    const int wm = wid >> 2;
    const int wn = wid & 3;
    const int l8  = lane & 7;
    const int sel = lane >> 3;

    const int nstages = K / 64;
    auto stage_load = [&](int s, uint32_t dst) {
        const int k0 = s * 64;
        #pragma unroll
        for (int i = 0; i < 4; i++) {
            int u = tid + 256 * i;
            int r = u >> 3, uk = u & 7;
            uint32_t so = SW128((uint32_t)(r * 128 + uk * 16));
            cp16(dst + GS_A + so, Ah + (size_t)(m0 + r) * K + k0 + uk * 8);
        }
        #pragma unroll
        for (int i = 0; i < 8; i++) {
            int u = tid + 256 * i;
            int r = u >> 3, uk = u & 7;
            uint32_t so = SW128((uint32_t)(r * 128 + uk * 16));
            cp16(dst + GS_B + so, Bh + (size_t)(n0 + r) * K + k0 + uk * 8);
        }
    };

    float acc[4][8][4];
    #pragma unroll
    for (int i = 0; i < 4; i++)
        #pragma unroll
        for (int j = 0; j < 8; j++)
            #pragma unroll
            for (int r = 0; r < 4; r++) acc[i][j][r] = 0.f;

    stage_load(0, sb);
    CP_COMMIT();
    stage_load(1, sb + GSTG);
    CP_COMMIT();

    for (int s = 0; s < nstages; s++) {
        const uint32_t cur = sb + (uint32_t)(s & 1) * GSTG;
        if (s + 1 < nstages) { CP_WAIT(1); } else { CP_WAIT(0); }
        __syncthreads();

        #pragma unroll
        for (int kk = 0; kk < 4; kk++) {
            uint32_t bh4[4][4];
            #pragma unroll
            for (int nt2 = 0; nt2 < 4; nt2++) {
                uint32_t row = (uint32_t)(wn * 64 + nt2 * 16 + ((sel & 2) ? 8 : 0) + l8);
                uint32_t so = SW128(row * 128 + kk * 32 + ((sel & 1) << 4));
                ldm_x4(bh4[nt2], cur + GS_B + so);
            }
            #pragma unroll
            for (int mt = 0; mt < 4; mt++) {
                uint32_t rm = (uint32_t)(wm * 64 + mt * 16 + (lane & 15));
                uint32_t so = SW128(rm * 128 + kk * 32 + ((lane >> 4) << 4));
                uint32_t ah[4];
                ldm_x4(ah, cur + GS_A + so);
                #pragma unroll
                for (int nt = 0; nt < 8; nt++) {
                    mma_f16(acc[mt][nt], ah,
                            bh4[nt >> 1][(nt & 1) * 2], bh4[nt >> 1][(nt & 1) * 2 + 1]);
                }
            }
        }
        __syncthreads();
        if (s + 2 < nstages) {
            stage_load(s + 2, cur);
            CP_COMMIT();
        }
    }

    #pragma unroll
    for (int mt = 0; mt < 4; mt++) {
        #pragma unroll
        for (int nt = 0; nt < 8; nt++) {
            int grow = m0 + wm * 64 + mt * 16 + (lane >> 2);
            int gcol = n0 + wn * 64 + nt * 8 + (lane & 3) * 2;
            float2 bb = *(const float2*)&bias[gcol];
            float v0 = acc[mt][nt][0] + bb.x, v1 = acc[mt][nt][1] + bb.y;
            float v2 = acc[mt][nt][2] + bb.x, v3 = acc[mt][nt][3] + bb.y;
            if (MODE == 1) {
                *(uint32_t*)&Hh[(size_t)grow * N + gcol] = packh2(v0, v1);
                *(uint32_t*)&Hh[(size_t)(grow + 8) * N + gcol] = packh2(v2, v3);
            } else {
                *(float2*)&Out[(size_t)grow * N + gcol] = make_float2(v0, v1);
                *(float2*)&Out[(size_t)(grow + 8) * N + gcol] = make_float2(v2, v3);
            }
        }
    }
}

// ---------------------------------------------------------------------------
// Flash attention over COMPACTED keys: only attended positions are processed.
// q-tile 256, 512 threads / 16 warps, warp owns 16 rows.
// S = Qh Kh^T; P = ex2.approx.f16x2(s-m); row sums via ones-MMA; O = P @ Vh.
// K gathered via g_cidx, staged 128 rows/stage, two 64-wide halves per stage.
// ---------------------------------------------------------------------------
#define AQ_H   0
#define ASTG_BASE 32768
#define ASTG   32768          // per-stage: K_H(0..16K), V_H(16K..32K)
#define A_BIAS 98304          // float[2][128]
#define A_TOTAL 99328
#define ONES_H2 0x3C003C00u   // half2(1.0, 1.0)

__global__ __launch_bounds__(512) void attn_mma(
    const __half* __restrict__ qkvh, __half* __restrict__ ch)
{
    extern __shared__ __align__(1024) char smem[];
    const uint32_t sb = smem_u32(smem);
    float (*sbias)[128] = (float(*)[128])(smem + A_BIAS);

    const int tid  = threadIdx.x;
    const int wid  = tid >> 5;
    const int lane = tid & 31;
    const int l8   = lane & 7;
    const int sel  = lane >> 3;
    const int q0 = blockIdx.x * 256;
    const int h  = blockIdx.y;
    const int b  = blockIdx.z;

    const size_t rowbase = (size_t)b * T_;
    const int* cidx = g_cidx + b * T_;
    const int cnt = g_cnt[b];
    const float biasv = g_biasval[b];
    const int niter = (cnt + 127) >> 7;
    const float SC = 0.125f * 1.44269504088896f;  // (1/sqrt(D)) * log2(e)

    #pragma unroll
    for (int i = 0; i < 4; i++) {
        int u = tid + 512 * i;
        int r = u >> 3, uk = u & 7;
        uint32_t so = SW128((uint32_t)(r * 128 + uk * 16));
        cp16(sb + AQ_H + so, qkvh + (rowbase + q0 + r) * C3_ + h * D_ + uk * 8);
    }

    // Gathered KV staging: 128 compacted rows/stage; 2 units/thread/tile
    auto kv_load = [&](int kb2, uint32_t dst) {
        const int k0 = kb2 * 128;
        #pragma unroll
        for (int i = 0; i < 2; i++) {
            int u = tid + 512 * i;
            int r = u >> 3, uk = u & 7;
            int j = k0 + r;
            int gi = (j < cnt) ? cidx[j] : cidx[0];
            uint32_t so = SW128((uint32_t)(r * 128 + uk * 16));
            size_t gk = (rowbase + gi) * C3_ + C_ + h * D_ + uk * 8;
            size_t gv = (rowbase + gi) * C3_ + 2 * C_ + h * D_ + uk * 8;
            cp16(dst + 0     + so, qkvh + gk);
            cp16(dst + 16384 + so, qkvh + gv);
        }
    };
    kv_load(0, sb + ASTG_BASE);
    CP_COMMIT();

    const int r0 = wid * 16 + (lane >> 2);
    const int r1 = r0 + 8;

    float mrow[2] = {-INFINITY, -INFINITY};
    float lrow[2] = {0.f, 0.f};
    float o[8][4];
    #pragma unroll
    for (int nt = 0; nt < 8; nt++)
        #pragma unroll
        for (int r = 0; r < 4; r++) o[nt][r] = 0.f;

    for (int kb2 = 0; kb2 < niter; kb2++) {
        const int k0 = kb2 * 128;
        const uint32_t cur = sb + ASTG_BASE + (uint32_t)(kb2 & 1) * ASTG;

        CP_WAIT(0);
        if (tid < 128) sbias[kb2 & 1][tid] = (k0 + tid < cnt) ? biasv : -1e30f;
        __syncthreads();
        if (kb2 + 1 < niter) {
            kv_load(kb2 + 1, sb + ASTG_BASE + (uint32_t)((kb2 + 1) & 1) * ASTG);
            CP_COMMIT();
        }

        #pragma unroll
        for (int half = 0; half < 2; half++) {
            const uint32_t curK = cur + (uint32_t)half * 8192;
            const uint32_t curV = cur + 16384 + (uint32_t)half * 8192;
            const float* bia = sbias[kb2 & 1] + half * 64;

            // S = Qh @ Kh^T
            float s[8][4];
            #pragma unroll
            for (int nt = 0; nt < 8; nt++)
                #pragma unroll
                for (int r = 0; r < 4; r++) s[nt][r] = 0.f;

            #pragma unroll
            for (int kk = 0; kk < 4; kk++) {
                uint32_t rm = (uint32_t)(wid * 16 + (lane & 15));
                uint32_t soa = SW128(rm * 128 + kk * 32 + ((lane >> 4) << 4));
                uint32_t qh[4];
                ldm_x4(qh, sb + AQ_H + soa);
                #pragma unroll
                for (int nt2 = 0; nt2 < 4; nt2++) {
                    uint32_t row = (uint32_t)(nt2 * 16 + ((sel & 2) ? 8 : 0) + l8);
                    uint32_t sob = SW128(row * 128 + kk * 32 + ((sel & 1) << 4));
                    uint32_t kh4[4];
                    ldm_x4(kh4, curK + sob);
                    mma_f16(s[2 * nt2],     qh, kh4[0], kh4[1]);
                    mma_f16(s[2 * nt2 + 1], qh, kh4[2], kh4[3]);
                }
            }

            // Scale (log2 domain) + tail/fallback bias
            #pragma unroll
            for (int nt = 0; nt < 8; nt++) {
                int c = nt * 8 + (lane & 3) * 2;
                float b0 = bia[c], b1 = bia[c + 1];
                s[nt][0] = s[nt][0] * SC + b0;
                s[nt][1] = s[nt][1] * SC + b1;
                s[nt][2] = s[nt][2] * SC + b0;
                s[nt][3] = s[nt][3] * SC + b1;
            }

            // Row max (intra-quad)
            float mx0 = -INFINITY, mx1 = -INFINITY;
            #pragma unroll
            for (int nt = 0; nt < 8; nt++) {
                mx0 = fmaxf(mx0, fmaxf(s[nt][0], s[nt][1]));
                mx1 = fmaxf(mx1, fmaxf(s[nt][2], s[nt][3]));
            }
            mx0 = fmaxf(mx0, __shfl_xor_sync(0xffffffffu, mx0, 1));
            mx0 = fmaxf(mx0, __shfl_xor_sync(0xffffffffu, mx0, 2));
            mx1 = fmaxf(mx1, __shfl_xor_sync(0xffffffffu, mx1, 1));
            mx1 = fmaxf(mx1, __shfl_xor_sync(0xffffffffu, mx1, 2));
            float mnew0 = fmaxf(mrow[0], mx0);
            float mnew1 = fmaxf(mrow[1], mx1);
            float corr0 = exp2f(mrow[0] - mnew0);
            float corr1 = exp2f(mrow[1] - mnew1);
            mrow[0] = mnew0; mrow[1] = mnew1;

            #pragma unroll
            for (int nt = 0; nt < 8; nt++) {
                o[nt][0] *= corr0; o[nt][1] *= corr0;
                o[nt][2] *= corr1; o[nt][3] *= corr1;
            }

            // P = 2^(s - m) as half2 fragments
            uint32_t p2[16];
            #pragma unroll
            for (int nt = 0; nt < 8; nt++) {
                p2[2 * nt]     = ex2h2(s[nt][0] - mnew0, s[nt][1] - mnew0);
                p2[2 * nt + 1] = ex2h2(s[nt][2] - mnew1, s[nt][3] - mnew1);
            }

            // PV MMAs + row-sum via constant-ones B fragment
            float dsum[4] = {0.f, 0.f, 0.f, 0.f};
            #pragma unroll
            for (int kc = 0; kc < 4; kc++) {
                uint32_t ph[4] = {p2[4 * kc], p2[4 * kc + 1],
                                  p2[4 * kc + 2], p2[4 * kc + 3]};
                #pragma unroll
                for (int nt2 = 0; nt2 < 4; nt2++) {
                    uint32_t row = (uint32_t)(kc * 16 + ((sel & 1) ? 8 : 0) + l8);
                    uint32_t sov = SW128(row * 128 + nt2 * 32 + (((sel >> 1) & 1) << 4));
                    uint32_t vh4[4];
                    ldm_x4t(vh4, curV + sov);
                    mma_f16(o[2 * nt2],     ph, vh4[0], vh4[1]);
                    mma_f16(o[2 * nt2 + 1], ph, vh4[2], vh4[3]);
                }
                mma_f16(dsum, ph, ONES_H2, ONES_H2);
            }
            lrow[0] = lrow[0] * corr0 + dsum[0];
            lrow[1] = lrow[1] * corr1 + dsum[2];
        }
    }

    float inv0 = 1.0f / lrow[0];
    float inv1 = 1.0f / lrow[1];
    #pragma unroll
    for (int nt = 0; nt < 8; nt++) {
        int c = h * D_ + nt * 8 + (lane & 3) * 2;
        size_t g0 = (rowbase + q0 + r0) * C_ + c;
        size_t g1 = (rowbase + q0 + r1) * C_ + c;
        *(uint32_t*)&ch[g0] = packh2(o[nt][0] * inv0, o[nt][1] * inv0);
        *(uint32_t*)&ch[g1] = packh2(o[nt][2] * inv1, o[nt][3] * inv1);
    }
}

// ---------------------------------------------------------------------------
extern "C" void kernel_launch(void* const* d_in, const int* in_sizes, int n_in,
                              void* d_out, int out_size)
{
    const float* x    = (const float*)d_in[0];
    const int*   am   = (const int*)d_in[1];
    const float* Wqkv = (const float*)d_in[2];
    const float* bqkv = (const float*)d_in[3];
    const float* Wo   = (const float*)d_in[4];
    const float* bo   = (const float*)d_in[5];
    float* out = (float*)d_out;

    __half *xh, *qh, *ch, *wqh, *woh;
    cudaGetSymbolAddress((void**)&xh, g_xh);
    cudaGetSymbolAddress((void**)&qh, g_qkvh);
    cudaGetSymbolAddress((void**)&ch, g_ch);
    cudaGetSymbolAddress((void**)&wqh, g_wqh);
    cudaGetSymbolAddress((void**)&woh, g_woh);

    static bool attr_done = false;
    if (!attr_done) {
        cudaFuncSetAttribute(gemm_f16<0>,
                             cudaFuncAttributeMaxDynamicSharedMemorySize, GS_TOTAL);
        cudaFuncSetAttribute(gemm_f16<1>,
                             cudaFuncAttributeMaxDynamicSharedMemorySize, GS_TOTAL);
        cudaFuncSetAttribute(attn_mma,
                             cudaFuncAttributeMaxDynamicSharedMemorySize, A_TOTAL);
        attr_done = true;
    }

    mask_norm<<<1, 1024>>>(am);
    mask_compact<<<B_, 256>>>();
    conv_h<<<(BT_ * C_ / 4 + 255) / 256, 256>>>(x, xh, BT_ * C_ / 4);
    split_tr_h<<<dim3(C3_ / 32, C_ / 32), 256>>>(Wqkv, wqh, C_, C3_);

    gemm_f16<1><<<dim3(C3_ / 256, BT_ / 128), 256, GS_TOTAL>>>(
        xh, wqh, bqkv, nullptr, qh, BT_, C3_, C_);

    attn_mma<<<dim3(T_ / 256, H_, B_), 512, A_TOTAL>>>(qh, ch);

    split_tr_h<<<dim3(C_ / 32, C_ / 32), 256>>>(Wo, woh, C_, C_);
    gemm_f16<0><<<dim3(C_ / 256, BT_ / 128), 256, GS_TOTAL>>>(
        ch, woh, bo, out, nullptr, BT_, C_, C_);
}

// round 16
// speedup vs baseline: 9.8396x; 1.0315x over previous
#include <cuda_runtime.h>
#include <cuda_bf16.h>
#include <cuda_fp16.h>
#include <math.h>
#include <stdint.h>

#define B_ 4
#define T_ 2048
#define C_ 768
#define H_ 12
#define D_ 64
#define BT_ (B_ * T_)
#define C3_ (3 * C_)
#define C2_ (2 * C_)

// ---------------------------------------------------------------------------
// Device scratch (no runtime allocation allowed)
// ---------------------------------------------------------------------------
__device__ int   g_keep[BT_];
__device__ int   g_cidx[BT_];     // compacted attended-key indices per batch
__device__ int   g_cnt[B_];       // attended count per batch
__device__ float g_biasval[B_];   // 0 normally; -1e30 for all-masked fallback

__device__ __half g_xh[(size_t)BT_ * C_];
__device__ __half g_qh[(size_t)BT_ * C_];     // Q projection (all rows)
__device__ __half g_kvh[(size_t)BT_ * C2_];   // K|V projection (compacted rows)
__device__ __half g_ch[(size_t)BT_ * C_];
__device__ __half g_wqh[(size_t)C3_ * C_];    // Wqkv^T hi
__device__ __half g_woh[(size_t)C_ * C_];     // Wo^T   hi

// ---------------------------------------------------------------------------
// PTX helpers
// ---------------------------------------------------------------------------
__device__ __forceinline__ uint32_t smem_u32(const void* p) {
    uint32_t a;
    asm("{ .reg .u64 t; cvta.to.shared.u64 t, %1; cvt.u32.u64 %0, t; }"
        : "=r"(a) : "l"(p));
    return a;
}
__device__ __forceinline__ void ldm_x4(uint32_t (&r)[4], uint32_t addr) {
    asm volatile("ldmatrix.sync.aligned.m8n8.x4.shared.b16 {%0,%1,%2,%3}, [%4];"
        : "=r"(r[0]), "=r"(r[1]), "=r"(r[2]), "=r"(r[3]) : "r"(addr));
}
__device__ __forceinline__ void ldm_x4t(uint32_t (&r)[4], uint32_t addr) {
    asm volatile("ldmatrix.sync.aligned.m8n8.x4.trans.shared.b16 {%0,%1,%2,%3}, [%4];"
        : "=r"(r[0]), "=r"(r[1]), "=r"(r[2]), "=r"(r[3]) : "r"(addr));
}
__device__ __forceinline__ void mma_f16(float (&d)[4], const uint32_t (&a)[4],
                                        uint32_t b0, uint32_t b1) {
    asm volatile(
        "mma.sync.aligned.m16n8k16.row.col.f32.f16.f16.f32 "
        "{%0,%1,%2,%3}, {%4,%5,%6,%7}, {%8,%9}, {%0,%1,%2,%3};"
        : "+f"(d[0]), "+f"(d[1]), "+f"(d[2]), "+f"(d[3])
        : "r"(a[0]), "r"(a[1]), "r"(a[2]), "r"(a[3]), "r"(b0), "r"(b1));
}
__device__ __forceinline__ void cp16(uint32_t saddr, const void* g) {
    asm volatile("cp.async.cg.shared.global [%0], [%1], 16;"
        :: "r"(saddr), "l"(g));
}
#define CP_COMMIT() asm volatile("cp.async.commit_group;" ::: "memory")
#define CP_WAIT(n)  asm volatile("cp.async.wait_group %0;" :: "n"(n) : "memory")
#define SW128(o) ((o) ^ (((o) >> 3) & 0x70))

__device__ __forceinline__ uint32_t packh2(float a, float b) {
    __half2 hh = __floats2half2_rn(a, b);
    return *(uint32_t*)&hh;
}
__device__ __forceinline__ uint32_t ex2h2(float a, float b) {
    uint32_t t = packh2(a, b), r;
    asm("ex2.approx.f16x2 %0, %1;" : "=r"(r) : "r"(t));
    return r;
}

// ---------------------------------------------------------------------------
__global__ __launch_bounds__(1024) void mask_norm(const int* __restrict__ amw)
{
    const int tid = threadIdx.x;
    int allzero = 1;
    for (int i = tid; i < BT_; i += 1024)
        if (i & 1) allzero &= (amw[i] == 0);
    int is64 = __syncthreads_and(allzero);
    for (int i = tid; i < BT_; i += 1024) {
        int v = is64 ? amw[2 * i] : amw[i];
        g_keep[i] = (v == 0) ? 1 : 0;
    }
}

// Stable compaction of attended key indices. One block (256 thr) per batch.
__global__ __launch_bounds__(256) void mask_compact()
{
    const int b = blockIdx.x;
    const int tid = threadIdx.x;
    const int lane = tid & 31, w = tid >> 5;
    __shared__ int wsum[8];
    const int* keep = g_keep + b * T_;
    const int base = tid * 8;

    int loc[8], s = 0;
    #pragma unroll
    for (int i = 0; i < 8; i++) { loc[i] = keep[base + i]; s += loc[i]; }

    int pre = s;
    #pragma unroll
    for (int off = 1; off < 32; off <<= 1) {
        int t = __shfl_up_sync(0xffffffffu, pre, off);
        if (lane >= off) pre += t;
    }
    if (lane == 31) wsum[w] = pre;
    __syncthreads();

    int total = 0;
    #pragma unroll
    for (int i = 0; i < 8; i++) total += wsum[i];

    if (total == 0) {
        for (int i = tid; i < T_; i += 256) g_cidx[b * T_ + i] = i;
        if (tid == 0) { g_cnt[b] = T_; g_biasval[b] = -1e30f; }
    } else {
        int woff = 0;
        for (int i = 0; i < w; i++) woff += wsum[i];
        int excl = woff + pre - s;
        #pragma unroll
        for (int i = 0; i < 8; i++) {
            if (loc[i]) { g_cidx[b * T_ + excl] = base + i; excl++; }
        }
        if (tid == 0) { g_cnt[b] = total; g_biasval[b] = 0.f; }
    }
}

__global__ __launch_bounds__(256) void conv_h(
    const float* __restrict__ in, __half* __restrict__ hi, int n4)
{
    int i = blockIdx.x * 256 + threadIdx.x;
    if (i >= n4) return;
    float4 v = *(const float4*)(in + 4 * (size_t)i);
    uint2 o = make_uint2(packh2(v.x, v.y), packh2(v.z, v.w));
    *(uint2*)(hi + 4 * (size_t)i) = o;
}

__global__ __launch_bounds__(256) void split_tr_h(
    const float* __restrict__ in, __half* __restrict__ out, int K, int N)
{
    __shared__ __half tile[32][34];
    const int k0 = blockIdx.y * 32;
    const int n0 = blockIdx.x * 32;
    #pragma unroll
    for (int p = 0; p < 4; p++) {
        int idx = threadIdx.x + 256 * p;
        int kk = idx >> 5, nn = idx & 31;
        tile[nn][kk] = __float2half_rn(in[(size_t)(k0 + kk) * N + n0 + nn]);
    }
    __syncthreads();
    #pragma unroll
    for (int p = 0; p < 4; p++) {
        int idx = threadIdx.x + 256 * p;
        int nn = idx >> 5, kk = idx & 31;
        out[(size_t)(n0 + nn) * K + k0 + kk] = tile[nn][kk];
    }
}

// ---------------------------------------------------------------------------
// fp16 HMMA GEMM: Out = Ah[M][K] @ (Bh[N][K])^T + bias
// CTA 128x256, 8 warps (2x4), warp tile 64x64. 2-stage cp.async pipeline.
// ---------------------------------------------------------------------------
#define GS_A  0
#define GS_B  16384
#define GSTG  49152
#define GS_TOTAL (2 * GSTG)

template <int MODE>
__global__ __launch_bounds__(256) void gemm_f16(
    const __half* __restrict__ Ah, const __half* __restrict__ Bh,
    const float* __restrict__ bias, float* __restrict__ Out,
    __half* __restrict__ Hh,
    int M, int N, int K)
{
    extern __shared__ __align__(1024) char smem[];
    const uint32_t sb = smem_u32(smem);
    const int tid  = threadIdx.x;
    const int wid  = tid >> 5;
    const int lane = tid & 31;
    const int m0 = blockIdx.y * 128;
    const int n0 = blockIdx.x * 256;
    const int wm = wid >> 2;
    const int wn = wid & 3;
    const int l8  = lane & 7;
    const int sel = lane >> 3;

    const int nstages = K / 64;
    auto stage_load = [&](int s, uint32_t dst) {
        const int k0 = s * 64;
        #pragma unroll
        for (int i = 0; i < 4; i++) {
            int u = tid + 256 * i;
            int r = u >> 3, uk = u & 7;
            uint32_t so = SW128((uint32_t)(r * 128 + uk * 16));
            cp16(dst + GS_A + so, Ah + (size_t)(m0 + r) * K + k0 + uk * 8);
        }
        #pragma unroll
        for (int i = 0; i < 8; i++) {
            int u = tid + 256 * i;
            int r = u >> 3, uk = u & 7;
            uint32_t so = SW128((uint32_t)(r * 128 + uk * 16));
            cp16(dst + GS_B + so, Bh + (size_t)(n0 + r) * K + k0 + uk * 8);
        }
    };

    float acc[4][8][4];
    #pragma unroll
    for (int i = 0; i < 4; i++)
        #pragma unroll
        for (int j = 0; j < 8; j++)
            #pragma unroll
            for (int r = 0; r < 4; r++) acc[i][j][r] = 0.f;

    stage_load(0, sb);
    CP_COMMIT();
    stage_load(1, sb + GSTG);
    CP_COMMIT();

    for (int s = 0; s < nstages; s++) {
        const uint32_t cur = sb + (uint32_t)(s & 1) * GSTG;
        if (s + 1 < nstages) { CP_WAIT(1); } else { CP_WAIT(0); }
        __syncthreads();

        #pragma unroll
        for (int kk = 0; kk < 4; kk++) {
            uint32_t bh4[4][4];
            #pragma unroll
            for (int nt2 = 0; nt2 < 4; nt2++) {
                uint32_t row = (uint32_t)(wn * 64 + nt2 * 16 + ((sel & 2) ? 8 : 0) + l8);
                uint32_t so = SW128(row * 128 + kk * 32 + ((sel & 1) << 4));
                ldm_x4(bh4[nt2], cur + GS_B + so);
            }
            #pragma unroll
            for (int mt = 0; mt < 4; mt++) {
                uint32_t rm = (uint32_t)(wm * 64 + mt * 16 + (lane & 15));
                uint32_t so = SW128(rm * 128 + kk * 32 + ((lane >> 4) << 4));
                uint32_t ah[4];
                ldm_x4(ah, cur + GS_A + so);
                #pragma unroll
                for (int nt = 0; nt < 8; nt++) {
                    mma_f16(acc[mt][nt], ah,
                            bh4[nt >> 1][(nt & 1) * 2], bh4[nt >> 1][(nt & 1) * 2 + 1]);
                }
            }
        }
        __syncthreads();
        if (s + 2 < nstages) {
            stage_load(s + 2, cur);
            CP_COMMIT();
        }
    }

    #pragma unroll
    for (int mt = 0; mt < 4; mt++) {
        #pragma unroll
        for (int nt = 0; nt < 8; nt++) {
            int grow = m0 + wm * 64 + mt * 16 + (lane >> 2);
            int gcol = n0 + wn * 64 + nt * 8 + (lane & 3) * 2;
            float2 bb = *(const float2*)&bias[gcol];
            float v0 = acc[mt][nt][0] + bb.x, v1 = acc[mt][nt][1] + bb.y;
            float v2 = acc[mt][nt][2] + bb.x, v3 = acc[mt][nt][3] + bb.y;
            if (MODE == 1) {
                *(uint32_t*)&Hh[(size_t)grow * N + gcol] = packh2(v0, v1);
                *(uint32_t*)&Hh[(size_t)(grow + 8) * N + gcol] = packh2(v2, v3);
            } else {
                *(float2*)&Out[(size_t)grow * N + gcol] = make_float2(v0, v1);
                *(float2*)&Out[(size_t)(grow + 8) * N + gcol] = make_float2(v2, v3);
            }
        }
    }
}

// ---------------------------------------------------------------------------
// Gathered KV GEMM: rows of A (= x fp16) taken via compacted indices; only
// attended rows computed. Out (fp16) stored compacted: g_kvh[b*T + j][1536].
// CTA grid.y spans B_*T_/128; CTAs whose 128-row block starts >= cnt exit.
// ---------------------------------------------------------------------------
__global__ __launch_bounds__(256) void gemm_kv(
    const __half* __restrict__ Ah, const __half* __restrict__ Bh,
    const float* __restrict__ bias, __half* __restrict__ Hh)
{
    const int m0 = blockIdx.y * 128;
    const int b  = m0 >> 11;            // / T_
    const int j0 = m0 & (T_ - 1);
    const int cnt = g_cnt[b];
    if (j0 >= cnt) return;

    extern __shared__ __align__(1024) char smem[];
    const uint32_t sb = smem_u32(smem);
    const int tid  = threadIdx.x;
    const int wid  = tid >> 5;
    const int lane = tid & 31;
    const int n0 = blockIdx.x * 256;
    const int wm = wid >> 2;
    const int wn = wid & 3;
    const int l8  = lane & 7;
    const int sel = lane >> 3;
    const int* cidx = g_cidx + b * T_;
    const size_t rowbase = (size_t)b * T_;
    const int K = C_, N = C2_;

    // Pre-resolve gathered global rows for this thread's 4 A-loads
    int grow_a[4];
    #pragma unroll
    for (int i = 0; i < 4; i++) {
        int r = (tid + 256 * i) >> 3;
        int j = j0 + r; if (j >= cnt) j = cnt - 1;
        grow_a[i] = cidx[j];
    }

    const int nstages = K / 64;
    auto stage_load = [&](int s, uint32_t dst) {
        const int k0 = s * 64;
        #pragma unroll
        for (int i = 0; i < 4; i++) {
            int u = tid + 256 * i;
            int r = u >> 3, uk = u & 7;
            uint32_t so = SW128((uint32_t)(r * 128 + uk * 16));
            cp16(dst + GS_A + so, Ah + (rowbase + grow_a[i]) * K + k0 + uk * 8);
        }
        #pragma unroll
        for (int i = 0; i < 8; i++) {
            int u = tid + 256 * i;
            int r = u >> 3, uk = u & 7;
            uint32_t so = SW128((uint32_t)(r * 128 + uk * 16));
            cp16(dst + GS_B + so, Bh + (size_t)(n0 + r) * K + k0 + uk * 8);
        }
    };

    float acc[4][8][4];
    #pragma unroll
    for (int i = 0; i < 4; i++)
        #pragma unroll
        for (int j = 0; j < 8; j++)
            #pragma unroll
            for (int r = 0; r < 4; r++) acc[i][j][r] = 0.f;

    stage_load(0, sb);
    CP_COMMIT();
    stage_load(1, sb + GSTG);
    CP_COMMIT();

    for (int s = 0; s < nstages; s++) {
        const uint32_t cur = sb + (uint32_t)(s & 1) * GSTG;
        if (s + 1 < nstages) { CP_WAIT(1); } else { CP_WAIT(0); }
        __syncthreads();

        #pragma unroll
        for (int kk = 0; kk < 4; kk++) {
            uint32_t bh4[4][4];
            #pragma unroll
            for (int nt2 = 0; nt2 < 4; nt2++) {
                uint32_t row = (uint32_t)(wn * 64 + nt2 * 16 + ((sel & 2) ? 8 : 0) + l8);
                uint32_t so = SW128(row * 128 + kk * 32 + ((sel & 1) << 4));
                ldm_x4(bh4[nt2], cur + GS_B + so);
            }
            #pragma unroll
            for (int mt = 0; mt < 4; mt++) {
                uint32_t rm = (uint32_t)(wm * 64 + mt * 16 + (lane & 15));
                uint32_t so = SW128(rm * 128 + kk * 32 + ((lane >> 4) << 4));
                uint32_t ah[4];
                ldm_x4(ah, cur + GS_A + so);
                #pragma unroll
                for (int nt = 0; nt < 8; nt++) {
                    mma_f16(acc[mt][nt], ah,
                            bh4[nt >> 1][(nt & 1) * 2], bh4[nt >> 1][(nt & 1) * 2 + 1]);
                }
            }
        }
        __syncthreads();
        if (s + 2 < nstages) {
            stage_load(s + 2, cur);
            CP_COMMIT();
        }
    }

    #pragma unroll
    for (int mt = 0; mt < 4; mt++) {
        #pragma unroll
        for (int nt = 0; nt < 8; nt++) {
            int jrow = j0 + wm * 64 + mt * 16 + (lane >> 2);
            int gcol = n0 + wn * 64 + nt * 8 + (lane & 3) * 2;
            float2 bb = *(const float2*)&bias[gcol];
            float v0 = acc[mt][nt][0] + bb.x, v1 = acc[mt][nt][1] + bb.y;
            float v2 = acc[mt][nt][2] + bb.x, v3 = acc[mt][nt][3] + bb.y;
            *(uint32_t*)&Hh[(rowbase + jrow) * N + gcol] = packh2(v0, v1);
            *(uint32_t*)&Hh[(rowbase + jrow + 8) * N + gcol] = packh2(v2, v3);
        }
    }
}

// ---------------------------------------------------------------------------
// Flash attention over compacted keys (K/V already compacted in g_kvh).
// q-tile 256, 512 threads / 16 warps, warp owns 16 rows.
// S = Qh Kh^T; P = ex2.approx.f16x2(s-m); row sums via ones-MMA; O = P @ Vh.
// ---------------------------------------------------------------------------
#define AQ_H   0
#define ASTG_BASE 32768
#define ASTG   32768          // per-stage: K_H(0..16K), V_H(16K..32K)
#define A_BIAS 98304          // float[2][128]
#define A_TOTAL 99328
#define ONES_H2 0x3C003C00u

__global__ __launch_bounds__(512) void attn_mma(
    const __half* __restrict__ qh_g, const __half* __restrict__ kvh,
    __half* __restrict__ ch)
{
    extern __shared__ __align__(1024) char smem[];
    const uint32_t sb = smem_u32(smem);
    float (*sbias)[128] = (float(*)[128])(smem + A_BIAS);

    const int tid  = threadIdx.x;
    const int wid  = tid >> 5;
    const int lane = tid & 31;
    const int l8   = lane & 7;
    const int sel  = lane >> 3;
    const int q0 = blockIdx.x * 256;
    const int h  = blockIdx.y;
    const int b  = blockIdx.z;

    const size_t rowbase = (size_t)b * T_;
    const int cnt = g_cnt[b];
    const float biasv = g_biasval[b];
    const int niter = (cnt + 127) >> 7;
    const float SC = 0.125f * 1.44269504088896f;

    #pragma unroll
    for (int i = 0; i < 4; i++) {
        int u = tid + 512 * i;
        int r = u >> 3, uk = u & 7;
        uint32_t so = SW128((uint32_t)(r * 128 + uk * 16));
        cp16(sb + AQ_H + so, qh_g + (rowbase + q0 + r) * C_ + h * D_ + uk * 8);
    }

    // Contiguous compacted KV staging: 128 rows/stage; 2 units/thread/tile
    auto kv_load = [&](int kb2, uint32_t dst) {
        const int k0 = kb2 * 128;
        #pragma unroll
        for (int i = 0; i < 2; i++) {
            int u = tid + 512 * i;
            int r = u >> 3, uk = u & 7;
            uint32_t so = SW128((uint32_t)(r * 128 + uk * 16));
            size_t gk = (rowbase + k0 + r) * C2_ + h * D_ + uk * 8;
            cp16(dst + 0     + so, kvh + gk);
            cp16(dst + 16384 + so, kvh + gk + C_);
        }
    };
    kv_load(0, sb + ASTG_BASE);
    CP_COMMIT();

    const int r0 = wid * 16 + (lane >> 2);
    const int r1 = r0 + 8;

    float mrow[2] = {-INFINITY, -INFINITY};
    float lrow[2] = {0.f, 0.f};
    float o[8][4];
    #pragma unroll
    for (int nt = 0; nt < 8; nt++)
        #pragma unroll
        for (int r = 0; r < 4; r++) o[nt][r] = 0.f;

    for (int kb2 = 0; kb2 < niter; kb2++) {
        const int k0 = kb2 * 128;
        const uint32_t cur = sb + ASTG_BASE + (uint32_t)(kb2 & 1) * ASTG;

        CP_WAIT(0);
        if (tid < 128) sbias[kb2 & 1][tid] = (k0 + tid < cnt) ? biasv : -1e30f;
        __syncthreads();
        if (kb2 + 1 < niter) {
            kv_load(kb2 + 1, sb + ASTG_BASE + (uint32_t)((kb2 + 1) & 1) * ASTG);
            CP_COMMIT();
        }

        #pragma unroll
        for (int half = 0; half < 2; half++) {
            const uint32_t curK = cur + (uint32_t)half * 8192;
            const uint32_t curV = cur + 16384 + (uint32_t)half * 8192;
            const float* bia = sbias[kb2 & 1] + half * 64;

            float s[8][4];
            #pragma unroll
            for (int nt = 0; nt < 8; nt++)
                #pragma unroll
                for (int r = 0; r < 4; r++) s[nt][r] = 0.f;

            #pragma unroll
            for (int kk = 0; kk < 4; kk++) {
                uint32_t rm = (uint32_t)(wid * 16 + (lane & 15));
                uint32_t soa = SW128(rm * 128 + kk * 32 + ((lane >> 4) << 4));
                uint32_t qh[4];
                ldm_x4(qh, sb + AQ_H + soa);
                #pragma unroll
                for (int nt2 = 0; nt2 < 4; nt2++) {
                    uint32_t row = (uint32_t)(nt2 * 16 + ((sel & 2) ? 8 : 0) + l8);
                    uint32_t sob = SW128(row * 128 + kk * 32 + ((sel & 1) << 4));
                    uint32_t kh4[4];
                    ldm_x4(kh4, curK + sob);
                    mma_f16(s[2 * nt2],     qh, kh4[0], kh4[1]);
                    mma_f16(s[2 * nt2 + 1], qh, kh4[2], kh4[3]);
                }
            }

            #pragma unroll
            for (int nt = 0; nt < 8; nt++) {
                int c = nt * 8 + (lane & 3) * 2;
                float b0 = bia[c], b1 = bia[c + 1];
                s[nt][0] = s[nt][0] * SC + b0;
                s[nt][1] = s[nt][1] * SC + b1;
                s[nt][2] = s[nt][2] * SC + b0;
                s[nt][3] = s[nt][3] * SC + b1;
            }

            float mx0 = -INFINITY, mx1 = -INFINITY;
            #pragma unroll
            for (int nt = 0; nt < 8; nt++) {
                mx0 = fmaxf(mx0, fmaxf(s[nt][0], s[nt][1]));
                mx1 = fmaxf(mx1, fmaxf(s[nt][2], s[nt][3]));
            }
            mx0 = fmaxf(mx0, __shfl_xor_sync(0xffffffffu, mx0, 1));
            mx0 = fmaxf(mx0, __shfl_xor_sync(0xffffffffu, mx0, 2));
            mx1 = fmaxf(mx1, __shfl_xor_sync(0xffffffffu, mx1, 1));
            mx1 = fmaxf(mx1, __shfl_xor_sync(0xffffffffu, mx1, 2));
            float mnew0 = fmaxf(mrow[0], mx0);
            float mnew1 = fmaxf(mrow[1], mx1);
            float corr0 = exp2f(mrow[0] - mnew0);
            float corr1 = exp2f(mrow[1] - mnew1);
            mrow[0] = mnew0; mrow[1] = mnew1;

            #pragma unroll
            for (int nt = 0; nt < 8; nt++) {
                o[nt][0] *= corr0; o[nt][1] *= corr0;
                o[nt][2] *= corr1; o[nt][3] *= corr1;
            }

            uint32_t p2[16];
            #pragma unroll
            for (int nt = 0; nt < 8; nt++) {
                p2[2 * nt]     = ex2h2(s[nt][0] - mnew0, s[nt][1] - mnew0);
                p2[2 * nt + 1] = ex2h2(s[nt][2] - mnew1, s[nt][3] - mnew1);
            }

            float dsum[4] = {0.f, 0.f, 0.f, 0.f};
            #pragma unroll
            for (int kc = 0; kc < 4; kc++) {
                uint32_t ph[4] = {p2[4 * kc], p2[4 * kc + 1],
                                  p2[4 * kc + 2], p2[4 * kc + 3]};
                #pragma unroll
                for (int nt2 = 0; nt2 < 4; nt2++) {
                    uint32_t row = (uint32_t)(kc * 16 + ((sel & 1) ? 8 : 0) + l8);
                    uint32_t sov = SW128(row * 128 + nt2 * 32 + (((sel >> 1) & 1) << 4));
                    uint32_t vh4[4];
                    ldm_x4t(vh4, curV + sov);
                    mma_f16(o[2 * nt2],     ph, vh4[0], vh4[1]);
                    mma_f16(o[2 * nt2 + 1], ph, vh4[2], vh4[3]);
                }
                mma_f16(dsum, ph, ONES_H2, ONES_H2);
            }
            lrow[0] = lrow[0] * corr0 + dsum[0];
            lrow[1] = lrow[1] * corr1 + dsum[2];
        }
    }

    float inv0 = 1.0f / lrow[0];
    float inv1 = 1.0f / lrow[1];
    #pragma unroll
    for (int nt = 0; nt < 8; nt++) {
        int c = h * D_ + nt * 8 + (lane & 3) * 2;
        size_t g0 = (rowbase + q0 + r0) * C_ + c;
        size_t g1 = (rowbase + q0 + r1) * C_ + c;
        *(uint32_t*)&ch[g0] = packh2(o[nt][0] * inv0, o[nt][1] * inv0);
        *(uint32_t*)&ch[g1] = packh2(o[nt][2] * inv1, o[nt][3] * inv1);
    }
}

// ---------------------------------------------------------------------------
extern "C" void kernel_launch(void* const* d_in, const int* in_sizes, int n_in,
                              void* d_out, int out_size)
{
    const float* x    = (const float*)d_in[0];
    const int*   am   = (const int*)d_in[1];
    const float* Wqkv = (const float*)d_in[2];
    const float* bqkv = (const float*)d_in[3];
    const float* Wo   = (const float*)d_in[4];
    const float* bo   = (const float*)d_in[5];
    float* out = (float*)d_out;

    __half *xh, *qh, *kvh, *ch, *wqh, *woh;
    cudaGetSymbolAddress((void**)&xh, g_xh);
    cudaGetSymbolAddress((void**)&qh, g_qh);
    cudaGetSymbolAddress((void**)&kvh, g_kvh);
    cudaGetSymbolAddress((void**)&ch, g_ch);
    cudaGetSymbolAddress((void**)&wqh, g_wqh);
    cudaGetSymbolAddress((void**)&woh, g_woh);

    static bool attr_done = false;
    if (!attr_done) {
        cudaFuncSetAttribute(gemm_f16<0>,
                             cudaFuncAttributeMaxDynamicSharedMemorySize, GS_TOTAL);
        cudaFuncSetAttribute(gemm_f16<1>,
                             cudaFuncAttributeMaxDynamicSharedMemorySize, GS_TOTAL);
        cudaFuncSetAttribute(gemm_kv,
                             cudaFuncAttributeMaxDynamicSharedMemorySize, GS_TOTAL);
        cudaFuncSetAttribute(attn_mma,
                             cudaFuncAttributeMaxDynamicSharedMemorySize, A_TOTAL);
        attr_done = true;
    }

    mask_norm<<<1, 1024>>>(am);
    mask_compact<<<B_, 256>>>();
    conv_h<<<(BT_ * C_ / 4 + 255) / 256, 256>>>(x, xh, BT_ * C_ / 4);
    split_tr_h<<<dim3(C3_ / 32, C_ / 32), 256>>>(Wqkv, wqh, C_, C3_);

    // 1a) Q projection (all rows): N = 768 (first third of Wqkv^T)
    gemm_f16<1><<<dim3(C_ / 256, BT_ / 128), 256, GS_TOTAL>>>(
        xh, wqh, bqkv, nullptr, qh, BT_, C_, C_);
    // 1b) K|V projection (compacted rows only): N = 1536
    gemm_kv<<<dim3(C2_ / 256, BT_ / 128), 256, GS_TOTAL>>>(
        xh, wqh + (size_t)C_ * C_, bqkv + C_, kvh);

    // 2) Attention over compacted keys
    attn_mma<<<dim3(T_ / 256, H_, B_), 512, A_TOTAL>>>(qh, kvh, ch);

    // 3) Output projection -> fp32
    split_tr_h<<<dim3(C_ / 32, C_ / 32), 256>>>(Wo, woh, C_, C_);
    gemm_f16<0><<<dim3(C_ / 256, BT_ / 128), 256, GS_TOTAL>>>(
        ch, woh, bo, out, nullptr, BT_, C_, C_);
}